// round 2
// baseline (speedup 1.0000x reference)
#include <cuda_runtime.h>
#include <math.h>

// ---------------------------------------------------------------------------
// Problem constants (fixed by the reference): B=4, S=2048, D=1024, H=16, dk=64
// ---------------------------------------------------------------------------
#define BB 4
#define SS 2048
#define DD 1024
#define HH 16
#define DK 64
#define MM (BB * SS)          // 8192 rows for all projections

// Scratch: Q,K,V in [B,H,S,dk] layout; ctx in [B,S,D] layout.
__device__ float g_Q[(size_t)BB * HH * SS * DK];
__device__ float g_K[(size_t)BB * HH * SS * DK];
__device__ float g_V[(size_t)BB * HH * SS * DK];
__device__ float g_C[(size_t)BB * SS * DD];

// ---------------------------------------------------------------------------
// GEMM: out = A[M,K] @ W[K,N] + bias[N]
// 128x128 block tile, 8x8 per-thread micro-tile, 256 threads.
// splitHeads=1 writes out in [B,H,S,dk] layout instead of [M,N].
// ---------------------------------------------------------------------------
#define TM 128
#define TN 128
#define TK 16

__global__ __launch_bounds__(256)
void gemm_bias_kernel(const float* __restrict__ A,
                      const float* __restrict__ W,
                      const float* __restrict__ bias,
                      float* __restrict__ out,
                      int M, int N, int K, int splitHeads)
{
    __shared__ float As[TK][TM + 4];   // padded to dodge store conflicts
    __shared__ float Bs[TK][TN];

    const int rowBase = blockIdx.y * TM;
    const int colBase = blockIdx.x * TN;
    const int tid = threadIdx.x;
    const int ty = tid >> 4;           // 0..15
    const int tx = tid & 15;           // 0..15

    float acc[8][8];
#pragma unroll
    for (int i = 0; i < 8; i++)
#pragma unroll
        for (int j = 0; j < 8; j++) acc[i][j] = 0.f;

    for (int k0 = 0; k0 < K; k0 += TK) {
        // Load A tile: 128 x 16
#pragma unroll
        for (int i = 0; i < 8; i++) {
            int idx = tid + i * 256;           // 0..2047
            int r = idx >> 4, c = idx & 15;
            As[c][r] = A[(size_t)(rowBase + r) * K + (k0 + c)];
        }
        // Load B tile: 16 x 128 (coalesced)
#pragma unroll
        for (int i = 0; i < 8; i++) {
            int idx = tid + i * 256;
            int r = idx >> 7, c = idx & 127;
            Bs[r][c] = W[(size_t)(k0 + r) * N + (colBase + c)];
        }
        __syncthreads();

#pragma unroll
        for (int kk = 0; kk < TK; kk++) {
            float4 a0 = *(const float4*)&As[kk][ty * 8];
            float4 a1 = *(const float4*)&As[kk][ty * 8 + 4];
            float4 b0 = *(const float4*)&Bs[kk][tx * 8];
            float4 b1 = *(const float4*)&Bs[kk][tx * 8 + 4];
            float a[8] = {a0.x, a0.y, a0.z, a0.w, a1.x, a1.y, a1.z, a1.w};
            float b[8] = {b0.x, b0.y, b0.z, b0.w, b1.x, b1.y, b1.z, b1.w};
#pragma unroll
            for (int i = 0; i < 8; i++)
#pragma unroll
                for (int j = 0; j < 8; j++)
                    acc[i][j] += a[i] * b[j];
        }
        __syncthreads();
    }

    // Epilogue
#pragma unroll
    for (int i = 0; i < 8; i++) {
        int m = rowBase + ty * 8 + i;
#pragma unroll
        for (int j = 0; j < 8; j++) {
            int n = colBase + tx * 8 + j;
            float v = acc[i][j] + bias[n];
            if (splitHeads) {
                int b  = m >> 11;         // m / 2048
                int s  = m & (SS - 1);
                int h  = n >> 6;          // n / 64
                int dd = n & (DK - 1);
                out[(((size_t)(b * HH + h)) * SS + s) * DK + dd] = v;
            } else {
                out[(size_t)m * N + n] = v;
            }
        }
    }
}

// ---------------------------------------------------------------------------
// Causal flash attention, fp32. One block = 128 query rows of one (b,h).
// Each thread owns one query row: q[64] and acc[64] in registers.
// Streams K/V tiles of 16 keys through shared memory with online softmax.
// ---------------------------------------------------------------------------
#define KT 16

__global__ __launch_bounds__(128)
void attn_kernel(const float* __restrict__ Q,
                 const float* __restrict__ K,
                 const float* __restrict__ V,
                 float* __restrict__ C)
{
    __shared__ float4 Ks[KT][DK / 4];
    __shared__ float4 Vs[KT][DK / 4];

    const int qt = blockIdx.x;   // 0..15 (query tile)
    const int h  = blockIdx.y;   // 0..15
    const int b  = blockIdx.z;   // 0..3
    const size_t bh = (size_t)(b * HH + h);
    const float* Qb = Q + bh * SS * DK;
    const float* Kb = K + bh * SS * DK;
    const float* Vb = V + bh * SS * DK;

    const int qi = qt * 128 + threadIdx.x;   // this thread's query row

    // Load q row, pre-scaled by 1/sqrt(dk) = 0.125
    float4 q[DK / 4];
    const float4* qp = (const float4*)(Qb + (size_t)qi * DK);
#pragma unroll
    for (int i = 0; i < DK / 4; i++) {
        float4 t = qp[i];
        t.x *= 0.125f; t.y *= 0.125f; t.z *= 0.125f; t.w *= 0.125f;
        q[i] = t;
    }

    float4 acc[DK / 4];
#pragma unroll
    for (int i = 0; i < DK / 4; i++) acc[i] = make_float4(0.f, 0.f, 0.f, 0.f);
    float m = -INFINITY, l = 0.f;

    const int kend = qt * 128 + 128;         // causal: keys beyond this tile all masked

    for (int j0 = 0; j0 < kend; j0 += KT) {
        // Load KT x 64 floats of K and V (= 256 float4 each, 128 threads -> 2 each)
        const float4* Ksrc = (const float4*)(Kb + (size_t)j0 * DK);
        const float4* Vsrc = (const float4*)(Vb + (size_t)j0 * DK);
#pragma unroll
        for (int i = 0; i < 2; i++) {
            int idx = threadIdx.x + i * 128;
            ((float4*)Ks)[idx] = Ksrc[idx];
            ((float4*)Vs)[idx] = Vsrc[idx];
        }
        __syncthreads();

        // Scores for this key tile
        float s[KT];
#pragma unroll
        for (int j = 0; j < KT; j++) {
            float4 sum = make_float4(0.f, 0.f, 0.f, 0.f);
#pragma unroll
            for (int d = 0; d < DK / 4; d++) {
                float4 kk = Ks[j][d];
                sum.x += q[d].x * kk.x; sum.y += q[d].y * kk.y;
                sum.z += q[d].z * kk.z; sum.w += q[d].w * kk.w;
            }
            float sv = (sum.x + sum.y) + (sum.z + sum.w);
            s[j] = ((j0 + j) <= qi) ? sv : -INFINITY;
        }

        // Online softmax update
        float mt = m;
#pragma unroll
        for (int j = 0; j < KT; j++) mt = fmaxf(mt, s[j]);
        float scale = __expf(m - mt);        // 0 when m=-inf, mt finite
        l *= scale;
#pragma unroll
        for (int i = 0; i < DK / 4; i++) {
            acc[i].x *= scale; acc[i].y *= scale;
            acc[i].z *= scale; acc[i].w *= scale;
        }
#pragma unroll
        for (int j = 0; j < KT; j++) {
            float p = __expf(s[j] - mt);     // 0 for masked keys
            l += p;
#pragma unroll
            for (int d = 0; d < DK / 4; d++) {
                float4 vv = Vs[j][d];
                acc[d].x += p * vv.x; acc[d].y += p * vv.y;
                acc[d].z += p * vv.z; acc[d].w += p * vv.w;
            }
        }
        m = mt;
        __syncthreads();
    }

    // Write ctx in [B,S,D] layout
    const float inv = 1.f / l;
    float* outp = C + ((size_t)b * SS + qi) * DD + h * DK;
#pragma unroll
    for (int i = 0; i < DK / 4; i++) {
        float4 o = acc[i];
        o.x *= inv; o.y *= inv; o.z *= inv; o.w *= inv;
        ((float4*)outp)[i] = o;
    }
}

// ---------------------------------------------------------------------------
// Launch
// ---------------------------------------------------------------------------
extern "C" void kernel_launch(void* const* d_in, const int* in_sizes, int n_in,
                              void* d_out, int out_size)
{
    const float* q  = (const float*)d_in[0];
    const float* k  = (const float*)d_in[1];
    const float* v  = (const float*)d_in[2];
    // d_in[3] is the causal mask -> hardcoded
    const float* Wq = (const float*)d_in[4];
    const float* bq = (const float*)d_in[5];
    const float* Wk = (const float*)d_in[6];
    const float* bk = (const float*)d_in[7];
    const float* Wv = (const float*)d_in[8];
    const float* bv = (const float*)d_in[9];
    const float* Wo = (const float*)d_in[10];
    const float* bo = (const float*)d_in[11];

    float *gQ, *gK, *gV, *gC;
    cudaGetSymbolAddress((void**)&gQ, g_Q);
    cudaGetSymbolAddress((void**)&gK, g_K);
    cudaGetSymbolAddress((void**)&gV, g_V);
    cudaGetSymbolAddress((void**)&gC, g_C);

    dim3 gemmGrid(DD / TN, MM / TM);   // (8, 64)

    gemm_bias_kernel<<<gemmGrid, 256>>>(q, Wq, bq, gQ, MM, DD, DD, 1);
    gemm_bias_kernel<<<gemmGrid, 256>>>(k, Wk, bk, gK, MM, DD, DD, 1);
    gemm_bias_kernel<<<gemmGrid, 256>>>(v, Wv, bv, gV, MM, DD, DD, 1);

    attn_kernel<<<dim3(SS / 128, HH, BB), 128>>>(gQ, gK, gV, gC);

    gemm_bias_kernel<<<gemmGrid, 256>>>(gC, Wo, bo, (float*)d_out, MM, DD, DD, 0);
}

// round 4
// speedup vs baseline: 2.5481x; 2.5481x over previous
#include <cuda_runtime.h>
#include <cuda_bf16.h>
#include <cstdint>
#include <math.h>

// ---------------------------------------------------------------------------
// Problem constants: B=4, S=2048, D=1024, H=16, dk=64
// ---------------------------------------------------------------------------
#define BB 4
#define SS 2048
#define DD 1024
#define HH 16
#define DK 64
#define MM (BB * SS)          // 8192

// ---------------------------------------------------------------------------
// Scratch (__device__ globals; no cudaMalloc allowed)
// ---------------------------------------------------------------------------
__device__ float g_Q[(size_t)BB * HH * SS * DK];
__device__ float g_K[(size_t)BB * HH * SS * DK];
__device__ float g_V[(size_t)BB * HH * SS * DK];
__device__ float g_C[(size_t)BB * SS * DD];
__device__ __nv_bfloat16 g_Ah[(size_t)MM * DD];   // activation hi
__device__ __nv_bfloat16 g_Al[(size_t)MM * DD];   // activation lo
__device__ __nv_bfloat16 g_Wh[(size_t)DD * DD];   // W hi  [K][N] (no transpose)
__device__ __nv_bfloat16 g_Wl[(size_t)DD * DD];   // W lo  [K][N]

// ---------------------------------------------------------------------------
// PTX helpers (arch-portable: ldmatrix / mma.sync / cp.async only)
// ---------------------------------------------------------------------------
__device__ __forceinline__ uint32_t smem_u32(const void* p) {
    uint32_t a;
    asm("{ .reg .u64 t; cvta.to.shared.u64 t, %1; cvt.u32.u64 %0, t; }" : "=r"(a) : "l"(p));
    return a;
}
__device__ __forceinline__ void cp16(uint32_t saddr, const void* g) {
    asm volatile("cp.async.cg.shared.global [%0], [%1], 16;" :: "r"(saddr), "l"(g) : "memory");
}
#define CP_COMMIT() asm volatile("cp.async.commit_group;" ::: "memory")
#define CP_WAIT(n)  asm volatile("cp.async.wait_group %0;" :: "n"(n) : "memory")

#define LDSM4(r, addr) asm volatile( \
    "ldmatrix.sync.aligned.m8n8.x4.shared.b16 {%0,%1,%2,%3}, [%4];" \
    : "=r"((r)[0]), "=r"((r)[1]), "=r"((r)[2]), "=r"((r)[3]) : "r"(addr))
#define LDSM4T(r, addr) asm volatile( \
    "ldmatrix.sync.aligned.m8n8.x4.trans.shared.b16 {%0,%1,%2,%3}, [%4];" \
    : "=r"((r)[0]), "=r"((r)[1]), "=r"((r)[2]), "=r"((r)[3]) : "r"(addr))

#define MMA16816(d, a, b0, b1) asm volatile( \
    "mma.sync.aligned.m16n8k16.row.col.f32.bf16.bf16.f32 " \
    "{%0,%1,%2,%3}, {%4,%5,%6,%7}, {%8,%9}, {%0,%1,%2,%3};" \
    : "+f"((d)[0]), "+f"((d)[1]), "+f"((d)[2]), "+f"((d)[3]) \
    : "r"((a)[0]), "r"((a)[1]), "r"((a)[2]), "r"((a)[3]), "r"(b0), "r"(b1))

// ---------------------------------------------------------------------------
// Conversion: fp32 -> (bf16 hi, bf16 lo),  lo = bf16(x - float(hi))
// ---------------------------------------------------------------------------
__global__ __launch_bounds__(256)
void convert_hi_lo(const float* __restrict__ x,
                   __nv_bfloat16* __restrict__ hi,
                   __nv_bfloat16* __restrict__ lo, int n4)
{
    int i = blockIdx.x * blockDim.x + threadIdx.x;
    if (i >= n4) return;
    float4 v = ((const float4*)x)[i];
    __nv_bfloat16 h0 = __float2bfloat16(v.x);
    __nv_bfloat16 h1 = __float2bfloat16(v.y);
    __nv_bfloat16 h2 = __float2bfloat16(v.z);
    __nv_bfloat16 h3 = __float2bfloat16(v.w);
    __nv_bfloat162 hA = __halves2bfloat162(h0, h1);
    __nv_bfloat162 hB = __halves2bfloat162(h2, h3);
    __nv_bfloat162 lA = __halves2bfloat162(__float2bfloat16(v.x - __bfloat162float(h0)),
                                           __float2bfloat16(v.y - __bfloat162float(h1)));
    __nv_bfloat162 lB = __halves2bfloat162(__float2bfloat16(v.z - __bfloat162float(h2)),
                                           __float2bfloat16(v.w - __bfloat162float(h3)));
    ((__nv_bfloat162*)hi)[2*i]   = hA;
    ((__nv_bfloat162*)hi)[2*i+1] = hB;
    ((__nv_bfloat162*)lo)[2*i]   = lA;
    ((__nv_bfloat162*)lo)[2*i+1] = lB;
}

// ---------------------------------------------------------------------------
// HMMA GEMM: out[M,N] = A[M,K] @ W[K,N] + bias, 3-pass bf16 split.
// CTA 128x128, 8 warps (4M x 2N), warp tile 32x64, KC=32, 2-stage cp.async.
// A tile: [128 m][32 k] bf16, pitch 40 elems (80B) -> conflict-free ldmatrix.
// B tile: [32 k][128 n] bf16, pitch 136 elems (272B) -> conflict-free trans.
// ---------------------------------------------------------------------------
#define KC 32
#define PA_B 80        // A row pitch bytes
#define PB_B 272       // B row pitch bytes
#define A_BYTES (128 * PA_B)    // 10240
#define B_BYTES (KC * PB_B)     // 8704
#define OFF_AH 0
#define OFF_AL A_BYTES
#define OFF_BH (2 * A_BYTES)
#define OFF_BL (2 * A_BYTES + B_BYTES)
#define STAGE (2 * A_BYTES + 2 * B_BYTES)   // 37888
#define SMEM_SZ (2 * STAGE)                 // 75776

__global__ __launch_bounds__(256)
void tc_gemm(const __nv_bfloat16* __restrict__ Ah,
             const __nv_bfloat16* __restrict__ Al,
             const __nv_bfloat16* __restrict__ Wh,
             const __nv_bfloat16* __restrict__ Wl,
             const float* __restrict__ bias,
             float* __restrict__ out, int splitHeads)
{
    extern __shared__ char smem[];
    const uint32_t sb = smem_u32(smem);
    const int tid = threadIdx.x;
    const int lane = tid & 31;
    const int warp = tid >> 5;
    const int warpM = warp >> 1;       // 0..3
    const int warpN = warp & 1;        // 0..1
    const int rowBase = blockIdx.y * 128;
    const int colBase = blockIdx.x * 128;

    float acc[2][8][4];
#pragma unroll
    for (int mi = 0; mi < 2; mi++)
#pragma unroll
        for (int ni = 0; ni < 8; ni++)
#pragma unroll
            for (int r = 0; r < 4; r++) acc[mi][ni][r] = 0.f;

    // ---- stage loader: 2048 x 16B chunks, 8 per thread ----
    auto load_stage = [&](int ch, int s) {
        const int k0 = ch * KC;
        const uint32_t sbase = sb + s * STAGE;
#pragma unroll
        for (int i = 0; i < 8; i++) {
            int idx = tid + i * 256;
            int t = idx >> 9;          // 0:Ah 1:Al 2:Bh 3:Bl
            int w = idx & 511;
            if (t < 2) {
                int r = w >> 2, c = w & 3;
                const __nv_bfloat16* src =
                    (t == 0 ? Ah : Al) + (size_t)(rowBase + r) * DD + k0 + c * 8;
                cp16(sbase + (t == 0 ? OFF_AH : OFF_AL) + r * PA_B + c * 16, src);
            } else {
                int r = w >> 4, c = w & 15;
                const __nv_bfloat16* src =
                    (t == 2 ? Wh : Wl) + (size_t)(k0 + r) * DD + colBase + c * 8;
                cp16(sbase + (t == 2 ? OFF_BH : OFF_BL) + r * PB_B + c * 16, src);
            }
        }
        CP_COMMIT();
    };

    load_stage(0, 0);

    const int NCH = DD / KC;   // 32
    for (int ch = 0; ch < NCH; ch++) {
        if (ch + 1 < NCH) {
            load_stage(ch + 1, (ch + 1) & 1);
            CP_WAIT(1);
        } else {
            CP_WAIT(0);
        }
        __syncthreads();

        const uint32_t stb = sb + (ch & 1) * STAGE;
#pragma unroll
        for (int kstep = 0; kstep < 2; kstep++) {
            // A fragments (row-major, non-trans ldmatrix)
            uint32_t ah[2][4], al[2][4];
#pragma unroll
            for (int mi = 0; mi < 2; mi++) {
                uint32_t row = warpM * 32 + mi * 16 + (lane & 15);
                uint32_t ad = stb + OFF_AH + row * PA_B + kstep * 32 + (lane >> 4) * 16;
                LDSM4(ah[mi], ad);
                LDSM4(al[mi], ad + (OFF_AL - OFF_AH));
            }
            // B fragments (k-major W, trans ldmatrix): 4 x4 loads cover n64
            uint32_t bh[4][4], bl[4][4];
#pragma unroll
            for (int ng = 0; ng < 4; ng++) {
                uint32_t krow = kstep * 16 + (lane & 15);
                uint32_t coln = warpN * 64 + ng * 16 + (lane >> 4) * 8;
                uint32_t bd = stb + OFF_BH + krow * PB_B + coln * 2;
                LDSM4T(bh[ng], bd);
                LDSM4T(bl[ng], bd + (OFF_BL - OFF_BH));
            }
            // 3-pass split MMA
#pragma unroll
            for (int mi = 0; mi < 2; mi++)
#pragma unroll
                for (int ni = 0; ni < 8; ni++) {
                    uint32_t b0h = bh[ni >> 1][(ni & 1) * 2];
                    uint32_t b1h = bh[ni >> 1][(ni & 1) * 2 + 1];
                    uint32_t b0l = bl[ni >> 1][(ni & 1) * 2];
                    uint32_t b1l = bl[ni >> 1][(ni & 1) * 2 + 1];
                    MMA16816(acc[mi][ni], ah[mi], b0h, b1h);
                    MMA16816(acc[mi][ni], ah[mi], b0l, b1l);
                    MMA16816(acc[mi][ni], al[mi], b0h, b1h);
                }
        }
        __syncthreads();
    }

    // ---- epilogue ----
    const int lg = lane >> 2;          // 0..7
    const int l4 = lane & 3;           // 0..3
#pragma unroll
    for (int mi = 0; mi < 2; mi++) {
#pragma unroll
        for (int ni = 0; ni < 8; ni++) {
            int r0 = rowBase + warpM * 32 + mi * 16 + lg;
            int col = colBase + warpN * 64 + ni * 8 + l4 * 2;
            float2 v0, v1;
            v0.x = acc[mi][ni][0] + bias[col];
            v0.y = acc[mi][ni][1] + bias[col + 1];
            v1.x = acc[mi][ni][2] + bias[col];
            v1.y = acc[mi][ni][3] + bias[col + 1];
            if (splitHeads) {
                int h = col >> 6, dd = col & (DK - 1);
                int b0r = r0 >> 11, s0 = r0 & (SS - 1);
                int r1 = r0 + 8;
                int b1r = r1 >> 11, s1 = r1 & (SS - 1);
                *(float2*)(out + (((size_t)(b0r * HH + h)) * SS + s0) * DK + dd) = v0;
                *(float2*)(out + (((size_t)(b1r * HH + h)) * SS + s1) * DK + dd) = v1;
            } else {
                *(float2*)(out + (size_t)r0 * DD + col) = v0;
                *(float2*)(out + (size_t)(r0 + 8) * DD + col) = v1;
            }
        }
    }
}

// ---------------------------------------------------------------------------
// Causal flash attention, fp32 (unchanged from passing round).
// ---------------------------------------------------------------------------
#define KT 16

__global__ __launch_bounds__(128)
void attn_kernel(const float* __restrict__ Q,
                 const float* __restrict__ K,
                 const float* __restrict__ V,
                 float* __restrict__ C)
{
    __shared__ float4 Ks[KT][DK / 4];
    __shared__ float4 Vs[KT][DK / 4];

    const int qt = blockIdx.x;
    const int h  = blockIdx.y;
    const int b  = blockIdx.z;
    const size_t bh = (size_t)(b * HH + h);
    const float* Qb = Q + bh * SS * DK;
    const float* Kb = K + bh * SS * DK;
    const float* Vb = V + bh * SS * DK;

    const int qi = qt * 128 + threadIdx.x;

    float4 q[DK / 4];
    const float4* qp = (const float4*)(Qb + (size_t)qi * DK);
#pragma unroll
    for (int i = 0; i < DK / 4; i++) {
        float4 t = qp[i];
        t.x *= 0.125f; t.y *= 0.125f; t.z *= 0.125f; t.w *= 0.125f;
        q[i] = t;
    }

    float4 acc[DK / 4];
#pragma unroll
    for (int i = 0; i < DK / 4; i++) acc[i] = make_float4(0.f, 0.f, 0.f, 0.f);
    float m = -INFINITY, l = 0.f;

    const int kend = qt * 128 + 128;

    for (int j0 = 0; j0 < kend; j0 += KT) {
        const float4* Ksrc = (const float4*)(Kb + (size_t)j0 * DK);
        const float4* Vsrc = (const float4*)(Vb + (size_t)j0 * DK);
#pragma unroll
        for (int i = 0; i < 2; i++) {
            int idx = threadIdx.x + i * 128;
            ((float4*)Ks)[idx] = Ksrc[idx];
            ((float4*)Vs)[idx] = Vsrc[idx];
        }
        __syncthreads();

        float s[KT];
#pragma unroll
        for (int j = 0; j < KT; j++) {
            float4 sum = make_float4(0.f, 0.f, 0.f, 0.f);
#pragma unroll
            for (int d = 0; d < DK / 4; d++) {
                float4 kk = Ks[j][d];
                sum.x += q[d].x * kk.x; sum.y += q[d].y * kk.y;
                sum.z += q[d].z * kk.z; sum.w += q[d].w * kk.w;
            }
            float sv = (sum.x + sum.y) + (sum.z + sum.w);
            s[j] = ((j0 + j) <= qi) ? sv : -INFINITY;
        }

        float mt = m;
#pragma unroll
        for (int j = 0; j < KT; j++) mt = fmaxf(mt, s[j]);
        float scale = __expf(m - mt);
        l *= scale;
#pragma unroll
        for (int i = 0; i < DK / 4; i++) {
            acc[i].x *= scale; acc[i].y *= scale;
            acc[i].z *= scale; acc[i].w *= scale;
        }
#pragma unroll
        for (int j = 0; j < KT; j++) {
            float p = __expf(s[j] - mt);
            l += p;
#pragma unroll
            for (int d = 0; d < DK / 4; d++) {
                float4 vv = Vs[j][d];
                acc[d].x += p * vv.x; acc[d].y += p * vv.y;
                acc[d].z += p * vv.z; acc[d].w += p * vv.w;
            }
        }
        m = mt;
        __syncthreads();
    }

    const float inv = 1.f / l;
    float* outp = C + ((size_t)b * SS + qi) * DD + h * DK;
#pragma unroll
    for (int i = 0; i < DK / 4; i++) {
        float4 o = acc[i];
        o.x *= inv; o.y *= inv; o.z *= inv; o.w *= inv;
        ((float4*)outp)[i] = o;
    }
}

// ---------------------------------------------------------------------------
// Launch
// ---------------------------------------------------------------------------
extern "C" void kernel_launch(void* const* d_in, const int* in_sizes, int n_in,
                              void* d_out, int out_size)
{
    const float* q  = (const float*)d_in[0];
    const float* k  = (const float*)d_in[1];
    const float* v  = (const float*)d_in[2];
    const float* Wq = (const float*)d_in[4];
    const float* bq = (const float*)d_in[5];
    const float* Wk = (const float*)d_in[6];
    const float* bk = (const float*)d_in[7];
    const float* Wv = (const float*)d_in[8];
    const float* bv = (const float*)d_in[9];
    const float* Wo = (const float*)d_in[10];
    const float* bo = (const float*)d_in[11];

    float *gQ, *gK, *gV, *gC;
    __nv_bfloat16 *gAh, *gAl, *gWh, *gWl;
    cudaGetSymbolAddress((void**)&gQ, g_Q);
    cudaGetSymbolAddress((void**)&gK, g_K);
    cudaGetSymbolAddress((void**)&gV, g_V);
    cudaGetSymbolAddress((void**)&gC, g_C);
    cudaGetSymbolAddress((void**)&gAh, g_Ah);
    cudaGetSymbolAddress((void**)&gAl, g_Al);
    cudaGetSymbolAddress((void**)&gWh, g_Wh);
    cudaGetSymbolAddress((void**)&gWl, g_Wl);

    cudaFuncSetAttribute(tc_gemm, cudaFuncAttributeMaxDynamicSharedMemorySize, SMEM_SZ);

    const int n4a = MM * DD / 4;     // activations
    const int n4w = DD * DD / 4;     // weights
    dim3 cgridA((n4a + 255) / 256);
    dim3 cgridW((n4w + 255) / 256);
    dim3 ggrid(DD / 128, MM / 128);  // (8, 64)

    // Q projection
    convert_hi_lo<<<cgridA, 256>>>(q, gAh, gAl, n4a);
    convert_hi_lo<<<cgridW, 256>>>(Wq, gWh, gWl, n4w);
    tc_gemm<<<ggrid, 256, SMEM_SZ>>>(gAh, gAl, gWh, gWl, bq, gQ, 1);
    // K projection
    convert_hi_lo<<<cgridA, 256>>>(k, gAh, gAl, n4a);
    convert_hi_lo<<<cgridW, 256>>>(Wk, gWh, gWl, n4w);
    tc_gemm<<<ggrid, 256, SMEM_SZ>>>(gAh, gAl, gWh, gWl, bk, gK, 1);
    // V projection
    convert_hi_lo<<<cgridA, 256>>>(v, gAh, gAl, n4a);
    convert_hi_lo<<<cgridW, 256>>>(Wv, gWh, gWl, n4w);
    tc_gemm<<<ggrid, 256, SMEM_SZ>>>(gAh, gAl, gWh, gWl, bv, gV, 1);

    // Attention
    attn_kernel<<<dim3(SS / 128, HH, BB), 128>>>(gQ, gK, gV, gC);

    // Output projection
    convert_hi_lo<<<cgridA, 256>>>(gC, gAh, gAl, n4a);
    convert_hi_lo<<<cgridW, 256>>>(Wo, gWh, gWl, n4w);
    tc_gemm<<<ggrid, 256, SMEM_SZ>>>(gAh, gAl, gWh, gWl, bo, (float*)d_out, 0);
}

// round 6
// speedup vs baseline: 5.2919x; 2.0768x over previous
#include <cuda_runtime.h>
#include <cuda_bf16.h>
#include <cstdint>
#include <math.h>

// ---------------------------------------------------------------------------
// Problem constants: B=4, S=2048, D=1024, H=16, dk=64
// ---------------------------------------------------------------------------
#define BB 4
#define SS 2048
#define DD 1024
#define HH 16
#define DK 64
#define MM (BB * SS)          // 8192

// ---------------------------------------------------------------------------
// Scratch (__device__ globals; no cudaMalloc allowed)
// ---------------------------------------------------------------------------
__device__ __nv_bfloat16 g_Qh[(size_t)BB * HH * SS * DK];
__device__ __nv_bfloat16 g_Ql[(size_t)BB * HH * SS * DK];
__device__ __nv_bfloat16 g_Kh[(size_t)BB * HH * SS * DK];
__device__ __nv_bfloat16 g_Kl[(size_t)BB * HH * SS * DK];
__device__ __nv_bfloat16 g_Vh[(size_t)BB * HH * SS * DK];
__device__ __nv_bfloat16 g_Vl[(size_t)BB * HH * SS * DK];
__device__ __nv_bfloat16 g_Ah[(size_t)MM * DD];   // activation hi (also ctx hi)
__device__ __nv_bfloat16 g_Al[(size_t)MM * DD];   // activation lo (also ctx lo)
__device__ __nv_bfloat16 g_Wh[(size_t)DD * DD];   // W hi [K][N]
__device__ __nv_bfloat16 g_Wl[(size_t)DD * DD];   // W lo [K][N]

// ---------------------------------------------------------------------------
// PTX helpers (arch-portable: ldmatrix / mma.sync / cp.async only)
// ---------------------------------------------------------------------------
__device__ __forceinline__ uint32_t smem_u32(const void* p) {
    uint32_t a;
    asm("{ .reg .u64 t; cvta.to.shared.u64 t, %1; cvt.u32.u64 %0, t; }" : "=r"(a) : "l"(p));
    return a;
}
__device__ __forceinline__ void cp16(uint32_t saddr, const void* g) {
    asm volatile("cp.async.cg.shared.global [%0], [%1], 16;" :: "r"(saddr), "l"(g) : "memory");
}
#define CP_COMMIT() asm volatile("cp.async.commit_group;" ::: "memory")
#define CP_WAIT(n)  asm volatile("cp.async.wait_group %0;" :: "n"(n) : "memory")

#define LDSM4(r, addr) asm volatile( \
    "ldmatrix.sync.aligned.m8n8.x4.shared.b16 {%0,%1,%2,%3}, [%4];" \
    : "=r"((r)[0]), "=r"((r)[1]), "=r"((r)[2]), "=r"((r)[3]) : "r"(addr))
#define LDSM4T(r, addr) asm volatile( \
    "ldmatrix.sync.aligned.m8n8.x4.trans.shared.b16 {%0,%1,%2,%3}, [%4];" \
    : "=r"((r)[0]), "=r"((r)[1]), "=r"((r)[2]), "=r"((r)[3]) : "r"(addr))

#define MMA16816(d, a, b0, b1) asm volatile( \
    "mma.sync.aligned.m16n8k16.row.col.f32.bf16.bf16.f32 " \
    "{%0,%1,%2,%3}, {%4,%5,%6,%7}, {%8,%9}, {%0,%1,%2,%3};" \
    : "+f"((d)[0]), "+f"((d)[1]), "+f"((d)[2]), "+f"((d)[3]) \
    : "r"((a)[0]), "r"((a)[1]), "r"((a)[2]), "r"((a)[3]), "r"(b0), "r"(b1))

// split two fp32 into packed bf16x2 (hi) and bf16x2 (lo residual)
__device__ __forceinline__ void split2(float x, float y, uint32_t& hp, uint32_t& lp) {
    __nv_bfloat16 hx = __float2bfloat16(x), hy = __float2bfloat16(y);
    __nv_bfloat162 hh = __halves2bfloat162(hx, hy);
    __nv_bfloat162 ll = __halves2bfloat162(__float2bfloat16(x - __bfloat162float(hx)),
                                           __float2bfloat16(y - __bfloat162float(hy)));
    hp = *reinterpret_cast<uint32_t*>(&hh);
    lp = *reinterpret_cast<uint32_t*>(&ll);
}

// ---------------------------------------------------------------------------
// Conversion: fp32 -> (bf16 hi, bf16 lo)
// ---------------------------------------------------------------------------
__global__ __launch_bounds__(256)
void convert_hi_lo(const float* __restrict__ x,
                   __nv_bfloat16* __restrict__ hi,
                   __nv_bfloat16* __restrict__ lo, int n4)
{
    int i = blockIdx.x * blockDim.x + threadIdx.x;
    if (i >= n4) return;
    float4 v = ((const float4*)x)[i];
    uint32_t h0, l0, h1, l1;
    split2(v.x, v.y, h0, l0);
    split2(v.z, v.w, h1, l1);
    ((uint32_t*)hi)[2*i]   = h0;
    ((uint32_t*)hi)[2*i+1] = h1;
    ((uint32_t*)lo)[2*i]   = l0;
    ((uint32_t*)lo)[2*i+1] = l1;
}

// ---------------------------------------------------------------------------
// HMMA GEMM: out = A[M,K] @ W[K,N] + bias, 3-pass bf16 split.
// CTA 128x128, 8 warps (4M x 2N), KC=32, 2-stage cp.async.
// outF != null -> fp32 [M,N].  Else -> bf16 hi/lo, [B,H,S,dk], scaled.
// ---------------------------------------------------------------------------
#define KC 32
#define PA_B 80
#define PB_B 272
#define A_BYTES (128 * PA_B)
#define B_BYTES (KC * PB_B)
#define OFF_AH 0
#define OFF_AL A_BYTES
#define OFF_BH (2 * A_BYTES)
#define OFF_BL (2 * A_BYTES + B_BYTES)
#define STAGE (2 * A_BYTES + 2 * B_BYTES)
#define SMEM_SZ (2 * STAGE)

__global__ __launch_bounds__(256)
void tc_gemm(const __nv_bfloat16* __restrict__ Ah,
             const __nv_bfloat16* __restrict__ Al,
             const __nv_bfloat16* __restrict__ Wh,
             const __nv_bfloat16* __restrict__ Wl,
             const float* __restrict__ bias,
             float* __restrict__ outF,
             __nv_bfloat16* __restrict__ outH,
             __nv_bfloat16* __restrict__ outL,
             float scale)
{
    extern __shared__ char smem[];
    const uint32_t sb = smem_u32(smem);
    const int tid = threadIdx.x;
    const int lane = tid & 31;
    const int warp = tid >> 5;
    const int warpM = warp >> 1;
    const int warpN = warp & 1;
    const int rowBase = blockIdx.y * 128;
    const int colBase = blockIdx.x * 128;

    float acc[2][8][4];
#pragma unroll
    for (int mi = 0; mi < 2; mi++)
#pragma unroll
        for (int ni = 0; ni < 8; ni++)
#pragma unroll
            for (int r = 0; r < 4; r++) acc[mi][ni][r] = 0.f;

    auto load_stage = [&](int ch, int s) {
        const int k0 = ch * KC;
        const uint32_t sbase = sb + s * STAGE;
#pragma unroll
        for (int i = 0; i < 8; i++) {
            int idx = tid + i * 256;
            int t = idx >> 9;
            int w = idx & 511;
            if (t < 2) {
                int r = w >> 2, c = w & 3;
                const __nv_bfloat16* src =
                    (t == 0 ? Ah : Al) + (size_t)(rowBase + r) * DD + k0 + c * 8;
                cp16(sbase + (t == 0 ? OFF_AH : OFF_AL) + r * PA_B + c * 16, src);
            } else {
                int r = w >> 4, c = w & 15;
                const __nv_bfloat16* src =
                    (t == 2 ? Wh : Wl) + (size_t)(k0 + r) * DD + colBase + c * 8;
                cp16(sbase + (t == 2 ? OFF_BH : OFF_BL) + r * PB_B + c * 16, src);
            }
        }
        CP_COMMIT();
    };

    load_stage(0, 0);

    const int NCH = DD / KC;
    for (int ch = 0; ch < NCH; ch++) {
        if (ch + 1 < NCH) {
            load_stage(ch + 1, (ch + 1) & 1);
            CP_WAIT(1);
        } else {
            CP_WAIT(0);
        }
        __syncthreads();

        const uint32_t stb = sb + (ch & 1) * STAGE;
#pragma unroll
        for (int kstep = 0; kstep < 2; kstep++) {
            uint32_t ah[2][4], al[2][4];
#pragma unroll
            for (int mi = 0; mi < 2; mi++) {
                uint32_t row = warpM * 32 + mi * 16 + (lane & 15);
                uint32_t ad = stb + OFF_AH + row * PA_B + kstep * 32 + (lane >> 4) * 16;
                LDSM4(ah[mi], ad);
                LDSM4(al[mi], ad + (OFF_AL - OFF_AH));
            }
            uint32_t bh[4][4], bl[4][4];
#pragma unroll
            for (int ng = 0; ng < 4; ng++) {
                uint32_t krow = kstep * 16 + (lane & 15);
                uint32_t coln = warpN * 64 + ng * 16 + (lane >> 4) * 8;
                uint32_t bd = stb + OFF_BH + krow * PB_B + coln * 2;
                LDSM4T(bh[ng], bd);
                LDSM4T(bl[ng], bd + (OFF_BL - OFF_BH));
            }
#pragma unroll
            for (int mi = 0; mi < 2; mi++)
#pragma unroll
                for (int ni = 0; ni < 8; ni++) {
                    uint32_t b0h = bh[ni >> 1][(ni & 1) * 2];
                    uint32_t b1h = bh[ni >> 1][(ni & 1) * 2 + 1];
                    uint32_t b0l = bl[ni >> 1][(ni & 1) * 2];
                    uint32_t b1l = bl[ni >> 1][(ni & 1) * 2 + 1];
                    MMA16816(acc[mi][ni], ah[mi], b0h, b1h);
                    MMA16816(acc[mi][ni], ah[mi], b0l, b1l);
                    MMA16816(acc[mi][ni], al[mi], b0h, b1h);
                }
        }
        __syncthreads();
    }

    // ---- epilogue ----
    const int lg = lane >> 2;
    const int l4 = lane & 3;
#pragma unroll
    for (int mi = 0; mi < 2; mi++) {
#pragma unroll
        for (int ni = 0; ni < 8; ni++) {
            int r0 = rowBase + warpM * 32 + mi * 16 + lg;
            int r1 = r0 + 8;
            int col = colBase + warpN * 64 + ni * 8 + l4 * 2;
            float v00 = (acc[mi][ni][0] + bias[col]) * scale;
            float v01 = (acc[mi][ni][1] + bias[col + 1]) * scale;
            float v10 = (acc[mi][ni][2] + bias[col]) * scale;
            float v11 = (acc[mi][ni][3] + bias[col + 1]) * scale;
            if (outF) {
                *(float2*)(outF + (size_t)r0 * DD + col) = make_float2(v00, v01);
                *(float2*)(outF + (size_t)r1 * DD + col) = make_float2(v10, v11);
            } else {
                int h = col >> 6, dd = col & (DK - 1);
                int b0r = r0 >> 11, s0 = r0 & (SS - 1);
                int b1r = r1 >> 11, s1 = r1 & (SS - 1);
                size_t o0 = (((size_t)(b0r * HH + h)) * SS + s0) * DK + dd;
                size_t o1 = (((size_t)(b1r * HH + h)) * SS + s1) * DK + dd;
                uint32_t hp, lp;
                split2(v00, v01, hp, lp);
                *(uint32_t*)(outH + o0) = hp;
                *(uint32_t*)(outL + o0) = lp;
                split2(v10, v11, hp, lp);
                *(uint32_t*)(outH + o1) = hp;
                *(uint32_t*)(outL + o1) = lp;
            }
        }
    }
}

// ---------------------------------------------------------------------------
// HMMA causal flash attention.
// CTA: 128 q-rows of one (b,h); 8 warps x 16 rows; 64-key tiles, 2-stage.
// Split-bf16: S = Qh Kh^T + Qh Kl^T + Ql Kh^T;  O += Ph Vh + Ph Vl + Pl Vh.
// Writes ctx hi/lo bf16 in [B,S,D] layout (O-proj activation format).
// ---------------------------------------------------------------------------
#define APITCH 144
#define ASQH 0
#define ASQL 18432
#define AKV0 36864
#define AKSTAGE 36864          // Kh(9216) Kl Vh Vl
#define ATT_SMEM (AKV0 + 2 * AKSTAGE)   // 110592

__global__ __launch_bounds__(256)
void attn_mma(const __nv_bfloat16* __restrict__ Qh, const __nv_bfloat16* __restrict__ Ql,
              const __nv_bfloat16* __restrict__ Kh, const __nv_bfloat16* __restrict__ Kl,
              const __nv_bfloat16* __restrict__ Vh, const __nv_bfloat16* __restrict__ Vl,
              __nv_bfloat16* __restrict__ Ch, __nv_bfloat16* __restrict__ Cl)
{
    extern __shared__ char smem[];
    const uint32_t sb = smem_u32(smem);
    const int tid = threadIdx.x;
    const int lane = tid & 31;
    const int warp = tid >> 5;
    const int lg = lane >> 2;
    const int l4 = lane & 3;

    const int qt = 15 - blockIdx.x;   // heavy tiles first
    const int h  = blockIdx.y;
    const int b  = blockIdx.z;
    const size_t bhoff = (size_t)(b * HH + h) * SS * DK;

    // --- stage Q (hi+lo) ---
#pragma unroll
    for (int i = 0; i < 8; i++) {
        int idx = tid + i * 256;
        int mat = idx >> 10;           // 0:Qh 1:Ql
        int w = idx & 1023;
        int r = w >> 3, c = w & 7;
        const __nv_bfloat16* src = (mat ? Ql : Qh) + bhoff + (size_t)(qt * 128 + r) * DK + c * 8;
        cp16(sb + mat * 18432 + r * APITCH + c * 16, src);
    }
    CP_COMMIT();

    auto kv_load = [&](int jt, int st) {
        uint32_t base = sb + AKV0 + st * AKSTAGE;
        size_t koff = bhoff + (size_t)jt * 64 * DK;
#pragma unroll
        for (int i = 0; i < 8; i++) {
            int idx = tid + i * 256;
            int mat = idx >> 9;        // 0:Kh 1:Kl 2:Vh 3:Vl
            int w = idx & 511;
            int r = w >> 3, c = w & 7;
            const __nv_bfloat16* mp = (mat == 0) ? Kh : (mat == 1) ? Kl : (mat == 2) ? Vh : Vl;
            cp16(base + mat * 9216 + r * APITCH + c * 16, mp + koff + (size_t)r * DK + c * 8);
        }
        CP_COMMIT();
    };

    kv_load(0, 0);
    CP_WAIT(1);                  // Q group done
    __syncthreads();

    // --- Q fragments in registers ---
    uint32_t qah[4][4], qal[4][4];
#pragma unroll
    for (int kk = 0; kk < 4; kk++) {
        uint32_t ad = sb + ASQH + (warp * 16 + (lane & 15)) * APITCH + kk * 32 + (lane >> 4) * 16;
        LDSM4(qah[kk], ad);
        LDSM4(qal[kk], ad + (ASQL - ASQH));
    }

    float o[8][4];
#pragma unroll
    for (int c = 0; c < 8; c++)
#pragma unroll
        for (int r = 0; r < 4; r++) o[c][r] = 0.f;
    float m0 = -1e30f, m1 = -1e30f, l0 = 0.f, l1 = 0.f;

    const int row0 = qt * 128 + warp * 16 + lg;   // rows for regs {0,1}; {2,3} = row0+8
    const int ntiles = 2 * qt + 2;

    for (int jt = 0; jt < ntiles; jt++) {
        if (jt + 1 < ntiles) { kv_load(jt + 1, (jt + 1) & 1); CP_WAIT(1); }
        else                 { CP_WAIT(0); }
        __syncthreads();

        const uint32_t kvb = sb + AKV0 + (jt & 1) * AKSTAGE;

        // ---- scores: S = Qh Kh + Qh Kl + Ql Kh ----
        float s[8][4];
#pragma unroll
        for (int c = 0; c < 8; c++)
#pragma unroll
            for (int r = 0; r < 4; r++) s[c][r] = 0.f;

#pragma unroll
        for (int ng = 0; ng < 4; ng++) {
#pragma unroll
            for (int kk = 0; kk < 4; kk++) {
                uint32_t kh[4], kl[4];
                uint32_t ka = kvb + (ng * 16 + (lane & 15)) * APITCH + kk * 32 + (lane >> 4) * 16;
                LDSM4(kh, ka);
                LDSM4(kl, ka + 9216);
                MMA16816(s[2 * ng],     qah[kk], kh[0], kh[2]);
                MMA16816(s[2 * ng],     qah[kk], kl[0], kl[2]);
                MMA16816(s[2 * ng],     qal[kk], kh[0], kh[2]);
                MMA16816(s[2 * ng + 1], qah[kk], kh[1], kh[3]);
                MMA16816(s[2 * ng + 1], qah[kk], kl[1], kl[3]);
                MMA16816(s[2 * ng + 1], qal[kk], kh[1], kh[3]);
            }
        }

        // ---- causal mask: apply whenever this key tile can exceed the
        //      warp's MINIMUM row (warp rows are warp*16 .. warp*16+15) ----
        if (jt * 64 + 63 > qt * 128 + warp * 16) {
#pragma unroll
            for (int c = 0; c < 8; c++) {
                int col = jt * 64 + c * 8 + 2 * l4;
                if (col > row0)         s[c][0] = -1e30f;
                if (col + 1 > row0)     s[c][1] = -1e30f;
                if (col > row0 + 8)     s[c][2] = -1e30f;
                if (col + 1 > row0 + 8) s[c][3] = -1e30f;
            }
        }

        // ---- online softmax ----
        float mx0 = -1e30f, mx1 = -1e30f;
#pragma unroll
        for (int c = 0; c < 8; c++) {
            mx0 = fmaxf(mx0, fmaxf(s[c][0], s[c][1]));
            mx1 = fmaxf(mx1, fmaxf(s[c][2], s[c][3]));
        }
        mx0 = fmaxf(mx0, __shfl_xor_sync(0xFFFFFFFFu, mx0, 1));
        mx0 = fmaxf(mx0, __shfl_xor_sync(0xFFFFFFFFu, mx0, 2));
        mx1 = fmaxf(mx1, __shfl_xor_sync(0xFFFFFFFFu, mx1, 1));
        mx1 = fmaxf(mx1, __shfl_xor_sync(0xFFFFFFFFu, mx1, 2));
        float mn0 = fmaxf(m0, mx0), mn1 = fmaxf(m1, mx1);
        float sc0 = __expf(m0 - mn0), sc1 = __expf(m1 - mn1);
        m0 = mn0; m1 = mn1;
        l0 *= sc0; l1 *= sc1;
#pragma unroll
        for (int c = 0; c < 8; c++) {
            o[c][0] *= sc0; o[c][1] *= sc0;
            o[c][2] *= sc1; o[c][3] *= sc1;
        }
#pragma unroll
        for (int c = 0; c < 8; c++) {
            s[c][0] = __expf(s[c][0] - mn0);
            s[c][1] = __expf(s[c][1] - mn0);
            s[c][2] = __expf(s[c][2] - mn1);
            s[c][3] = __expf(s[c][3] - mn1);
            l0 += s[c][0] + s[c][1];
            l1 += s[c][2] + s[c][3];
        }

        // ---- P fragments (hi/lo), FA2 register reuse ----
        uint32_t pah[4][4], pal[4][4];
#pragma unroll
        for (int kk = 0; kk < 4; kk++) {
            split2(s[2 * kk][0],     s[2 * kk][1],     pah[kk][0], pal[kk][0]);
            split2(s[2 * kk][2],     s[2 * kk][3],     pah[kk][1], pal[kk][1]);
            split2(s[2 * kk + 1][0], s[2 * kk + 1][1], pah[kk][2], pal[kk][2]);
            split2(s[2 * kk + 1][2], s[2 * kk + 1][3], pah[kk][3], pal[kk][3]);
        }

        // ---- O += Ph Vh + Ph Vl + Pl Vh ----
#pragma unroll
        for (int dg = 0; dg < 4; dg++) {
#pragma unroll
            for (int kk = 0; kk < 4; kk++) {
                uint32_t vh[4], vl[4];
                uint32_t va = kvb + 18432 + (kk * 16 + (lane & 15)) * APITCH
                            + dg * 32 + (lane >> 4) * 16;
                LDSM4T(vh, va);
                LDSM4T(vl, va + 9216);
                MMA16816(o[2 * dg],     pah[kk], vh[0], vh[1]);
                MMA16816(o[2 * dg],     pah[kk], vl[0], vl[1]);
                MMA16816(o[2 * dg],     pal[kk], vh[0], vh[1]);
                MMA16816(o[2 * dg + 1], pah[kk], vh[2], vh[3]);
                MMA16816(o[2 * dg + 1], pah[kk], vl[2], vl[3]);
                MMA16816(o[2 * dg + 1], pal[kk], vh[2], vh[3]);
            }
        }
        __syncthreads();
    }

    // ---- finalize: normalize and write ctx hi/lo in [B,S,D] ----
    l0 += __shfl_xor_sync(0xFFFFFFFFu, l0, 1);
    l0 += __shfl_xor_sync(0xFFFFFFFFu, l0, 2);
    l1 += __shfl_xor_sync(0xFFFFFFFFu, l1, 1);
    l1 += __shfl_xor_sync(0xFFFFFFFFu, l1, 2);
    const float inv0 = 1.f / l0, inv1 = 1.f / l1;

    const size_t r0 = (size_t)b * SS + row0;
    const size_t r1 = r0 + 8;
#pragma unroll
    for (int c = 0; c < 8; c++) {
        int col = h * DK + c * 8 + 2 * l4;
        uint32_t hp, lp;
        split2(o[c][0] * inv0, o[c][1] * inv0, hp, lp);
        *(uint32_t*)(Ch + r0 * DD + col) = hp;
        *(uint32_t*)(Cl + r0 * DD + col) = lp;
        split2(o[c][2] * inv1, o[c][3] * inv1, hp, lp);
        *(uint32_t*)(Ch + r1 * DD + col) = hp;
        *(uint32_t*)(Cl + r1 * DD + col) = lp;
    }
}

// ---------------------------------------------------------------------------
// Launch
// ---------------------------------------------------------------------------
extern "C" void kernel_launch(void* const* d_in, const int* in_sizes, int n_in,
                              void* d_out, int out_size)
{
    const float* q  = (const float*)d_in[0];
    const float* k  = (const float*)d_in[1];
    const float* v  = (const float*)d_in[2];
    const float* Wq = (const float*)d_in[4];
    const float* bq = (const float*)d_in[5];
    const float* Wk = (const float*)d_in[6];
    const float* bk = (const float*)d_in[7];
    const float* Wv = (const float*)d_in[8];
    const float* bv = (const float*)d_in[9];
    const float* Wo = (const float*)d_in[10];
    const float* bo = (const float*)d_in[11];

    __nv_bfloat16 *gQh, *gQl, *gKh, *gKl, *gVh, *gVl, *gAh, *gAl, *gWh, *gWl;
    cudaGetSymbolAddress((void**)&gQh, g_Qh);
    cudaGetSymbolAddress((void**)&gQl, g_Ql);
    cudaGetSymbolAddress((void**)&gKh, g_Kh);
    cudaGetSymbolAddress((void**)&gKl, g_Kl);
    cudaGetSymbolAddress((void**)&gVh, g_Vh);
    cudaGetSymbolAddress((void**)&gVl, g_Vl);
    cudaGetSymbolAddress((void**)&gAh, g_Ah);
    cudaGetSymbolAddress((void**)&gAl, g_Al);
    cudaGetSymbolAddress((void**)&gWh, g_Wh);
    cudaGetSymbolAddress((void**)&gWl, g_Wl);

    cudaFuncSetAttribute(tc_gemm, cudaFuncAttributeMaxDynamicSharedMemorySize, SMEM_SZ);
    cudaFuncSetAttribute(attn_mma, cudaFuncAttributeMaxDynamicSharedMemorySize, ATT_SMEM);

    const int n4a = MM * DD / 4;
    const int n4w = DD * DD / 4;
    dim3 cgridA((n4a + 255) / 256);
    dim3 cgridW((n4w + 255) / 256);
    dim3 ggrid(DD / 128, MM / 128);

    // Q projection (pre-scaled by 1/sqrt(dk) = 0.125)
    convert_hi_lo<<<cgridA, 256>>>(q, gAh, gAl, n4a);
    convert_hi_lo<<<cgridW, 256>>>(Wq, gWh, gWl, n4w);
    tc_gemm<<<ggrid, 256, SMEM_SZ>>>(gAh, gAl, gWh, gWl, bq, nullptr, gQh, gQl, 0.125f);
    // K projection
    convert_hi_lo<<<cgridA, 256>>>(k, gAh, gAl, n4a);
    convert_hi_lo<<<cgridW, 256>>>(Wk, gWh, gWl, n4w);
    tc_gemm<<<ggrid, 256, SMEM_SZ>>>(gAh, gAl, gWh, gWl, bk, nullptr, gKh, gKl, 1.f);
    // V projection
    convert_hi_lo<<<cgridA, 256>>>(v, gAh, gAl, n4a);
    convert_hi_lo<<<cgridW, 256>>>(Wv, gWh, gWl, n4w);
    tc_gemm<<<ggrid, 256, SMEM_SZ>>>(gAh, gAl, gWh, gWl, bv, nullptr, gVh, gVl, 1.f);

    // Attention -> ctx hi/lo directly into O-proj activation buffers
    attn_mma<<<dim3(16, HH, BB), 256, ATT_SMEM>>>(gQh, gQl, gKh, gKl, gVh, gVl, gAh, gAl);

    // Output projection (fp32 out)
    convert_hi_lo<<<cgridW, 256>>>(Wo, gWh, gWl, n4w);
    tc_gemm<<<ggrid, 256, SMEM_SZ>>>(gAh, gAl, gWh, gWl, bo, (float*)d_out, nullptr, nullptr, 1.f);
}

// round 7
// speedup vs baseline: 8.0369x; 1.5187x over previous
#include <cuda_runtime.h>
#include <cuda_fp16.h>
#include <cstdint>
#include <math.h>

// ---------------------------------------------------------------------------
// Problem constants: B=4, S=2048, D=1024, H=16, dk=64
// ---------------------------------------------------------------------------
#define BB 4
#define SS 2048
#define DD 1024
#define HH 16
#define DK 64
#define MM (BB * SS)          // 8192

// ---------------------------------------------------------------------------
// Scratch (__device__ globals; no cudaMalloc allowed)
// ---------------------------------------------------------------------------
__device__ __half g_Qh[(size_t)BB * HH * SS * DK];
__device__ __half g_Ql[(size_t)BB * HH * SS * DK];
__device__ __half g_Kh[(size_t)BB * HH * SS * DK];   // hi only
__device__ __half g_Vh[(size_t)BB * HH * SS * DK];   // hi only
__device__ __half g_Ah[(size_t)MM * DD];             // activation hi (also ctx hi)
__device__ __half g_Al[(size_t)MM * DD];             // activation lo (also ctx lo)
__device__ __half g_Wh[(size_t)DD * DD];             // W hi only [K][N]

// ---------------------------------------------------------------------------
// PTX helpers (arch-portable: ldmatrix / mma.sync / cp.async only)
// ---------------------------------------------------------------------------
__device__ __forceinline__ uint32_t smem_u32(const void* p) {
    uint32_t a;
    asm("{ .reg .u64 t; cvta.to.shared.u64 t, %1; cvt.u32.u64 %0, t; }" : "=r"(a) : "l"(p));
    return a;
}
__device__ __forceinline__ void cp16(uint32_t saddr, const void* g) {
    asm volatile("cp.async.cg.shared.global [%0], [%1], 16;" :: "r"(saddr), "l"(g) : "memory");
}
#define CP_COMMIT() asm volatile("cp.async.commit_group;" ::: "memory")
#define CP_WAIT(n)  asm volatile("cp.async.wait_group %0;" :: "n"(n) : "memory")

#define LDSM4(r, addr) asm volatile( \
    "ldmatrix.sync.aligned.m8n8.x4.shared.b16 {%0,%1,%2,%3}, [%4];" \
    : "=r"((r)[0]), "=r"((r)[1]), "=r"((r)[2]), "=r"((r)[3]) : "r"(addr))
#define LDSM4T(r, addr) asm volatile( \
    "ldmatrix.sync.aligned.m8n8.x4.trans.shared.b16 {%0,%1,%2,%3}, [%4];" \
    : "=r"((r)[0]), "=r"((r)[1]), "=r"((r)[2]), "=r"((r)[3]) : "r"(addr))

#define MMA16816(d, a, b0, b1) asm volatile( \
    "mma.sync.aligned.m16n8k16.row.col.f32.f16.f16.f32 " \
    "{%0,%1,%2,%3}, {%4,%5,%6,%7}, {%8,%9}, {%0,%1,%2,%3};" \
    : "+f"((d)[0]), "+f"((d)[1]), "+f"((d)[2]), "+f"((d)[3]) \
    : "r"((a)[0]), "r"((a)[1]), "r"((a)[2]), "r"((a)[3]), "r"(b0), "r"(b1))

// split two fp32 into packed fp16x2 (hi) and fp16x2 (lo residual)
__device__ __forceinline__ void split2(float x, float y, uint32_t& hp, uint32_t& lp) {
    __half hx = __float2half_rn(x), hy = __float2half_rn(y);
    __half2 hh = __halves2half2(hx, hy);
    __half2 ll = __halves2half2(__float2half_rn(x - __half2float(hx)),
                                __float2half_rn(y - __half2float(hy)));
    hp = *reinterpret_cast<uint32_t*>(&hh);
    lp = *reinterpret_cast<uint32_t*>(&ll);
}
__device__ __forceinline__ uint32_t pack_hi(float x, float y) {
    __half2 hh = __halves2half2(__float2half_rn(x), __float2half_rn(y));
    return *reinterpret_cast<uint32_t*>(&hh);
}

// ---------------------------------------------------------------------------
// Conversions
// ---------------------------------------------------------------------------
__global__ __launch_bounds__(256)
void convert_hi_lo(const float* __restrict__ x,
                   __half* __restrict__ hi, __half* __restrict__ lo, int n4)
{
    int i = blockIdx.x * blockDim.x + threadIdx.x;
    if (i >= n4) return;
    float4 v = ((const float4*)x)[i];
    uint32_t h0, l0, h1, l1;
    split2(v.x, v.y, h0, l0);
    split2(v.z, v.w, h1, l1);
    ((uint32_t*)hi)[2*i]   = h0;
    ((uint32_t*)hi)[2*i+1] = h1;
    ((uint32_t*)lo)[2*i]   = l0;
    ((uint32_t*)lo)[2*i+1] = l1;
}

__global__ __launch_bounds__(256)
void convert_hi(const float* __restrict__ x, __half* __restrict__ hi, int n4)
{
    int i = blockIdx.x * blockDim.x + threadIdx.x;
    if (i >= n4) return;
    float4 v = ((const float4*)x)[i];
    ((uint32_t*)hi)[2*i]   = pack_hi(v.x, v.y);
    ((uint32_t*)hi)[2*i+1] = pack_hi(v.z, v.w);
}

// ---------------------------------------------------------------------------
// HMMA GEMM: out = (Ah+Al)[M,K] @ Wh[K,N] + bias, fp16 2-pass.
// CTA 128x128, 8 warps (4M x 2N), KC=32, 2-stage cp.async.
// outF -> fp32 [M,N]. Else hi/lo (lo optional) in [B,H,S,dk], scaled.
// ---------------------------------------------------------------------------
#define KC 32
#define PA_B 80
#define PB_B 272
#define A_BYTES (128 * PA_B)    // 10240
#define B_BYTES (KC * PB_B)     // 8704
#define OFF_AH 0
#define OFF_AL A_BYTES
#define OFF_BH (2 * A_BYTES)
#define STAGE (2 * A_BYTES + B_BYTES)   // 29184
#define SMEM_SZ (2 * STAGE)             // 58368

__global__ __launch_bounds__(256)
void tc_gemm(const __half* __restrict__ Ah,
             const __half* __restrict__ Al,
             const __half* __restrict__ Wh,
             const float* __restrict__ bias,
             float* __restrict__ outF,
             __half* __restrict__ outH,
             __half* __restrict__ outL,
             float scale)
{
    extern __shared__ char smem[];
    const uint32_t sb = smem_u32(smem);
    const int tid = threadIdx.x;
    const int lane = tid & 31;
    const int warp = tid >> 5;
    const int warpM = warp >> 1;
    const int warpN = warp & 1;
    const int rowBase = blockIdx.y * 128;
    const int colBase = blockIdx.x * 128;

    float acc[2][8][4];
#pragma unroll
    for (int mi = 0; mi < 2; mi++)
#pragma unroll
        for (int ni = 0; ni < 8; ni++)
#pragma unroll
            for (int r = 0; r < 4; r++) acc[mi][ni][r] = 0.f;

    auto load_stage = [&](int ch, int s) {
        const int k0 = ch * KC;
        const uint32_t sbase = sb + s * STAGE;
#pragma unroll
        for (int i = 0; i < 6; i++) {
            int idx = tid + i * 256;       // 0..1535
            int t = idx >> 9;              // 0:Ah 1:Al 2:Wh
            int w = idx & 511;
            if (t < 2) {
                int r = w >> 2, c = w & 3;
                const __half* src = (t == 0 ? Ah : Al) + (size_t)(rowBase + r) * DD + k0 + c * 8;
                cp16(sbase + (t == 0 ? OFF_AH : OFF_AL) + r * PA_B + c * 16, src);
            } else {
                int r = w >> 4, c = w & 15;
                cp16(sbase + OFF_BH + r * PB_B + c * 16,
                     Wh + (size_t)(k0 + r) * DD + colBase + c * 8);
            }
        }
        CP_COMMIT();
    };

    load_stage(0, 0);

    const int NCH = DD / KC;
    for (int ch = 0; ch < NCH; ch++) {
        if (ch + 1 < NCH) {
            load_stage(ch + 1, (ch + 1) & 1);
            CP_WAIT(1);
        } else {
            CP_WAIT(0);
        }
        __syncthreads();

        const uint32_t stb = sb + (ch & 1) * STAGE;
#pragma unroll
        for (int kstep = 0; kstep < 2; kstep++) {
            uint32_t ah[2][4], al[2][4];
#pragma unroll
            for (int mi = 0; mi < 2; mi++) {
                uint32_t row = warpM * 32 + mi * 16 + (lane & 15);
                uint32_t ad = stb + OFF_AH + row * PA_B + kstep * 32 + (lane >> 4) * 16;
                LDSM4(ah[mi], ad);
                LDSM4(al[mi], ad + (OFF_AL - OFF_AH));
            }
            uint32_t bh[4][4];
#pragma unroll
            for (int ng = 0; ng < 4; ng++) {
                uint32_t krow = kstep * 16 + (lane & 15);
                uint32_t coln = warpN * 64 + ng * 16 + (lane >> 4) * 8;
                LDSM4T(bh[ng], stb + OFF_BH + krow * PB_B + coln * 2);
            }
#pragma unroll
            for (int mi = 0; mi < 2; mi++)
#pragma unroll
                for (int ni = 0; ni < 8; ni++) {
                    uint32_t b0 = bh[ni >> 1][(ni & 1) * 2];
                    uint32_t b1 = bh[ni >> 1][(ni & 1) * 2 + 1];
                    MMA16816(acc[mi][ni], ah[mi], b0, b1);
                    MMA16816(acc[mi][ni], al[mi], b0, b1);
                }
        }
        __syncthreads();
    }

    // ---- epilogue ----
    const int lg = lane >> 2;
    const int l4 = lane & 3;
#pragma unroll
    for (int mi = 0; mi < 2; mi++) {
#pragma unroll
        for (int ni = 0; ni < 8; ni++) {
            int r0 = rowBase + warpM * 32 + mi * 16 + lg;
            int r1 = r0 + 8;
            int col = colBase + warpN * 64 + ni * 8 + l4 * 2;
            float v00 = (acc[mi][ni][0] + bias[col]) * scale;
            float v01 = (acc[mi][ni][1] + bias[col + 1]) * scale;
            float v10 = (acc[mi][ni][2] + bias[col]) * scale;
            float v11 = (acc[mi][ni][3] + bias[col + 1]) * scale;
            if (outF) {
                *(float2*)(outF + (size_t)r0 * DD + col) = make_float2(v00, v01);
                *(float2*)(outF + (size_t)r1 * DD + col) = make_float2(v10, v11);
            } else {
                int h = col >> 6, dd = col & (DK - 1);
                int b0r = r0 >> 11, s0 = r0 & (SS - 1);
                int b1r = r1 >> 11, s1 = r1 & (SS - 1);
                size_t o0 = (((size_t)(b0r * HH + h)) * SS + s0) * DK + dd;
                size_t o1 = (((size_t)(b1r * HH + h)) * SS + s1) * DK + dd;
                if (outL) {
                    uint32_t hp, lp;
                    split2(v00, v01, hp, lp);
                    *(uint32_t*)(outH + o0) = hp;
                    *(uint32_t*)(outL + o0) = lp;
                    split2(v10, v11, hp, lp);
                    *(uint32_t*)(outH + o1) = hp;
                    *(uint32_t*)(outL + o1) = lp;
                } else {
                    *(uint32_t*)(outH + o0) = pack_hi(v00, v01);
                    *(uint32_t*)(outH + o1) = pack_hi(v10, v11);
                }
            }
        }
    }
}

// ---------------------------------------------------------------------------
// HMMA causal flash attention, fp16 2-pass.
// S = (Qh+Ql) Kh^T;  O += (Ph+Pl) Vh.
// CTA: 128 q-rows of one (b,h); 8 warps x 16 rows; 64-key tiles, 2-stage.
// Writes ctx hi/lo fp16 in [B,S,D] layout (O-proj activation format).
// ---------------------------------------------------------------------------
#define APITCH 144
#define ASQH 0
#define ASQL 18432
#define AKV0 36864
#define AKSTAGE 18432                    // Kh(9216) Vh(9216)
#define ATT_SMEM (AKV0 + 2 * AKSTAGE)    // 73728

__global__ __launch_bounds__(256)
void attn_mma(const __half* __restrict__ Qh, const __half* __restrict__ Ql,
              const __half* __restrict__ Kh, const __half* __restrict__ Vh,
              __half* __restrict__ Ch, __half* __restrict__ Cl)
{
    extern __shared__ char smem[];
    const uint32_t sb = smem_u32(smem);
    const int tid = threadIdx.x;
    const int lane = tid & 31;
    const int warp = tid >> 5;
    const int lg = lane >> 2;
    const int l4 = lane & 3;

    const int qt = 15 - blockIdx.x;   // heavy tiles first
    const int h  = blockIdx.y;
    const int b  = blockIdx.z;
    const size_t bhoff = (size_t)(b * HH + h) * SS * DK;

    // --- stage Q (hi+lo) ---
#pragma unroll
    for (int i = 0; i < 8; i++) {
        int idx = tid + i * 256;
        int mat = idx >> 10;           // 0:Qh 1:Ql
        int w = idx & 1023;
        int r = w >> 3, c = w & 7;
        const __half* src = (mat ? Ql : Qh) + bhoff + (size_t)(qt * 128 + r) * DK + c * 8;
        cp16(sb + mat * 18432 + r * APITCH + c * 16, src);
    }
    CP_COMMIT();

    auto kv_load = [&](int jt, int st) {
        uint32_t base = sb + AKV0 + st * AKSTAGE;
        size_t koff = bhoff + (size_t)jt * 64 * DK;
#pragma unroll
        for (int i = 0; i < 4; i++) {
            int idx = tid + i * 256;
            int mat = idx >> 9;        // 0:Kh 1:Vh
            int w = idx & 511;
            int r = w >> 3, c = w & 7;
            const __half* mp = mat ? Vh : Kh;
            cp16(base + mat * 9216 + r * APITCH + c * 16, mp + koff + (size_t)r * DK + c * 8);
        }
        CP_COMMIT();
    };

    kv_load(0, 0);
    CP_WAIT(1);                  // Q group done
    __syncthreads();

    // --- Q fragments in registers ---
    uint32_t qah[4][4], qal[4][4];
#pragma unroll
    for (int kk = 0; kk < 4; kk++) {
        uint32_t ad = sb + ASQH + (warp * 16 + (lane & 15)) * APITCH + kk * 32 + (lane >> 4) * 16;
        LDSM4(qah[kk], ad);
        LDSM4(qal[kk], ad + (ASQL - ASQH));
    }

    float o[8][4];
#pragma unroll
    for (int c = 0; c < 8; c++)
#pragma unroll
        for (int r = 0; r < 4; r++) o[c][r] = 0.f;
    float m0 = -1e30f, m1 = -1e30f, l0 = 0.f, l1 = 0.f;

    const int row0 = qt * 128 + warp * 16 + lg;
    const int ntiles = 2 * qt + 2;

    for (int jt = 0; jt < ntiles; jt++) {
        if (jt + 1 < ntiles) { kv_load(jt + 1, (jt + 1) & 1); CP_WAIT(1); }
        else                 { CP_WAIT(0); }
        __syncthreads();

        const uint32_t kvb = sb + AKV0 + (jt & 1) * AKSTAGE;

        // ---- scores: S = (Qh+Ql) Kh ----
        float s[8][4];
#pragma unroll
        for (int c = 0; c < 8; c++)
#pragma unroll
            for (int r = 0; r < 4; r++) s[c][r] = 0.f;

#pragma unroll
        for (int ng = 0; ng < 4; ng++) {
#pragma unroll
            for (int kk = 0; kk < 4; kk++) {
                uint32_t kh[4];
                LDSM4(kh, kvb + (ng * 16 + (lane & 15)) * APITCH + kk * 32 + (lane >> 4) * 16);
                MMA16816(s[2 * ng],     qah[kk], kh[0], kh[2]);
                MMA16816(s[2 * ng],     qal[kk], kh[0], kh[2]);
                MMA16816(s[2 * ng + 1], qah[kk], kh[1], kh[3]);
                MMA16816(s[2 * ng + 1], qal[kk], kh[1], kh[3]);
            }
        }

        // ---- causal mask vs the warp's MINIMUM row ----
        if (jt * 64 + 63 > qt * 128 + warp * 16) {
#pragma unroll
            for (int c = 0; c < 8; c++) {
                int col = jt * 64 + c * 8 + 2 * l4;
                if (col > row0)         s[c][0] = -1e30f;
                if (col + 1 > row0)     s[c][1] = -1e30f;
                if (col > row0 + 8)     s[c][2] = -1e30f;
                if (col + 1 > row0 + 8) s[c][3] = -1e30f;
            }
        }

        // ---- online softmax ----
        float mx0 = -1e30f, mx1 = -1e30f;
#pragma unroll
        for (int c = 0; c < 8; c++) {
            mx0 = fmaxf(mx0, fmaxf(s[c][0], s[c][1]));
            mx1 = fmaxf(mx1, fmaxf(s[c][2], s[c][3]));
        }
        mx0 = fmaxf(mx0, __shfl_xor_sync(0xFFFFFFFFu, mx0, 1));
        mx0 = fmaxf(mx0, __shfl_xor_sync(0xFFFFFFFFu, mx0, 2));
        mx1 = fmaxf(mx1, __shfl_xor_sync(0xFFFFFFFFu, mx1, 1));
        mx1 = fmaxf(mx1, __shfl_xor_sync(0xFFFFFFFFu, mx1, 2));
        float mn0 = fmaxf(m0, mx0), mn1 = fmaxf(m1, mx1);
        float sc0 = __expf(m0 - mn0), sc1 = __expf(m1 - mn1);
        m0 = mn0; m1 = mn1;
        l0 *= sc0; l1 *= sc1;
#pragma unroll
        for (int c = 0; c < 8; c++) {
            o[c][0] *= sc0; o[c][1] *= sc0;
            o[c][2] *= sc1; o[c][3] *= sc1;
        }
#pragma unroll
        for (int c = 0; c < 8; c++) {
            s[c][0] = __expf(s[c][0] - mn0);
            s[c][1] = __expf(s[c][1] - mn0);
            s[c][2] = __expf(s[c][2] - mn1);
            s[c][3] = __expf(s[c][3] - mn1);
            l0 += s[c][0] + s[c][1];
            l1 += s[c][2] + s[c][3];
        }

        // ---- P fragments (hi/lo), FA2 register reuse ----
        uint32_t pah[4][4], pal[4][4];
#pragma unroll
        for (int kk = 0; kk < 4; kk++) {
            split2(s[2 * kk][0],     s[2 * kk][1],     pah[kk][0], pal[kk][0]);
            split2(s[2 * kk][2],     s[2 * kk][3],     pah[kk][1], pal[kk][1]);
            split2(s[2 * kk + 1][0], s[2 * kk + 1][1], pah[kk][2], pal[kk][2]);
            split2(s[2 * kk + 1][2], s[2 * kk + 1][3], pah[kk][3], pal[kk][3]);
        }

        // ---- O += (Ph+Pl) Vh ----
#pragma unroll
        for (int dg = 0; dg < 4; dg++) {
#pragma unroll
            for (int kk = 0; kk < 4; kk++) {
                uint32_t vh[4];
                LDSM4T(vh, kvb + 9216 + (kk * 16 + (lane & 15)) * APITCH
                           + dg * 32 + (lane >> 4) * 16);
                MMA16816(o[2 * dg],     pah[kk], vh[0], vh[1]);
                MMA16816(o[2 * dg],     pal[kk], vh[0], vh[1]);
                MMA16816(o[2 * dg + 1], pah[kk], vh[2], vh[3]);
                MMA16816(o[2 * dg + 1], pal[kk], vh[2], vh[3]);
            }
        }
        __syncthreads();
    }

    // ---- finalize: normalize and write ctx hi/lo in [B,S,D] ----
    l0 += __shfl_xor_sync(0xFFFFFFFFu, l0, 1);
    l0 += __shfl_xor_sync(0xFFFFFFFFu, l0, 2);
    l1 += __shfl_xor_sync(0xFFFFFFFFu, l1, 1);
    l1 += __shfl_xor_sync(0xFFFFFFFFu, l1, 2);
    const float inv0 = 1.f / l0, inv1 = 1.f / l1;

    const size_t r0 = (size_t)b * SS + row0;
    const size_t r1 = r0 + 8;
#pragma unroll
    for (int c = 0; c < 8; c++) {
        int col = h * DK + c * 8 + 2 * l4;
        uint32_t hp, lp;
        split2(o[c][0] * inv0, o[c][1] * inv0, hp, lp);
        *(uint32_t*)(Ch + r0 * DD + col) = hp;
        *(uint32_t*)(Cl + r0 * DD + col) = lp;
        split2(o[c][2] * inv1, o[c][3] * inv1, hp, lp);
        *(uint32_t*)(Ch + r1 * DD + col) = hp;
        *(uint32_t*)(Cl + r1 * DD + col) = lp;
    }
}

// ---------------------------------------------------------------------------
// Launch
// ---------------------------------------------------------------------------
extern "C" void kernel_launch(void* const* d_in, const int* in_sizes, int n_in,
                              void* d_out, int out_size)
{
    const float* q  = (const float*)d_in[0];
    const float* k  = (const float*)d_in[1];
    const float* v  = (const float*)d_in[2];
    const float* Wq = (const float*)d_in[4];
    const float* bq = (const float*)d_in[5];
    const float* Wk = (const float*)d_in[6];
    const float* bk = (const float*)d_in[7];
    const float* Wv = (const float*)d_in[8];
    const float* bv = (const float*)d_in[9];
    const float* Wo = (const float*)d_in[10];
    const float* bo = (const float*)d_in[11];

    __half *gQh, *gQl, *gKh, *gVh, *gAh, *gAl, *gWh;
    cudaGetSymbolAddress((void**)&gQh, g_Qh);
    cudaGetSymbolAddress((void**)&gQl, g_Ql);
    cudaGetSymbolAddress((void**)&gKh, g_Kh);
    cudaGetSymbolAddress((void**)&gVh, g_Vh);
    cudaGetSymbolAddress((void**)&gAh, g_Ah);
    cudaGetSymbolAddress((void**)&gAl, g_Al);
    cudaGetSymbolAddress((void**)&gWh, g_Wh);

    cudaFuncSetAttribute(tc_gemm, cudaFuncAttributeMaxDynamicSharedMemorySize, SMEM_SZ);
    cudaFuncSetAttribute(attn_mma, cudaFuncAttributeMaxDynamicSharedMemorySize, ATT_SMEM);

    const int n4a = MM * DD / 4;
    const int n4w = DD * DD / 4;
    dim3 cgridA((n4a + 255) / 256);
    dim3 cgridW((n4w + 255) / 256);
    dim3 ggrid(DD / 128, MM / 128);

    // Q projection (pre-scaled by 1/sqrt(dk) = 0.125), split output
    convert_hi_lo<<<cgridA, 256>>>(q, gAh, gAl, n4a);
    convert_hi<<<cgridW, 256>>>(Wq, gWh, n4w);
    tc_gemm<<<ggrid, 256, SMEM_SZ>>>(gAh, gAl, gWh, bq, nullptr, gQh, gQl, 0.125f);
    // K projection, hi-only output
    convert_hi_lo<<<cgridA, 256>>>(k, gAh, gAl, n4a);
    convert_hi<<<cgridW, 256>>>(Wk, gWh, n4w);
    tc_gemm<<<ggrid, 256, SMEM_SZ>>>(gAh, gAl, gWh, bk, nullptr, gKh, nullptr, 1.f);
    // V projection, hi-only output
    convert_hi_lo<<<cgridA, 256>>>(v, gAh, gAl, n4a);
    convert_hi<<<cgridW, 256>>>(Wv, gWh, n4w);
    tc_gemm<<<ggrid, 256, SMEM_SZ>>>(gAh, gAl, gWh, bv, nullptr, gVh, nullptr, 1.f);

    // Attention -> ctx hi/lo directly into O-proj activation buffers
    attn_mma<<<dim3(16, HH, BB), 256, ATT_SMEM>>>(gQh, gQl, gKh, gVh, gAh, gAl);

    // Output projection (fp32 out)
    convert_hi<<<cgridW, 256>>>(Wo, gWh, n4w);
    tc_gemm<<<ggrid, 256, SMEM_SZ>>>(gAh, gAl, gWh, bo, (float*)d_out, nullptr, nullptr, 1.f);
}

// round 8
// speedup vs baseline: 8.5228x; 1.0605x over previous
#include <cuda_runtime.h>
#include <cuda_fp16.h>
#include <cstdint>
#include <math.h>

// ---------------------------------------------------------------------------
// Problem constants: B=4, S=2048, D=1024, H=16, dk=64
// ---------------------------------------------------------------------------
#define BB 4
#define SS 2048
#define DD 1024
#define HH 16
#define DK 64
#define MM (BB * SS)          // 8192

// ---------------------------------------------------------------------------
// Scratch (__device__ globals; no cudaMalloc allowed)
// ---------------------------------------------------------------------------
__device__ __half g_A[3][2][(size_t)MM * DD];   // [q/k/v][hi/lo] activations
__device__ __half g_W[4][(size_t)DD * DD];      // [q/k/v/o] weight hi
__device__ __half g_Qh[(size_t)BB * HH * SS * DK];
__device__ __half g_Ql[(size_t)BB * HH * SS * DK];
__device__ __half g_Kh[(size_t)BB * HH * SS * DK];
__device__ __half g_Vh[(size_t)BB * HH * SS * DK];
__device__ __half g_Ch[(size_t)MM * DD];        // ctx hi (O-proj activation)
__device__ __half g_Cl[(size_t)MM * DD];        // ctx lo

// ---------------------------------------------------------------------------
// PTX helpers (arch-portable: ldmatrix / mma.sync / cp.async only)
// ---------------------------------------------------------------------------
__device__ __forceinline__ uint32_t smem_u32(const void* p) {
    uint32_t a;
    asm("{ .reg .u64 t; cvta.to.shared.u64 t, %1; cvt.u32.u64 %0, t; }" : "=r"(a) : "l"(p));
    return a;
}
__device__ __forceinline__ void cp16(uint32_t saddr, const void* g) {
    asm volatile("cp.async.cg.shared.global [%0], [%1], 16;" :: "r"(saddr), "l"(g) : "memory");
}
#define CP_COMMIT() asm volatile("cp.async.commit_group;" ::: "memory")
#define CP_WAIT(n)  asm volatile("cp.async.wait_group %0;" :: "n"(n) : "memory")

#define LDSM4(r, addr) asm volatile( \
    "ldmatrix.sync.aligned.m8n8.x4.shared.b16 {%0,%1,%2,%3}, [%4];" \
    : "=r"((r)[0]), "=r"((r)[1]), "=r"((r)[2]), "=r"((r)[3]) : "r"(addr))
#define LDSM4T(r, addr) asm volatile( \
    "ldmatrix.sync.aligned.m8n8.x4.trans.shared.b16 {%0,%1,%2,%3}, [%4];" \
    : "=r"((r)[0]), "=r"((r)[1]), "=r"((r)[2]), "=r"((r)[3]) : "r"(addr))

#define MMA16816(d, a, b0, b1) asm volatile( \
    "mma.sync.aligned.m16n8k16.row.col.f32.f16.f16.f32 " \
    "{%0,%1,%2,%3}, {%4,%5,%6,%7}, {%8,%9}, {%0,%1,%2,%3};" \
    : "+f"((d)[0]), "+f"((d)[1]), "+f"((d)[2]), "+f"((d)[3]) \
    : "r"((a)[0]), "r"((a)[1]), "r"((a)[2]), "r"((a)[3]), "r"(b0), "r"(b1))

// split two fp32 into packed fp16x2 (hi) and fp16x2 (lo residual)
__device__ __forceinline__ void split2(float x, float y, uint32_t& hp, uint32_t& lp) {
    __half hx = __float2half_rn(x), hy = __float2half_rn(y);
    __half2 hh = __halves2half2(hx, hy);
    __half2 ll = __halves2half2(__float2half_rn(x - __half2float(hx)),
                                __float2half_rn(y - __half2float(hy)));
    hp = *reinterpret_cast<uint32_t*>(&hh);
    lp = *reinterpret_cast<uint32_t*>(&ll);
}
__device__ __forceinline__ uint32_t pack_hi(float x, float y) {
    __half2 hh = __halves2half2(__float2half_rn(x), __float2half_rn(y));
    return *reinterpret_cast<uint32_t*>(&hh);
}

// ---------------------------------------------------------------------------
// Batched conversions
// ---------------------------------------------------------------------------
__global__ __launch_bounds__(256)
void convert_act(const float* __restrict__ x0, const float* __restrict__ x1,
                 const float* __restrict__ x2, int n4)
{
    int i = blockIdx.x * blockDim.x + threadIdx.x;
    if (i >= n4) return;
    int t = blockIdx.y;
    const float* x = (t == 0) ? x0 : (t == 1) ? x1 : x2;
    __half* hi = g_A[t][0];
    __half* lo = g_A[t][1];
    float4 v = ((const float4*)x)[i];
    uint32_t h0, l0, h1, l1;
    split2(v.x, v.y, h0, l0);
    split2(v.z, v.w, h1, l1);
    ((uint32_t*)hi)[2*i]   = h0;
    ((uint32_t*)hi)[2*i+1] = h1;
    ((uint32_t*)lo)[2*i]   = l0;
    ((uint32_t*)lo)[2*i+1] = l1;
}

__global__ __launch_bounds__(256)
void convert_w(const float* __restrict__ w0, const float* __restrict__ w1,
               const float* __restrict__ w2, const float* __restrict__ w3, int n4)
{
    int i = blockIdx.x * blockDim.x + threadIdx.x;
    if (i >= n4) return;
    int t = blockIdx.y;
    const float* x = (t == 0) ? w0 : (t == 1) ? w1 : (t == 2) ? w2 : w3;
    __half* hi = g_W[t];
    float4 v = ((const float4*)x)[i];
    ((uint32_t*)hi)[2*i]   = pack_hi(v.x, v.y);
    ((uint32_t*)hi)[2*i+1] = pack_hi(v.z, v.w);
}

// ---------------------------------------------------------------------------
// HMMA GEMM body: out = (Ah+Al)[M,K] @ Wh[K,N] + bias, fp16 2-pass.
// CTA 128x128, 8 warps (4M x 2N), KC=32, 3-stage cp.async pipeline.
// ---------------------------------------------------------------------------
#define KC 32
#define PA_B 80
#define PB_B 272
#define A_BYTES (128 * PA_B)    // 10240
#define B_BYTES (KC * PB_B)     // 8704
#define OFF_AH 0
#define OFF_AL A_BYTES
#define OFF_BH (2 * A_BYTES)
#define STAGE (2 * A_BYTES + B_BYTES)   // 29184
#define NSTAGES 3
#define SMEM_SZ (NSTAGES * STAGE)       // 87552

__device__ __forceinline__
void gemm_body(const __half* __restrict__ Ah,
               const __half* __restrict__ Al,
               const __half* __restrict__ Wh,
               const float* __restrict__ bias,
               float* __restrict__ outF,
               __half* __restrict__ outH,
               __half* __restrict__ outL,
               float scale, char* smem)
{
    const uint32_t sb = smem_u32(smem);
    const int tid = threadIdx.x;
    const int lane = tid & 31;
    const int warp = tid >> 5;
    const int warpM = warp >> 1;
    const int warpN = warp & 1;
    const int rowBase = blockIdx.y * 128;
    const int colBase = blockIdx.x * 128;

    float acc[2][8][4];
#pragma unroll
    for (int mi = 0; mi < 2; mi++)
#pragma unroll
        for (int ni = 0; ni < 8; ni++)
#pragma unroll
            for (int r = 0; r < 4; r++) acc[mi][ni][r] = 0.f;

    auto load_stage = [&](int ch, int s) {
        const int k0 = ch * KC;
        const uint32_t sbase = sb + s * STAGE;
#pragma unroll
        for (int i = 0; i < 6; i++) {
            int idx = tid + i * 256;       // 0..1535
            int t = idx >> 9;              // 0:Ah 1:Al 2:Wh
            int w = idx & 511;
            if (t < 2) {
                int r = w >> 2, c = w & 3;
                const __half* src = (t == 0 ? Ah : Al) + (size_t)(rowBase + r) * DD + k0 + c * 8;
                cp16(sbase + (t == 0 ? OFF_AH : OFF_AL) + r * PA_B + c * 16, src);
            } else {
                int r = w >> 4, c = w & 15;
                cp16(sbase + OFF_BH + r * PB_B + c * 16,
                     Wh + (size_t)(k0 + r) * DD + colBase + c * 8);
            }
        }
        CP_COMMIT();
    };

    const int NCH = DD / KC;   // 32
    load_stage(0, 0);
    load_stage(1, 1);

    for (int ch = 0; ch < NCH; ch++) {
        CP_WAIT(1);                        // stage ch complete
        __syncthreads();                   // also: all warps done reading slot (ch+2)%3
        if (ch + 2 < NCH) load_stage(ch + 2, (ch + 2) % NSTAGES);

        const uint32_t stb = sb + (ch % NSTAGES) * STAGE;
#pragma unroll
        for (int kstep = 0; kstep < 2; kstep++) {
            uint32_t ah[2][4], al[2][4];
#pragma unroll
            for (int mi = 0; mi < 2; mi++) {
                uint32_t row = warpM * 32 + mi * 16 + (lane & 15);
                uint32_t ad = stb + OFF_AH + row * PA_B + kstep * 32 + (lane >> 4) * 16;
                LDSM4(ah[mi], ad);
                LDSM4(al[mi], ad + (OFF_AL - OFF_AH));
            }
            uint32_t bh[4][4];
#pragma unroll
            for (int ng = 0; ng < 4; ng++) {
                uint32_t krow = kstep * 16 + (lane & 15);
                uint32_t coln = warpN * 64 + ng * 16 + (lane >> 4) * 8;
                LDSM4T(bh[ng], stb + OFF_BH + krow * PB_B + coln * 2);
            }
#pragma unroll
            for (int mi = 0; mi < 2; mi++)
#pragma unroll
                for (int ni = 0; ni < 8; ni++) {
                    uint32_t b0 = bh[ni >> 1][(ni & 1) * 2];
                    uint32_t b1 = bh[ni >> 1][(ni & 1) * 2 + 1];
                    MMA16816(acc[mi][ni], ah[mi], b0, b1);
                    MMA16816(acc[mi][ni], al[mi], b0, b1);
                }
        }
    }

    // ---- epilogue ----
    const int lg = lane >> 2;
    const int l4 = lane & 3;
#pragma unroll
    for (int mi = 0; mi < 2; mi++) {
#pragma unroll
        for (int ni = 0; ni < 8; ni++) {
            int r0 = rowBase + warpM * 32 + mi * 16 + lg;
            int r1 = r0 + 8;
            int col = colBase + warpN * 64 + ni * 8 + l4 * 2;
            float v00 = (acc[mi][ni][0] + bias[col]) * scale;
            float v01 = (acc[mi][ni][1] + bias[col + 1]) * scale;
            float v10 = (acc[mi][ni][2] + bias[col]) * scale;
            float v11 = (acc[mi][ni][3] + bias[col + 1]) * scale;
            if (outF) {
                *(float2*)(outF + (size_t)r0 * DD + col) = make_float2(v00, v01);
                *(float2*)(outF + (size_t)r1 * DD + col) = make_float2(v10, v11);
            } else {
                int h = col >> 6, dd = col & (DK - 1);
                int b0r = r0 >> 11, s0 = r0 & (SS - 1);
                int b1r = r1 >> 11, s1 = r1 & (SS - 1);
                size_t o0 = (((size_t)(b0r * HH + h)) * SS + s0) * DK + dd;
                size_t o1 = (((size_t)(b1r * HH + h)) * SS + s1) * DK + dd;
                if (outL) {
                    uint32_t hp, lp;
                    split2(v00, v01, hp, lp);
                    *(uint32_t*)(outH + o0) = hp;
                    *(uint32_t*)(outL + o0) = lp;
                    split2(v10, v11, hp, lp);
                    *(uint32_t*)(outH + o1) = hp;
                    *(uint32_t*)(outL + o1) = lp;
                } else {
                    *(uint32_t*)(outH + o0) = pack_hi(v00, v01);
                    *(uint32_t*)(outH + o1) = pack_hi(v10, v11);
                }
            }
        }
    }
}

// Fused QKV projections: blockIdx.z selects q/k/v.
__global__ __launch_bounds__(256, 2)
void qkv_gemm(const float* __restrict__ bq, const float* __restrict__ bk,
              const float* __restrict__ bv)
{
    extern __shared__ char smem[];
    const int z = blockIdx.z;
    if (z == 0)
        gemm_body(g_A[0][0], g_A[0][1], g_W[0], bq, nullptr, g_Qh, g_Ql, 0.125f, smem);
    else if (z == 1)
        gemm_body(g_A[1][0], g_A[1][1], g_W[1], bk, nullptr, g_Kh, nullptr, 1.f, smem);
    else
        gemm_body(g_A[2][0], g_A[2][1], g_W[2], bv, nullptr, g_Vh, nullptr, 1.f, smem);
}

// Output projection: ctx hi/lo @ Wo -> fp32 out.
__global__ __launch_bounds__(256, 2)
void o_gemm(const float* __restrict__ bo, float* __restrict__ out)
{
    extern __shared__ char smem[];
    gemm_body(g_Ch, g_Cl, g_W[3], bo, out, nullptr, nullptr, 1.f, smem);
}

// ---------------------------------------------------------------------------
// HMMA causal flash attention, fp16 2-pass (unchanged from passing round 7).
// ---------------------------------------------------------------------------
#define APITCH 144
#define ASQH 0
#define ASQL 18432
#define AKV0 36864
#define AKSTAGE 18432                    // Kh(9216) Vh(9216)
#define ATT_SMEM (AKV0 + 2 * AKSTAGE)    // 73728

__global__ __launch_bounds__(256)
void attn_mma(const __half* __restrict__ Qh, const __half* __restrict__ Ql,
              const __half* __restrict__ Kh, const __half* __restrict__ Vh,
              __half* __restrict__ Ch, __half* __restrict__ Cl)
{
    extern __shared__ char smem[];
    const uint32_t sb = smem_u32(smem);
    const int tid = threadIdx.x;
    const int lane = tid & 31;
    const int warp = tid >> 5;
    const int lg = lane >> 2;
    const int l4 = lane & 3;

    const int qt = 15 - blockIdx.x;   // heavy tiles first
    const int h  = blockIdx.y;
    const int b  = blockIdx.z;
    const size_t bhoff = (size_t)(b * HH + h) * SS * DK;

    // --- stage Q (hi+lo) ---
#pragma unroll
    for (int i = 0; i < 8; i++) {
        int idx = tid + i * 256;
        int mat = idx >> 10;           // 0:Qh 1:Ql
        int w = idx & 1023;
        int r = w >> 3, c = w & 7;
        const __half* src = (mat ? Ql : Qh) + bhoff + (size_t)(qt * 128 + r) * DK + c * 8;
        cp16(sb + mat * 18432 + r * APITCH + c * 16, src);
    }
    CP_COMMIT();

    auto kv_load = [&](int jt, int st) {
        uint32_t base = sb + AKV0 + st * AKSTAGE;
        size_t koff = bhoff + (size_t)jt * 64 * DK;
#pragma unroll
        for (int i = 0; i < 4; i++) {
            int idx = tid + i * 256;
            int mat = idx >> 9;        // 0:Kh 1:Vh
            int w = idx & 511;
            int r = w >> 3, c = w & 7;
            const __half* mp = mat ? Vh : Kh;
            cp16(base + mat * 9216 + r * APITCH + c * 16, mp + koff + (size_t)r * DK + c * 8);
        }
        CP_COMMIT();
    };

    kv_load(0, 0);
    CP_WAIT(1);                  // Q group done
    __syncthreads();

    // --- Q fragments in registers ---
    uint32_t qah[4][4], qal[4][4];
#pragma unroll
    for (int kk = 0; kk < 4; kk++) {
        uint32_t ad = sb + ASQH + (warp * 16 + (lane & 15)) * APITCH + kk * 32 + (lane >> 4) * 16;
        LDSM4(qah[kk], ad);
        LDSM4(qal[kk], ad + (ASQL - ASQH));
    }

    float o[8][4];
#pragma unroll
    for (int c = 0; c < 8; c++)
#pragma unroll
        for (int r = 0; r < 4; r++) o[c][r] = 0.f;
    float m0 = -1e30f, m1 = -1e30f, l0 = 0.f, l1 = 0.f;

    const int row0 = qt * 128 + warp * 16 + lg;
    const int ntiles = 2 * qt + 2;

    for (int jt = 0; jt < ntiles; jt++) {
        if (jt + 1 < ntiles) { kv_load(jt + 1, (jt + 1) & 1); CP_WAIT(1); }
        else                 { CP_WAIT(0); }
        __syncthreads();

        const uint32_t kvb = sb + AKV0 + (jt & 1) * AKSTAGE;

        // ---- scores: S = (Qh+Ql) Kh ----
        float s[8][4];
#pragma unroll
        for (int c = 0; c < 8; c++)
#pragma unroll
            for (int r = 0; r < 4; r++) s[c][r] = 0.f;

#pragma unroll
        for (int ng = 0; ng < 4; ng++) {
#pragma unroll
            for (int kk = 0; kk < 4; kk++) {
                uint32_t kh[4];
                LDSM4(kh, kvb + (ng * 16 + (lane & 15)) * APITCH + kk * 32 + (lane >> 4) * 16);
                MMA16816(s[2 * ng],     qah[kk], kh[0], kh[2]);
                MMA16816(s[2 * ng],     qal[kk], kh[0], kh[2]);
                MMA16816(s[2 * ng + 1], qah[kk], kh[1], kh[3]);
                MMA16816(s[2 * ng + 1], qal[kk], kh[1], kh[3]);
            }
        }

        // ---- causal mask vs the warp's MINIMUM row ----
        if (jt * 64 + 63 > qt * 128 + warp * 16) {
#pragma unroll
            for (int c = 0; c < 8; c++) {
                int col = jt * 64 + c * 8 + 2 * l4;
                if (col > row0)         s[c][0] = -1e30f;
                if (col + 1 > row0)     s[c][1] = -1e30f;
                if (col > row0 + 8)     s[c][2] = -1e30f;
                if (col + 1 > row0 + 8) s[c][3] = -1e30f;
            }
        }

        // ---- online softmax ----
        float mx0 = -1e30f, mx1 = -1e30f;
#pragma unroll
        for (int c = 0; c < 8; c++) {
            mx0 = fmaxf(mx0, fmaxf(s[c][0], s[c][1]));
            mx1 = fmaxf(mx1, fmaxf(s[c][2], s[c][3]));
        }
        mx0 = fmaxf(mx0, __shfl_xor_sync(0xFFFFFFFFu, mx0, 1));
        mx0 = fmaxf(mx0, __shfl_xor_sync(0xFFFFFFFFu, mx0, 2));
        mx1 = fmaxf(mx1, __shfl_xor_sync(0xFFFFFFFFu, mx1, 1));
        mx1 = fmaxf(mx1, __shfl_xor_sync(0xFFFFFFFFu, mx1, 2));
        float mn0 = fmaxf(m0, mx0), mn1 = fmaxf(m1, mx1);
        float sc0 = __expf(m0 - mn0), sc1 = __expf(m1 - mn1);
        m0 = mn0; m1 = mn1;
        l0 *= sc0; l1 *= sc1;
#pragma unroll
        for (int c = 0; c < 8; c++) {
            o[c][0] *= sc0; o[c][1] *= sc0;
            o[c][2] *= sc1; o[c][3] *= sc1;
        }
#pragma unroll
        for (int c = 0; c < 8; c++) {
            s[c][0] = __expf(s[c][0] - mn0);
            s[c][1] = __expf(s[c][1] - mn0);
            s[c][2] = __expf(s[c][2] - mn1);
            s[c][3] = __expf(s[c][3] - mn1);
            l0 += s[c][0] + s[c][1];
            l1 += s[c][2] + s[c][3];
        }

        // ---- P fragments (hi/lo), FA2 register reuse ----
        uint32_t pah[4][4], pal[4][4];
#pragma unroll
        for (int kk = 0; kk < 4; kk++) {
            split2(s[2 * kk][0],     s[2 * kk][1],     pah[kk][0], pal[kk][0]);
            split2(s[2 * kk][2],     s[2 * kk][3],     pah[kk][1], pal[kk][1]);
            split2(s[2 * kk + 1][0], s[2 * kk + 1][1], pah[kk][2], pal[kk][2]);
            split2(s[2 * kk + 1][2], s[2 * kk + 1][3], pah[kk][3], pal[kk][3]);
        }

        // ---- O += (Ph+Pl) Vh ----
#pragma unroll
        for (int dg = 0; dg < 4; dg++) {
#pragma unroll
            for (int kk = 0; kk < 4; kk++) {
                uint32_t vh[4];
                LDSM4T(vh, kvb + 9216 + (kk * 16 + (lane & 15)) * APITCH
                           + dg * 32 + (lane >> 4) * 16);
                MMA16816(o[2 * dg],     pah[kk], vh[0], vh[1]);
                MMA16816(o[2 * dg],     pal[kk], vh[0], vh[1]);
                MMA16816(o[2 * dg + 1], pah[kk], vh[2], vh[3]);
                MMA16816(o[2 * dg + 1], pal[kk], vh[2], vh[3]);
            }
        }
        __syncthreads();
    }

    // ---- finalize: normalize and write ctx hi/lo in [B,S,D] ----
    l0 += __shfl_xor_sync(0xFFFFFFFFu, l0, 1);
    l0 += __shfl_xor_sync(0xFFFFFFFFu, l0, 2);
    l1 += __shfl_xor_sync(0xFFFFFFFFu, l1, 1);
    l1 += __shfl_xor_sync(0xFFFFFFFFu, l1, 2);
    const float inv0 = 1.f / l0, inv1 = 1.f / l1;

    const size_t r0 = (size_t)b * SS + row0;
    const size_t r1 = r0 + 8;
#pragma unroll
    for (int c = 0; c < 8; c++) {
        int col = h * DK + c * 8 + 2 * l4;
        uint32_t hp, lp;
        split2(o[c][0] * inv0, o[c][1] * inv0, hp, lp);
        *(uint32_t*)(Ch + r0 * DD + col) = hp;
        *(uint32_t*)(Cl + r0 * DD + col) = lp;
        split2(o[c][2] * inv1, o[c][3] * inv1, hp, lp);
        *(uint32_t*)(Ch + r1 * DD + col) = hp;
        *(uint32_t*)(Cl + r1 * DD + col) = lp;
    }
}

// ---------------------------------------------------------------------------
// Launch
// ---------------------------------------------------------------------------
extern "C" void kernel_launch(void* const* d_in, const int* in_sizes, int n_in,
                              void* d_out, int out_size)
{
    const float* q  = (const float*)d_in[0];
    const float* k  = (const float*)d_in[1];
    const float* v  = (const float*)d_in[2];
    const float* Wq = (const float*)d_in[4];
    const float* bq = (const float*)d_in[5];
    const float* Wk = (const float*)d_in[6];
    const float* bk = (const float*)d_in[7];
    const float* Wv = (const float*)d_in[8];
    const float* bv = (const float*)d_in[9];
    const float* Wo = (const float*)d_in[10];
    const float* bo = (const float*)d_in[11];

    __half *gQh, *gQl, *gKh, *gVh, *gCh, *gCl;
    cudaGetSymbolAddress((void**)&gQh, g_Qh);
    cudaGetSymbolAddress((void**)&gQl, g_Ql);
    cudaGetSymbolAddress((void**)&gKh, g_Kh);
    cudaGetSymbolAddress((void**)&gVh, g_Vh);
    cudaGetSymbolAddress((void**)&gCh, g_Ch);
    cudaGetSymbolAddress((void**)&gCl, g_Cl);

    cudaFuncSetAttribute(qkv_gemm, cudaFuncAttributeMaxDynamicSharedMemorySize, SMEM_SZ);
    cudaFuncSetAttribute(o_gemm,   cudaFuncAttributeMaxDynamicSharedMemorySize, SMEM_SZ);
    cudaFuncSetAttribute(attn_mma, cudaFuncAttributeMaxDynamicSharedMemorySize, ATT_SMEM);

    const int n4a = MM * DD / 4;
    const int n4w = DD * DD / 4;

    // 1) batched conversions
    convert_act<<<dim3((n4a + 255) / 256, 3), 256>>>(q, k, v, n4a);
    convert_w<<<dim3((n4w + 255) / 256, 4), 256>>>(Wq, Wk, Wv, Wo, n4w);

    // 2) fused Q/K/V projections (Q pre-scaled by 0.125, split output)
    qkv_gemm<<<dim3(DD / 128, MM / 128, 3), 256, SMEM_SZ>>>(bq, bk, bv);

    // 3) attention -> ctx hi/lo
    attn_mma<<<dim3(16, HH, BB), 256, ATT_SMEM>>>(gQh, gQl, gKh, gVh, gCh, gCl);

    // 4) output projection (fp32 out)
    o_gemm<<<dim3(DD / 128, MM / 128), 256, SMEM_SZ>>>(bo, (float*)d_out);
}

// round 9
// speedup vs baseline: 8.9780x; 1.0534x over previous
#include <cuda_runtime.h>
#include <cuda_fp16.h>
#include <cstdint>
#include <math.h>

// ---------------------------------------------------------------------------
// Problem constants: B=4, S=2048, D=1024, H=16, dk=64
// ---------------------------------------------------------------------------
#define BB 4
#define SS 2048
#define DD 1024
#define HH 16
#define DK 64
#define MM (BB * SS)          // 8192

// ---------------------------------------------------------------------------
// Scratch (__device__ globals; no cudaMalloc allowed)
// ---------------------------------------------------------------------------
__device__ __half g_A[3][2][(size_t)MM * DD];   // [q/k/v][hi/lo] activations
__device__ __half g_W[4][(size_t)DD * DD];      // [q/k/v/o] weight hi
__device__ __half g_Qh[(size_t)BB * HH * SS * DK];
__device__ __half g_Ql[(size_t)BB * HH * SS * DK];
__device__ __half g_Kh[(size_t)BB * HH * SS * DK];
__device__ __half g_Vh[(size_t)BB * HH * SS * DK];
__device__ __half g_Ch[(size_t)MM * DD];        // ctx hi (O-proj activation)
__device__ __half g_Cl[(size_t)MM * DD];        // ctx lo

// ---------------------------------------------------------------------------
// PTX helpers (arch-portable: ldmatrix / mma.sync / cp.async only)
// ---------------------------------------------------------------------------
__device__ __forceinline__ uint32_t smem_u32(const void* p) {
    uint32_t a;
    asm("{ .reg .u64 t; cvta.to.shared.u64 t, %1; cvt.u32.u64 %0, t; }" : "=r"(a) : "l"(p));
    return a;
}
__device__ __forceinline__ void cp16(uint32_t saddr, const void* g) {
    asm volatile("cp.async.cg.shared.global [%0], [%1], 16;" :: "r"(saddr), "l"(g) : "memory");
}
#define CP_COMMIT() asm volatile("cp.async.commit_group;" ::: "memory")
#define CP_WAIT(n)  asm volatile("cp.async.wait_group %0;" :: "n"(n) : "memory")

#define LDSM4(r, addr) asm volatile( \
    "ldmatrix.sync.aligned.m8n8.x4.shared.b16 {%0,%1,%2,%3}, [%4];" \
    : "=r"((r)[0]), "=r"((r)[1]), "=r"((r)[2]), "=r"((r)[3]) : "r"(addr))
#define LDSM4T(r, addr) asm volatile( \
    "ldmatrix.sync.aligned.m8n8.x4.trans.shared.b16 {%0,%1,%2,%3}, [%4];" \
    : "=r"((r)[0]), "=r"((r)[1]), "=r"((r)[2]), "=r"((r)[3]) : "r"(addr))

#define MMA16816(d, a, b0, b1) asm volatile( \
    "mma.sync.aligned.m16n8k16.row.col.f32.f16.f16.f32 " \
    "{%0,%1,%2,%3}, {%4,%5,%6,%7}, {%8,%9}, {%0,%1,%2,%3};" \
    : "+f"((d)[0]), "+f"((d)[1]), "+f"((d)[2]), "+f"((d)[3]) \
    : "r"((a)[0]), "r"((a)[1]), "r"((a)[2]), "r"((a)[3]), "r"(b0), "r"(b1))

// split two fp32 into packed fp16x2 (hi) and fp16x2 (lo residual)
__device__ __forceinline__ void split2(float x, float y, uint32_t& hp, uint32_t& lp) {
    __half hx = __float2half_rn(x), hy = __float2half_rn(y);
    __half2 hh = __halves2half2(hx, hy);
    __half2 ll = __halves2half2(__float2half_rn(x - __half2float(hx)),
                                __float2half_rn(y - __half2float(hy)));
    hp = *reinterpret_cast<uint32_t*>(&hh);
    lp = *reinterpret_cast<uint32_t*>(&ll);
}
__device__ __forceinline__ uint32_t pack_hi(float x, float y) {
    __half2 hh = __halves2half2(__float2half_rn(x), __float2half_rn(y));
    return *reinterpret_cast<uint32_t*>(&hh);
}

// ---------------------------------------------------------------------------
// Batched conversions
// ---------------------------------------------------------------------------
__global__ __launch_bounds__(256)
void convert_act(const float* __restrict__ x0, const float* __restrict__ x1,
                 const float* __restrict__ x2, int n4)
{
    int i = blockIdx.x * blockDim.x + threadIdx.x;
    if (i >= n4) return;
    int t = blockIdx.y;
    const float* x = (t == 0) ? x0 : (t == 1) ? x1 : x2;
    __half* hi = g_A[t][0];
    __half* lo = g_A[t][1];
    float4 v = ((const float4*)x)[i];
    uint32_t h0, l0, h1, l1;
    split2(v.x, v.y, h0, l0);
    split2(v.z, v.w, h1, l1);
    ((uint32_t*)hi)[2*i]   = h0;
    ((uint32_t*)hi)[2*i+1] = h1;
    ((uint32_t*)lo)[2*i]   = l0;
    ((uint32_t*)lo)[2*i+1] = l1;
}

__global__ __launch_bounds__(256)
void convert_w(const float* __restrict__ w0, const float* __restrict__ w1,
               const float* __restrict__ w2, const float* __restrict__ w3, int n4)
{
    int i = blockIdx.x * blockDim.x + threadIdx.x;
    if (i >= n4) return;
    int t = blockIdx.y;
    const float* x = (t == 0) ? w0 : (t == 1) ? w1 : (t == 2) ? w2 : w3;
    __half* hi = g_W[t];
    float4 v = ((const float4*)x)[i];
    ((uint32_t*)hi)[2*i]   = pack_hi(v.x, v.y);
    ((uint32_t*)hi)[2*i+1] = pack_hi(v.z, v.w);
}

// ---------------------------------------------------------------------------
// HMMA GEMM body: out = (Ah+Al)[M,K] @ Wh[K,N] + bias, fp16 2-pass.
// CTA 128x128, 8 warps (4M x 2N), KC=32, 3-stage cp.async pipeline.
// ---------------------------------------------------------------------------
#define KC 32
#define PA_B 80
#define PB_B 272
#define A_BYTES (128 * PA_B)    // 10240
#define B_BYTES (KC * PB_B)     // 8704
#define OFF_AH 0
#define OFF_AL A_BYTES
#define OFF_BH (2 * A_BYTES)
#define STAGE (2 * A_BYTES + B_BYTES)   // 29184
#define NSTAGES 3
#define SMEM_SZ (NSTAGES * STAGE)       // 87552

__device__ __forceinline__
void gemm_body(const __half* __restrict__ Ah,
               const __half* __restrict__ Al,
               const __half* __restrict__ Wh,
               const float* __restrict__ bias,
               float* __restrict__ outF,
               __half* __restrict__ outH,
               __half* __restrict__ outL,
               float scale, char* smem)
{
    const uint32_t sb = smem_u32(smem);
    const int tid = threadIdx.x;
    const int lane = tid & 31;
    const int warp = tid >> 5;
    const int warpM = warp >> 1;
    const int warpN = warp & 1;
    const int rowBase = blockIdx.y * 128;
    const int colBase = blockIdx.x * 128;

    float acc[2][8][4];
#pragma unroll
    for (int mi = 0; mi < 2; mi++)
#pragma unroll
        for (int ni = 0; ni < 8; ni++)
#pragma unroll
            for (int r = 0; r < 4; r++) acc[mi][ni][r] = 0.f;

    auto load_stage = [&](int ch, int s) {
        const int k0 = ch * KC;
        const uint32_t sbase = sb + s * STAGE;
#pragma unroll
        for (int i = 0; i < 6; i++) {
            int idx = tid + i * 256;       // 0..1535
            int t = idx >> 9;              // 0:Ah 1:Al 2:Wh
            int w = idx & 511;
            if (t < 2) {
                int r = w >> 2, c = w & 3;
                const __half* src = (t == 0 ? Ah : Al) + (size_t)(rowBase + r) * DD + k0 + c * 8;
                cp16(sbase + (t == 0 ? OFF_AH : OFF_AL) + r * PA_B + c * 16, src);
            } else {
                int r = w >> 4, c = w & 15;
                cp16(sbase + OFF_BH + r * PB_B + c * 16,
                     Wh + (size_t)(k0 + r) * DD + colBase + c * 8);
            }
        }
        CP_COMMIT();
    };

    const int NCH = DD / KC;   // 32
    load_stage(0, 0);
    load_stage(1, 1);

    for (int ch = 0; ch < NCH; ch++) {
        CP_WAIT(1);                        // stage ch complete
        __syncthreads();                   // all warps done reading slot (ch+2)%3
        if (ch + 2 < NCH) load_stage(ch + 2, (ch + 2) % NSTAGES);

        const uint32_t stb = sb + (ch % NSTAGES) * STAGE;
#pragma unroll
        for (int kstep = 0; kstep < 2; kstep++) {
            uint32_t ah[2][4], al[2][4];
#pragma unroll
            for (int mi = 0; mi < 2; mi++) {
                uint32_t row = warpM * 32 + mi * 16 + (lane & 15);
                uint32_t ad = stb + OFF_AH + row * PA_B + kstep * 32 + (lane >> 4) * 16;
                LDSM4(ah[mi], ad);
                LDSM4(al[mi], ad + (OFF_AL - OFF_AH));
            }
            uint32_t bh[4][4];
#pragma unroll
            for (int ng = 0; ng < 4; ng++) {
                uint32_t krow = kstep * 16 + (lane & 15);
                uint32_t coln = warpN * 64 + ng * 16 + (lane >> 4) * 8;
                LDSM4T(bh[ng], stb + OFF_BH + krow * PB_B + coln * 2);
            }
#pragma unroll
            for (int mi = 0; mi < 2; mi++)
#pragma unroll
                for (int ni = 0; ni < 8; ni++) {
                    uint32_t b0 = bh[ni >> 1][(ni & 1) * 2];
                    uint32_t b1 = bh[ni >> 1][(ni & 1) * 2 + 1];
                    MMA16816(acc[mi][ni], ah[mi], b0, b1);
                    MMA16816(acc[mi][ni], al[mi], b0, b1);
                }
        }
    }

    // ---- epilogue ----
    const int lg = lane >> 2;
    const int l4 = lane & 3;
#pragma unroll
    for (int mi = 0; mi < 2; mi++) {
#pragma unroll
        for (int ni = 0; ni < 8; ni++) {
            int r0 = rowBase + warpM * 32 + mi * 16 + lg;
            int r1 = r0 + 8;
            int col = colBase + warpN * 64 + ni * 8 + l4 * 2;
            float v00 = (acc[mi][ni][0] + bias[col]) * scale;
            float v01 = (acc[mi][ni][1] + bias[col + 1]) * scale;
            float v10 = (acc[mi][ni][2] + bias[col]) * scale;
            float v11 = (acc[mi][ni][3] + bias[col + 1]) * scale;
            if (outF) {
                *(float2*)(outF + (size_t)r0 * DD + col) = make_float2(v00, v01);
                *(float2*)(outF + (size_t)r1 * DD + col) = make_float2(v10, v11);
            } else {
                int h = col >> 6, dd = col & (DK - 1);
                int b0r = r0 >> 11, s0 = r0 & (SS - 1);
                int b1r = r1 >> 11, s1 = r1 & (SS - 1);
                size_t o0 = (((size_t)(b0r * HH + h)) * SS + s0) * DK + dd;
                size_t o1 = (((size_t)(b1r * HH + h)) * SS + s1) * DK + dd;
                if (outL) {
                    uint32_t hp, lp;
                    split2(v00, v01, hp, lp);
                    *(uint32_t*)(outH + o0) = hp;
                    *(uint32_t*)(outL + o0) = lp;
                    split2(v10, v11, hp, lp);
                    *(uint32_t*)(outH + o1) = hp;
                    *(uint32_t*)(outL + o1) = lp;
                } else {
                    *(uint32_t*)(outH + o0) = pack_hi(v00, v01);
                    *(uint32_t*)(outH + o1) = pack_hi(v10, v11);
                }
            }
        }
    }
}

// Fused QKV projections: blockIdx.z selects q/k/v.
__global__ __launch_bounds__(256, 2)
void qkv_gemm(const float* __restrict__ bq, const float* __restrict__ bk,
              const float* __restrict__ bv)
{
    extern __shared__ char smem[];
    const int z = blockIdx.z;
    if (z == 0)
        gemm_body(g_A[0][0], g_A[0][1], g_W[0], bq, nullptr, g_Qh, g_Ql, 0.125f, smem);
    else if (z == 1)
        gemm_body(g_A[1][0], g_A[1][1], g_W[1], bk, nullptr, g_Kh, nullptr, 1.f, smem);
    else
        gemm_body(g_A[2][0], g_A[2][1], g_W[2], bv, nullptr, g_Vh, nullptr, 1.f, smem);
}

// Output projection: ctx hi/lo @ Wo -> fp32 out.
__global__ __launch_bounds__(256, 2)
void o_gemm(const float* __restrict__ bo, float* __restrict__ out)
{
    extern __shared__ char smem[];
    gemm_body(g_Ch, g_Cl, g_W[3], bo, out, nullptr, nullptr, 1.f, smem);
}

// ---------------------------------------------------------------------------
// HMMA causal flash attention, fp16 2-pass.
// CTA: 64 q-rows of one (b,h); 4 warps x 16 rows; 64-key tiles, 2-stage.
// 128-thread CTAs -> 3 CTAs/SM (regs+smem), overlapping softmax with MMA.
// ---------------------------------------------------------------------------
#define APITCH 144
#define ASQH 0
#define ASQL 9216                        // 64 rows * 144B
#define AKV0 18432
#define AKSTAGE 18432                    // Kh(9216) Vh(9216)
#define ATT_SMEM (AKV0 + 2 * AKSTAGE)    // 55296

__global__ __launch_bounds__(128)
void attn_mma(const __half* __restrict__ Qh, const __half* __restrict__ Ql,
              const __half* __restrict__ Kh, const __half* __restrict__ Vh,
              __half* __restrict__ Ch, __half* __restrict__ Cl)
{
    extern __shared__ char smem[];
    const uint32_t sb = smem_u32(smem);
    const int tid = threadIdx.x;
    const int lane = tid & 31;
    const int warp = tid >> 5;          // 0..3
    const int lg = lane >> 2;
    const int l4 = lane & 3;

    const int qt = 31 - blockIdx.x;     // 64-row q tile, heavy first
    const int h  = blockIdx.y;
    const int b  = blockIdx.z;
    const size_t bhoff = (size_t)(b * HH + h) * SS * DK;

    // --- stage Q (hi+lo): 2 mats x 64 rows x 8 chunks = 1024 chunks ---
#pragma unroll
    for (int i = 0; i < 8; i++) {
        int idx = tid + i * 128;
        int mat = idx >> 9;            // 0:Qh 1:Ql
        int w = idx & 511;
        int r = w >> 3, c = w & 7;
        const __half* src = (mat ? Ql : Qh) + bhoff + (size_t)(qt * 64 + r) * DK + c * 8;
        cp16(sb + mat * ASQL + r * APITCH + c * 16, src);
    }
    CP_COMMIT();

    auto kv_load = [&](int jt, int st) {
        uint32_t base = sb + AKV0 + st * AKSTAGE;
        size_t koff = bhoff + (size_t)jt * 64 * DK;
#pragma unroll
        for (int i = 0; i < 8; i++) {
            int idx = tid + i * 128;
            int mat = idx >> 9;        // 0:Kh 1:Vh
            int w = idx & 511;
            int r = w >> 3, c = w & 7;
            const __half* mp = mat ? Vh : Kh;
            cp16(base + mat * 9216 + r * APITCH + c * 16, mp + koff + (size_t)r * DK + c * 8);
        }
        CP_COMMIT();
    };

    kv_load(0, 0);
    CP_WAIT(1);                  // Q group done
    __syncthreads();

    // --- Q fragments in registers ---
    uint32_t qah[4][4], qal[4][4];
#pragma unroll
    for (int kk = 0; kk < 4; kk++) {
        uint32_t ad = sb + ASQH + (warp * 16 + (lane & 15)) * APITCH + kk * 32 + (lane >> 4) * 16;
        LDSM4(qah[kk], ad);
        LDSM4(qal[kk], ad + ASQL);
    }

    float o[8][4];
#pragma unroll
    for (int c = 0; c < 8; c++)
#pragma unroll
        for (int r = 0; r < 4; r++) o[c][r] = 0.f;
    float m0 = -1e30f, m1 = -1e30f, l0 = 0.f, l1 = 0.f;

    const int row0 = qt * 64 + warp * 16 + lg;
    const int ntiles = qt + 1;

    for (int jt = 0; jt < ntiles; jt++) {
        if (jt + 1 < ntiles) { kv_load(jt + 1, (jt + 1) & 1); CP_WAIT(1); }
        else                 { CP_WAIT(0); }
        __syncthreads();

        const uint32_t kvb = sb + AKV0 + (jt & 1) * AKSTAGE;

        // ---- scores: S = (Qh+Ql) Kh ----
        float s[8][4];
#pragma unroll
        for (int c = 0; c < 8; c++)
#pragma unroll
            for (int r = 0; r < 4; r++) s[c][r] = 0.f;

#pragma unroll
        for (int ng = 0; ng < 4; ng++) {
#pragma unroll
            for (int kk = 0; kk < 4; kk++) {
                uint32_t kh[4];
                LDSM4(kh, kvb + (ng * 16 + (lane & 15)) * APITCH + kk * 32 + (lane >> 4) * 16);
                MMA16816(s[2 * ng],     qah[kk], kh[0], kh[2]);
                MMA16816(s[2 * ng],     qal[kk], kh[0], kh[2]);
                MMA16816(s[2 * ng + 1], qah[kk], kh[1], kh[3]);
                MMA16816(s[2 * ng + 1], qal[kk], kh[1], kh[3]);
            }
        }

        // ---- causal mask vs the warp's MINIMUM row ----
        if (jt * 64 + 63 > qt * 64 + warp * 16) {
#pragma unroll
            for (int c = 0; c < 8; c++) {
                int col = jt * 64 + c * 8 + 2 * l4;
                if (col > row0)         s[c][0] = -1e30f;
                if (col + 1 > row0)     s[c][1] = -1e30f;
                if (col > row0 + 8)     s[c][2] = -1e30f;
                if (col + 1 > row0 + 8) s[c][3] = -1e30f;
            }
        }

        // ---- online softmax ----
        float mx0 = -1e30f, mx1 = -1e30f;
#pragma unroll
        for (int c = 0; c < 8; c++) {
            mx0 = fmaxf(mx0, fmaxf(s[c][0], s[c][1]));
            mx1 = fmaxf(mx1, fmaxf(s[c][2], s[c][3]));
        }
        mx0 = fmaxf(mx0, __shfl_xor_sync(0xFFFFFFFFu, mx0, 1));
        mx0 = fmaxf(mx0, __shfl_xor_sync(0xFFFFFFFFu, mx0, 2));
        mx1 = fmaxf(mx1, __shfl_xor_sync(0xFFFFFFFFu, mx1, 1));
        mx1 = fmaxf(mx1, __shfl_xor_sync(0xFFFFFFFFu, mx1, 2));
        float mn0 = fmaxf(m0, mx0), mn1 = fmaxf(m1, mx1);
        float sc0 = __expf(m0 - mn0), sc1 = __expf(m1 - mn1);
        m0 = mn0; m1 = mn1;
        l0 *= sc0; l1 *= sc1;
#pragma unroll
        for (int c = 0; c < 8; c++) {
            o[c][0] *= sc0; o[c][1] *= sc0;
            o[c][2] *= sc1; o[c][3] *= sc1;
        }
#pragma unroll
        for (int c = 0; c < 8; c++) {
            s[c][0] = __expf(s[c][0] - mn0);
            s[c][1] = __expf(s[c][1] - mn0);
            s[c][2] = __expf(s[c][2] - mn1);
            s[c][3] = __expf(s[c][3] - mn1);
            l0 += s[c][0] + s[c][1];
            l1 += s[c][2] + s[c][3];
        }

        // ---- P fragments (hi/lo), FA2 register reuse ----
        uint32_t pah[4][4], pal[4][4];
#pragma unroll
        for (int kk = 0; kk < 4; kk++) {
            split2(s[2 * kk][0],     s[2 * kk][1],     pah[kk][0], pal[kk][0]);
            split2(s[2 * kk][2],     s[2 * kk][3],     pah[kk][1], pal[kk][1]);
            split2(s[2 * kk + 1][0], s[2 * kk + 1][1], pah[kk][2], pal[kk][2]);
            split2(s[2 * kk + 1][2], s[2 * kk + 1][3], pah[kk][3], pal[kk][3]);
        }

        // ---- O += (Ph+Pl) Vh ----
#pragma unroll
        for (int dg = 0; dg < 4; dg++) {
#pragma unroll
            for (int kk = 0; kk < 4; kk++) {
                uint32_t vh[4];
                LDSM4T(vh, kvb + 9216 + (kk * 16 + (lane & 15)) * APITCH
                           + dg * 32 + (lane >> 4) * 16);
                MMA16816(o[2 * dg],     pah[kk], vh[0], vh[1]);
                MMA16816(o[2 * dg],     pal[kk], vh[0], vh[1]);
                MMA16816(o[2 * dg + 1], pah[kk], vh[2], vh[3]);
                MMA16816(o[2 * dg + 1], pal[kk], vh[2], vh[3]);
            }
        }
        __syncthreads();
    }

    // ---- finalize: normalize and write ctx hi/lo in [B,S,D] ----
    l0 += __shfl_xor_sync(0xFFFFFFFFu, l0, 1);
    l0 += __shfl_xor_sync(0xFFFFFFFFu, l0, 2);
    l1 += __shfl_xor_sync(0xFFFFFFFFu, l1, 1);
    l1 += __shfl_xor_sync(0xFFFFFFFFu, l1, 2);
    const float inv0 = 1.f / l0, inv1 = 1.f / l1;

    const size_t r0 = (size_t)b * SS + row0;
    const size_t r1 = r0 + 8;
#pragma unroll
    for (int c = 0; c < 8; c++) {
        int col = h * DK + c * 8 + 2 * l4;
        uint32_t hp, lp;
        split2(o[c][0] * inv0, o[c][1] * inv0, hp, lp);
        *(uint32_t*)(Ch + r0 * DD + col) = hp;
        *(uint32_t*)(Cl + r0 * DD + col) = lp;
        split2(o[c][2] * inv1, o[c][3] * inv1, hp, lp);
        *(uint32_t*)(Ch + r1 * DD + col) = hp;
        *(uint32_t*)(Cl + r1 * DD + col) = lp;
    }
}

// ---------------------------------------------------------------------------
// Launch
// ---------------------------------------------------------------------------
extern "C" void kernel_launch(void* const* d_in, const int* in_sizes, int n_in,
                              void* d_out, int out_size)
{
    const float* q  = (const float*)d_in[0];
    const float* k  = (const float*)d_in[1];
    const float* v  = (const float*)d_in[2];
    const float* Wq = (const float*)d_in[4];
    const float* bq = (const float*)d_in[5];
    const float* Wk = (const float*)d_in[6];
    const float* bk = (const float*)d_in[7];
    const float* Wv = (const float*)d_in[8];
    const float* bv = (const float*)d_in[9];
    const float* Wo = (const float*)d_in[10];
    const float* bo = (const float*)d_in[11];

    __half *gQh, *gQl, *gKh, *gVh, *gCh, *gCl;
    cudaGetSymbolAddress((void**)&gQh, g_Qh);
    cudaGetSymbolAddress((void**)&gQl, g_Ql);
    cudaGetSymbolAddress((void**)&gKh, g_Kh);
    cudaGetSymbolAddress((void**)&gVh, g_Vh);
    cudaGetSymbolAddress((void**)&gCh, g_Ch);
    cudaGetSymbolAddress((void**)&gCl, g_Cl);

    cudaFuncSetAttribute(qkv_gemm, cudaFuncAttributeMaxDynamicSharedMemorySize, SMEM_SZ);
    cudaFuncSetAttribute(o_gemm,   cudaFuncAttributeMaxDynamicSharedMemorySize, SMEM_SZ);
    cudaFuncSetAttribute(attn_mma, cudaFuncAttributeMaxDynamicSharedMemorySize, ATT_SMEM);

    const int n4a = MM * DD / 4;
    const int n4w = DD * DD / 4;

    // 1) batched conversions
    convert_act<<<dim3((n4a + 255) / 256, 3), 256>>>(q, k, v, n4a);
    convert_w<<<dim3((n4w + 255) / 256, 4), 256>>>(Wq, Wk, Wv, Wo, n4w);

    // 2) fused Q/K/V projections (Q pre-scaled by 0.125, split output)
    qkv_gemm<<<dim3(DD / 128, MM / 128, 3), 256, SMEM_SZ>>>(bq, bk, bv);

    // 3) attention -> ctx hi/lo (64-row q tiles, 128-thread CTAs)
    attn_mma<<<dim3(32, HH, BB), 128, ATT_SMEM>>>(gQh, gQl, gKh, gVh, gCh, gCl);

    // 4) output projection (fp32 out)
    o_gemm<<<dim3(DD / 128, MM / 128), 256, SMEM_SZ>>>(bo, (float*)d_out);
}

// round 10
// speedup vs baseline: 9.0647x; 1.0097x over previous
#include <cuda_runtime.h>
#include <cuda_fp16.h>
#include <cstdint>
#include <math.h>

// ---------------------------------------------------------------------------
// Problem constants: B=4, S=2048, D=1024, H=16, dk=64
// ---------------------------------------------------------------------------
#define BB 4
#define SS 2048
#define DD 1024
#define HH 16
#define DK 64
#define MM (BB * SS)          // 8192

// Q pre-scale: (1/sqrt(dk)) * log2(e)  -> lets softmax use exp2f
#define QSCALE 0.1803368801111204f

// ---------------------------------------------------------------------------
// Scratch (__device__ globals; no cudaMalloc allowed)
// ---------------------------------------------------------------------------
__device__ __half g_A[3][2][(size_t)MM * DD];   // [q/k/v][hi/lo] activations
__device__ __half g_W[4][(size_t)DD * DD];      // [q/k/v/o] weight hi
__device__ __half g_Qh[(size_t)BB * HH * SS * DK];
__device__ __half g_Ql[(size_t)BB * HH * SS * DK];
__device__ __half g_Kh[(size_t)BB * HH * SS * DK];
__device__ __half g_Vh[(size_t)BB * HH * SS * DK];
__device__ __half g_Ch[(size_t)MM * DD];        // ctx hi (O-proj activation)
__device__ __half g_Cl[(size_t)MM * DD];        // ctx lo

// ---------------------------------------------------------------------------
// PTX helpers (arch-portable: ldmatrix / mma.sync / cp.async only)
// ---------------------------------------------------------------------------
__device__ __forceinline__ uint32_t smem_u32(const void* p) {
    uint32_t a;
    asm("{ .reg .u64 t; cvta.to.shared.u64 t, %1; cvt.u32.u64 %0, t; }" : "=r"(a) : "l"(p));
    return a;
}
__device__ __forceinline__ void cp16(uint32_t saddr, const void* g) {
    asm volatile("cp.async.cg.shared.global [%0], [%1], 16;" :: "r"(saddr), "l"(g) : "memory");
}
#define CP_COMMIT() asm volatile("cp.async.commit_group;" ::: "memory")
#define CP_WAIT(n)  asm volatile("cp.async.wait_group %0;" :: "n"(n) : "memory")

#define LDSM4(r, addr) asm volatile( \
    "ldmatrix.sync.aligned.m8n8.x4.shared.b16 {%0,%1,%2,%3}, [%4];" \
    : "=r"((r)[0]), "=r"((r)[1]), "=r"((r)[2]), "=r"((r)[3]) : "r"(addr))
#define LDSM4T(r, addr) asm volatile( \
    "ldmatrix.sync.aligned.m8n8.x4.trans.shared.b16 {%0,%1,%2,%3}, [%4];" \
    : "=r"((r)[0]), "=r"((r)[1]), "=r"((r)[2]), "=r"((r)[3]) : "r"(addr))

#define MMA16816(d, a, b0, b1) asm volatile( \
    "mma.sync.aligned.m16n8k16.row.col.f32.f16.f16.f32 " \
    "{%0,%1,%2,%3}, {%4,%5,%6,%7}, {%8,%9}, {%0,%1,%2,%3};" \
    : "+f"((d)[0]), "+f"((d)[1]), "+f"((d)[2]), "+f"((d)[3]) \
    : "r"((a)[0]), "r"((a)[1]), "r"((a)[2]), "r"((a)[3]), "r"(b0), "r"(b1))

// split two fp32 into packed fp16x2 (hi) and fp16x2 (lo residual)
__device__ __forceinline__ void split2(float x, float y, uint32_t& hp, uint32_t& lp) {
    __half hx = __float2half_rn(x), hy = __float2half_rn(y);
    __half2 hh = __halves2half2(hx, hy);
    __half2 ll = __halves2half2(__float2half_rn(x - __half2float(hx)),
                                __float2half_rn(y - __half2float(hy)));
    hp = *reinterpret_cast<uint32_t*>(&hh);
    lp = *reinterpret_cast<uint32_t*>(&ll);
}
__device__ __forceinline__ uint32_t pack_hi(float x, float y) {
    __half2 hh = __halves2half2(__float2half_rn(x), __float2half_rn(y));
    return *reinterpret_cast<uint32_t*>(&hh);
}

// ---------------------------------------------------------------------------
// Batched conversions
// ---------------------------------------------------------------------------
__global__ __launch_bounds__(256)
void convert_act(const float* __restrict__ x0, const float* __restrict__ x1,
                 const float* __restrict__ x2, int n4)
{
    int i = blockIdx.x * blockDim.x + threadIdx.x;
    if (i >= n4) return;
    int t = blockIdx.y;
    const float* x = (t == 0) ? x0 : (t == 1) ? x1 : x2;
    __half* hi = g_A[t][0];
    __half* lo = g_A[t][1];
    float4 v = ((const float4*)x)[i];
    uint32_t h0, l0, h1, l1;
    split2(v.x, v.y, h0, l0);
    split2(v.z, v.w, h1, l1);
    ((uint32_t*)hi)[2*i]   = h0;
    ((uint32_t*)hi)[2*i+1] = h1;
    ((uint32_t*)lo)[2*i]   = l0;
    ((uint32_t*)lo)[2*i+1] = l1;
}

__global__ __launch_bounds__(256)
void convert_w(const float* __restrict__ w0, const float* __restrict__ w1,
               const float* __restrict__ w2, const float* __restrict__ w3, int n4)
{
    int i = blockIdx.x * blockDim.x + threadIdx.x;
    if (i >= n4) return;
    int t = blockIdx.y;
    const float* x = (t == 0) ? w0 : (t == 1) ? w1 : (t == 2) ? w2 : w3;
    __half* hi = g_W[t];
    float4 v = ((const float4*)x)[i];
    ((uint32_t*)hi)[2*i]   = pack_hi(v.x, v.y);
    ((uint32_t*)hi)[2*i+1] = pack_hi(v.z, v.w);
}

// ---------------------------------------------------------------------------
// HMMA GEMM body: out = (Ah+Al)[M,K] @ Wh[K,N] + bias, fp16 2-pass.
// CTA 128x128, 8 warps (4M x 2N), KC=32, 3-stage cp.async pipeline.
// ---------------------------------------------------------------------------
#define KC 32
#define PA_B 80
#define PB_B 272
#define A_BYTES (128 * PA_B)    // 10240
#define B_BYTES (KC * PB_B)     // 8704
#define OFF_AH 0
#define OFF_AL A_BYTES
#define OFF_BH (2 * A_BYTES)
#define STAGE (2 * A_BYTES + B_BYTES)   // 29184
#define NSTAGES 3
#define SMEM_SZ (NSTAGES * STAGE)       // 87552

__device__ __forceinline__
void gemm_body(const __half* __restrict__ Ah,
               const __half* __restrict__ Al,
               const __half* __restrict__ Wh,
               const float* __restrict__ bias,
               float* __restrict__ outF,
               __half* __restrict__ outH,
               __half* __restrict__ outL,
               float scale, char* smem)
{
    const uint32_t sb = smem_u32(smem);
    const int tid = threadIdx.x;
    const int lane = tid & 31;
    const int warp = tid >> 5;
    const int warpM = warp >> 1;
    const int warpN = warp & 1;
    const int rowBase = blockIdx.y * 128;
    const int colBase = blockIdx.x * 128;

    float acc[2][8][4];
#pragma unroll
    for (int mi = 0; mi < 2; mi++)
#pragma unroll
        for (int ni = 0; ni < 8; ni++)
#pragma unroll
            for (int r = 0; r < 4; r++) acc[mi][ni][r] = 0.f;

    auto load_stage = [&](int ch, int s) {
        const int k0 = ch * KC;
        const uint32_t sbase = sb + s * STAGE;
#pragma unroll
        for (int i = 0; i < 6; i++) {
            int idx = tid + i * 256;       // 0..1535
            int t = idx >> 9;              // 0:Ah 1:Al 2:Wh
            int w = idx & 511;
            if (t < 2) {
                int r = w >> 2, c = w & 3;
                const __half* src = (t == 0 ? Ah : Al) + (size_t)(rowBase + r) * DD + k0 + c * 8;
                cp16(sbase + (t == 0 ? OFF_AH : OFF_AL) + r * PA_B + c * 16, src);
            } else {
                int r = w >> 4, c = w & 15;
                cp16(sbase + OFF_BH + r * PB_B + c * 16,
                     Wh + (size_t)(k0 + r) * DD + colBase + c * 8);
            }
        }
        CP_COMMIT();
    };

    const int NCH = DD / KC;   // 32
    load_stage(0, 0);
    load_stage(1, 1);

    for (int ch = 0; ch < NCH; ch++) {
        CP_WAIT(1);                        // stage ch complete
        __syncthreads();                   // all warps done reading slot (ch+2)%3
        if (ch + 2 < NCH) load_stage(ch + 2, (ch + 2) % NSTAGES);

        const uint32_t stb = sb + (ch % NSTAGES) * STAGE;
#pragma unroll
        for (int kstep = 0; kstep < 2; kstep++) {
            uint32_t ah[2][4], al[2][4];
#pragma unroll
            for (int mi = 0; mi < 2; mi++) {
                uint32_t row = warpM * 32 + mi * 16 + (lane & 15);
                uint32_t ad = stb + OFF_AH + row * PA_B + kstep * 32 + (lane >> 4) * 16;
                LDSM4(ah[mi], ad);
                LDSM4(al[mi], ad + (OFF_AL - OFF_AH));
            }
            uint32_t bh[4][4];
#pragma unroll
            for (int ng = 0; ng < 4; ng++) {
                uint32_t krow = kstep * 16 + (lane & 15);
                uint32_t coln = warpN * 64 + ng * 16 + (lane >> 4) * 8;
                LDSM4T(bh[ng], stb + OFF_BH + krow * PB_B + coln * 2);
            }
#pragma unroll
            for (int mi = 0; mi < 2; mi++)
#pragma unroll
                for (int ni = 0; ni < 8; ni++) {
                    uint32_t b0 = bh[ni >> 1][(ni & 1) * 2];
                    uint32_t b1 = bh[ni >> 1][(ni & 1) * 2 + 1];
                    MMA16816(acc[mi][ni], ah[mi], b0, b1);
                    MMA16816(acc[mi][ni], al[mi], b0, b1);
                }
        }
    }

    // ---- epilogue ----
    const int lg = lane >> 2;
    const int l4 = lane & 3;
#pragma unroll
    for (int mi = 0; mi < 2; mi++) {
#pragma unroll
        for (int ni = 0; ni < 8; ni++) {
            int r0 = rowBase + warpM * 32 + mi * 16 + lg;
            int r1 = r0 + 8;
            int col = colBase + warpN * 64 + ni * 8 + l4 * 2;
            float v00 = (acc[mi][ni][0] + bias[col]) * scale;
            float v01 = (acc[mi][ni][1] + bias[col + 1]) * scale;
            float v10 = (acc[mi][ni][2] + bias[col]) * scale;
            float v11 = (acc[mi][ni][3] + bias[col + 1]) * scale;
            if (outF) {
                *(float2*)(outF + (size_t)r0 * DD + col) = make_float2(v00, v01);
                *(float2*)(outF + (size_t)r1 * DD + col) = make_float2(v10, v11);
            } else {
                int h = col >> 6, dd = col & (DK - 1);
                int b0r = r0 >> 11, s0 = r0 & (SS - 1);
                int b1r = r1 >> 11, s1 = r1 & (SS - 1);
                size_t o0 = (((size_t)(b0r * HH + h)) * SS + s0) * DK + dd;
                size_t o1 = (((size_t)(b1r * HH + h)) * SS + s1) * DK + dd;
                if (outL) {
                    uint32_t hp, lp;
                    split2(v00, v01, hp, lp);
                    *(uint32_t*)(outH + o0) = hp;
                    *(uint32_t*)(outL + o0) = lp;
                    split2(v10, v11, hp, lp);
                    *(uint32_t*)(outH + o1) = hp;
                    *(uint32_t*)(outL + o1) = lp;
                } else {
                    *(uint32_t*)(outH + o0) = pack_hi(v00, v01);
                    *(uint32_t*)(outH + o1) = pack_hi(v10, v11);
                }
            }
        }
    }
}

// Fused QKV projections: blockIdx.z selects q/k/v.
__global__ __launch_bounds__(256, 2)
void qkv_gemm(const float* __restrict__ bq, const float* __restrict__ bk,
              const float* __restrict__ bv)
{
    extern __shared__ char smem[];
    const int z = blockIdx.z;
    if (z == 0)
        gemm_body(g_A[0][0], g_A[0][1], g_W[0], bq, nullptr, g_Qh, g_Ql, QSCALE, smem);
    else if (z == 1)
        gemm_body(g_A[1][0], g_A[1][1], g_W[1], bk, nullptr, g_Kh, nullptr, 1.f, smem);
    else
        gemm_body(g_A[2][0], g_A[2][1], g_W[2], bv, nullptr, g_Vh, nullptr, 1.f, smem);
}

// Output projection: ctx hi/lo @ Wo -> fp32 out.
__global__ __launch_bounds__(256, 2)
void o_gemm(const float* __restrict__ bo, float* __restrict__ out)
{
    extern __shared__ char smem[];
    gemm_body(g_Ch, g_Cl, g_W[3], bo, out, nullptr, nullptr, 1.f, smem);
}

// ---------------------------------------------------------------------------
// HMMA causal flash attention, fp16 2-pass, exp2 softmax.
// CTA: 64 q-rows of one (b,h); 4 warps x 16 rows; 64-key tiles, 3-stage ring.
// smem 73728 -> 3 CTAs/SM; diagonal-tile MMA skip.
// ---------------------------------------------------------------------------
#define APITCH 144
#define ASQH 0
#define ASQL 9216                        // 64 rows * 144B
#define AKV0 18432
#define AKSTAGE 18432                    // Kh(9216) Vh(9216)
#define AKV_ST 3
#define ATT_SMEM (AKV0 + AKV_ST * AKSTAGE)   // 73728

__global__ __launch_bounds__(128)
void attn_mma(const __half* __restrict__ Qh, const __half* __restrict__ Ql,
              const __half* __restrict__ Kh, const __half* __restrict__ Vh,
              __half* __restrict__ Ch, __half* __restrict__ Cl)
{
    extern __shared__ char smem[];
    const uint32_t sb = smem_u32(smem);
    const int tid = threadIdx.x;
    const int lane = tid & 31;
    const int warp = tid >> 5;          // 0..3
    const int lg = lane >> 2;
    const int l4 = lane & 3;
    const uint32_t lrow = (uint32_t)(lane & 15) * APITCH + (uint32_t)(lane >> 4) * 16;

    const int qt = 31 - blockIdx.x;     // 64-row q tile, heavy first
    const int h  = blockIdx.y;
    const int b  = blockIdx.z;
    const size_t bhoff = (size_t)(b * HH + h) * SS * DK;

    // --- stage Q (hi+lo): 2 mats x 64 rows x 8 chunks = 1024 chunks ---
#pragma unroll
    for (int i = 0; i < 8; i++) {
        int idx = tid + i * 128;
        int mat = idx >> 9;            // 0:Qh 1:Ql
        int w = idx & 511;
        int r = w >> 3, c = w & 7;
        const __half* src = (mat ? Ql : Qh) + bhoff + (size_t)(qt * 64 + r) * DK + c * 8;
        cp16(sb + mat * ASQL + r * APITCH + c * 16, src);
    }
    CP_COMMIT();

    auto kv_load = [&](int jt, int st) {
        uint32_t base = sb + AKV0 + st * AKSTAGE;
        size_t koff = bhoff + (size_t)jt * 64 * DK;
#pragma unroll
        for (int i = 0; i < 8; i++) {
            int idx = tid + i * 128;
            int mat = idx >> 9;        // 0:Kh 1:Vh
            int w = idx & 511;
            int r = w >> 3, c = w & 7;
            const __half* mp = mat ? Vh : Kh;
            cp16(base + mat * 9216 + r * APITCH + c * 16, mp + koff + (size_t)r * DK + c * 8);
        }
        CP_COMMIT();
    };

    const int ntiles = qt + 1;
    kv_load(0, 0);
    if (ntiles > 1) kv_load(1, 1);
    CP_WAIT(1);                  // Q + kv0 done (kv1 may be pending)
    __syncthreads();

    // --- Q fragments in registers ---
    uint32_t qah[4][4], qal[4][4];
#pragma unroll
    for (int kk = 0; kk < 4; kk++) {
        uint32_t ad = sb + ASQH + warp * (16 * APITCH) + lrow + kk * 32;
        LDSM4(qah[kk], ad);
        LDSM4(qal[kk], ad + ASQL);
    }

    float o[8][4];
#pragma unroll
    for (int c = 0; c < 8; c++)
#pragma unroll
        for (int r = 0; r < 4; r++) o[c][r] = 0.f;
    float m0 = -1e30f, m1 = -1e30f, l0 = 0.f, l1 = 0.f;

    const int row0 = qt * 64 + warp * 16 + lg;

    for (int jt = 0; jt < ntiles; jt++) {
        // ensure kv(jt) complete (kv(jt+1) may stay in flight)
        if (jt + 1 < ntiles) { CP_WAIT(1); } else { CP_WAIT(0); }
        __syncthreads();                       // all warps done with stage (jt+2)%3 reads
        if (jt + 2 < ntiles) kv_load(jt + 2, (jt + 2) % AKV_ST);

        const uint32_t kvb = sb + AKV0 + (jt % AKV_ST) * AKSTAGE;
        const bool diag = (jt == qt);
        const int nglim = diag ? (warp + 1) : 4;

        // ---- scores: S = (Qh+Ql) Kh ----
        float s[8][4];
#pragma unroll
        for (int c = 0; c < 8; c++)
#pragma unroll
            for (int r = 0; r < 4; r++) s[c][r] = 0.f;

#pragma unroll
        for (int ng = 0; ng < 4; ng++) {
            if (ng < nglim) {
#pragma unroll
                for (int kk = 0; kk < 4; kk++) {
                    uint32_t kh[4];
                    LDSM4(kh, kvb + ng * (16 * APITCH) + lrow + kk * 32);
                    MMA16816(s[2 * ng],     qah[kk], kh[0], kh[2]);
                    MMA16816(s[2 * ng],     qal[kk], kh[0], kh[2]);
                    MMA16816(s[2 * ng + 1], qah[kk], kh[1], kh[3]);
                    MMA16816(s[2 * ng + 1], qal[kk], kh[1], kh[3]);
                }
            }
        }

        // ---- causal mask (diagonal tile only; skipped groups covered too) ----
        if (diag) {
#pragma unroll
            for (int c = 0; c < 8; c++) {
                int col = jt * 64 + c * 8 + 2 * l4;
                if (col > row0)         s[c][0] = -1e30f;
                if (col + 1 > row0)     s[c][1] = -1e30f;
                if (col > row0 + 8)     s[c][2] = -1e30f;
                if (col + 1 > row0 + 8) s[c][3] = -1e30f;
            }
        }

        // ---- online softmax (base-2 domain; Q pre-scaled by log2e/8) ----
        float mx0 = -1e30f, mx1 = -1e30f;
#pragma unroll
        for (int c = 0; c < 8; c++) {
            mx0 = fmaxf(mx0, fmaxf(s[c][0], s[c][1]));
            mx1 = fmaxf(mx1, fmaxf(s[c][2], s[c][3]));
        }
        mx0 = fmaxf(mx0, __shfl_xor_sync(0xFFFFFFFFu, mx0, 1));
        mx0 = fmaxf(mx0, __shfl_xor_sync(0xFFFFFFFFu, mx0, 2));
        mx1 = fmaxf(mx1, __shfl_xor_sync(0xFFFFFFFFu, mx1, 1));
        mx1 = fmaxf(mx1, __shfl_xor_sync(0xFFFFFFFFu, mx1, 2));
        float mn0 = fmaxf(m0, mx0), mn1 = fmaxf(m1, mx1);
        float sc0 = exp2f(m0 - mn0), sc1 = exp2f(m1 - mn1);
        m0 = mn0; m1 = mn1;
        l0 *= sc0; l1 *= sc1;
#pragma unroll
        for (int c = 0; c < 8; c++) {
            o[c][0] *= sc0; o[c][1] *= sc0;
            o[c][2] *= sc1; o[c][3] *= sc1;
        }
#pragma unroll
        for (int c = 0; c < 8; c++) {
            s[c][0] = exp2f(s[c][0] - mn0);
            s[c][1] = exp2f(s[c][1] - mn0);
            s[c][2] = exp2f(s[c][2] - mn1);
            s[c][3] = exp2f(s[c][3] - mn1);
            l0 += s[c][0] + s[c][1];
            l1 += s[c][2] + s[c][3];
        }

        // ---- P fragments (hi/lo); skip fully-masked key groups on diagonal ----
        uint32_t pah[4][4], pal[4][4];
#pragma unroll
        for (int kk = 0; kk < 4; kk++) {
            if (kk < nglim) {
                split2(s[2 * kk][0],     s[2 * kk][1],     pah[kk][0], pal[kk][0]);
                split2(s[2 * kk][2],     s[2 * kk][3],     pah[kk][1], pal[kk][1]);
                split2(s[2 * kk + 1][0], s[2 * kk + 1][1], pah[kk][2], pal[kk][2]);
                split2(s[2 * kk + 1][2], s[2 * kk + 1][3], pah[kk][3], pal[kk][3]);
            }
        }

        // ---- O += (Ph+Pl) Vh ----
#pragma unroll
        for (int dg = 0; dg < 4; dg++) {
#pragma unroll
            for (int kk = 0; kk < 4; kk++) {
                if (kk < nglim) {
                    uint32_t vh[4];
                    LDSM4T(vh, kvb + 9216 + kk * (16 * APITCH) + lrow + dg * 32);
                    MMA16816(o[2 * dg],     pah[kk], vh[0], vh[1]);
                    MMA16816(o[2 * dg],     pal[kk], vh[0], vh[1]);
                    MMA16816(o[2 * dg + 1], pah[kk], vh[2], vh[3]);
                    MMA16816(o[2 * dg + 1], pal[kk], vh[2], vh[3]);
                }
            }
        }
    }

    // ---- finalize: normalize and write ctx hi/lo in [B,S,D] ----
    l0 += __shfl_xor_sync(0xFFFFFFFFu, l0, 1);
    l0 += __shfl_xor_sync(0xFFFFFFFFu, l0, 2);
    l1 += __shfl_xor_sync(0xFFFFFFFFu, l1, 1);
    l1 += __shfl_xor_sync(0xFFFFFFFFu, l1, 2);
    const float inv0 = 1.f / l0, inv1 = 1.f / l1;

    const size_t r0 = (size_t)b * SS + row0;
    const size_t r1 = r0 + 8;
#pragma unroll
    for (int c = 0; c < 8; c++) {
        int col = h * DK + c * 8 + 2 * l4;
        uint32_t hp, lp;
        split2(o[c][0] * inv0, o[c][1] * inv0, hp, lp);
        *(uint32_t*)(Ch + r0 * DD + col) = hp;
        *(uint32_t*)(Cl + r0 * DD + col) = lp;
        split2(o[c][2] * inv1, o[c][3] * inv1, hp, lp);
        *(uint32_t*)(Ch + r1 * DD + col) = hp;
        *(uint32_t*)(Cl + r1 * DD + col) = lp;
    }
}

// ---------------------------------------------------------------------------
// Launch
// ---------------------------------------------------------------------------
extern "C" void kernel_launch(void* const* d_in, const int* in_sizes, int n_in,
                              void* d_out, int out_size)
{
    const float* q  = (const float*)d_in[0];
    const float* k  = (const float*)d_in[1];
    const float* v  = (const float*)d_in[2];
    const float* Wq = (const float*)d_in[4];
    const float* bq = (const float*)d_in[5];
    const float* Wk = (const float*)d_in[6];
    const float* bk = (const float*)d_in[7];
    const float* Wv = (const float*)d_in[8];
    const float* bv = (const float*)d_in[9];
    const float* Wo = (const float*)d_in[10];
    const float* bo = (const float*)d_in[11];

    __half *gQh, *gQl, *gKh, *gVh, *gCh, *gCl;
    cudaGetSymbolAddress((void**)&gQh, g_Qh);
    cudaGetSymbolAddress((void**)&gQl, g_Ql);
    cudaGetSymbolAddress((void**)&gKh, g_Kh);
    cudaGetSymbolAddress((void**)&gVh, g_Vh);
    cudaGetSymbolAddress((void**)&gCh, g_Ch);
    cudaGetSymbolAddress((void**)&gCl, g_Cl);

    cudaFuncSetAttribute(qkv_gemm, cudaFuncAttributeMaxDynamicSharedMemorySize, SMEM_SZ);
    cudaFuncSetAttribute(o_gemm,   cudaFuncAttributeMaxDynamicSharedMemorySize, SMEM_SZ);
    cudaFuncSetAttribute(attn_mma, cudaFuncAttributeMaxDynamicSharedMemorySize, ATT_SMEM);

    const int n4a = MM * DD / 4;
    const int n4w = DD * DD / 4;

    // 1) batched conversions
    convert_act<<<dim3((n4a + 255) / 256, 3), 256>>>(q, k, v, n4a);
    convert_w<<<dim3((n4w + 255) / 256, 4), 256>>>(Wq, Wk, Wv, Wo, n4w);

    // 2) fused Q/K/V projections (Q pre-scaled by log2e/8, split output)
    qkv_gemm<<<dim3(DD / 128, MM / 128, 3), 256, SMEM_SZ>>>(bq, bk, bv);

    // 3) attention -> ctx hi/lo (64-row q tiles, 128-thread CTAs, 3-stage KV)
    attn_mma<<<dim3(32, HH, BB), 128, ATT_SMEM>>>(gQh, gQl, gKh, gVh, gCh, gCl);

    // 4) output projection (fp32 out)
    o_gemm<<<dim3(DD / 128, MM / 128), 256, SMEM_SZ>>>(bo, (float*)d_out);
}

// round 11
// speedup vs baseline: 10.2553x; 1.1313x over previous
#include <cuda_runtime.h>
#include <cuda_fp16.h>
#include <cstdint>
#include <math.h>

// ---------------------------------------------------------------------------
// Problem constants: B=4, S=2048, D=1024, H=16, dk=64
// ---------------------------------------------------------------------------
#define BB 4
#define SS 2048
#define DD 1024
#define HH 16
#define DK 64
#define MM (BB * SS)          // 8192

// Q pre-scale: (1/sqrt(dk)) * log2(e)  -> lets softmax use exp2f
#define QSCALE 0.1803368801111204f

// ---------------------------------------------------------------------------
// Scratch (__device__ globals; no cudaMalloc allowed)
// ---------------------------------------------------------------------------
__device__ __half g_A[3][2][(size_t)MM * DD];   // [q/k/v][hi/lo] activations
__device__ __half g_W[4][(size_t)DD * DD];      // [q/k/v/o] weight hi
__device__ __half g_Qh[(size_t)BB * HH * SS * DK];
__device__ __half g_Ql[(size_t)BB * HH * SS * DK];
__device__ __half g_Kh[(size_t)BB * HH * SS * DK];
__device__ __half g_Vh[(size_t)BB * HH * SS * DK];
__device__ __half g_Ch[(size_t)MM * DD];        // ctx hi (O-proj activation)
__device__ __half g_Cl[(size_t)MM * DD];        // ctx lo

// ---------------------------------------------------------------------------
// PTX helpers (arch-portable: ldmatrix / mma.sync / cp.async only)
// ---------------------------------------------------------------------------
__device__ __forceinline__ uint32_t smem_u32(const void* p) {
    uint32_t a;
    asm("{ .reg .u64 t; cvta.to.shared.u64 t, %1; cvt.u32.u64 %0, t; }" : "=r"(a) : "l"(p));
    return a;
}
__device__ __forceinline__ void cp16(uint32_t saddr, const void* g) {
    asm volatile("cp.async.cg.shared.global [%0], [%1], 16;" :: "r"(saddr), "l"(g) : "memory");
}
#define CP_COMMIT() asm volatile("cp.async.commit_group;" ::: "memory")
#define CP_WAIT(n)  asm volatile("cp.async.wait_group %0;" :: "n"(n) : "memory")

#define LDSM4(r, addr) asm volatile( \
    "ldmatrix.sync.aligned.m8n8.x4.shared.b16 {%0,%1,%2,%3}, [%4];" \
    : "=r"((r)[0]), "=r"((r)[1]), "=r"((r)[2]), "=r"((r)[3]) : "r"(addr))
#define LDSM4T(r, addr) asm volatile( \
    "ldmatrix.sync.aligned.m8n8.x4.trans.shared.b16 {%0,%1,%2,%3}, [%4];" \
    : "=r"((r)[0]), "=r"((r)[1]), "=r"((r)[2]), "=r"((r)[3]) : "r"(addr))

#define MMA16816(d, a, b0, b1) asm volatile( \
    "mma.sync.aligned.m16n8k16.row.col.f32.f16.f16.f32 " \
    "{%0,%1,%2,%3}, {%4,%5,%6,%7}, {%8,%9}, {%0,%1,%2,%3};" \
    : "+f"((d)[0]), "+f"((d)[1]), "+f"((d)[2]), "+f"((d)[3]) \
    : "r"((a)[0]), "r"((a)[1]), "r"((a)[2]), "r"((a)[3]), "r"(b0), "r"(b1))

// split two fp32 into packed fp16x2 (hi) and fp16x2 (lo residual)
__device__ __forceinline__ void split2(float x, float y, uint32_t& hp, uint32_t& lp) {
    __half hx = __float2half_rn(x), hy = __float2half_rn(y);
    __half2 hh = __halves2half2(hx, hy);
    __half2 ll = __halves2half2(__float2half_rn(x - __half2float(hx)),
                                __float2half_rn(y - __half2float(hy)));
    hp = *reinterpret_cast<uint32_t*>(&hh);
    lp = *reinterpret_cast<uint32_t*>(&ll);
}
__device__ __forceinline__ uint32_t pack_hi(float x, float y) {
    __half2 hh = __halves2half2(__float2half_rn(x), __float2half_rn(y));
    return *reinterpret_cast<uint32_t*>(&hh);
}

// ---------------------------------------------------------------------------
// Batched conversions
// ---------------------------------------------------------------------------
__global__ __launch_bounds__(256)
void convert_act(const float* __restrict__ x0, const float* __restrict__ x1,
                 const float* __restrict__ x2, int n4)
{
    int i = blockIdx.x * blockDim.x + threadIdx.x;
    if (i >= n4) return;
    int t = blockIdx.y;
    const float* x = (t == 0) ? x0 : (t == 1) ? x1 : x2;
    __half* hi = g_A[t][0];
    __half* lo = g_A[t][1];
    float4 v = ((const float4*)x)[i];
    uint32_t h0, l0, h1, l1;
    split2(v.x, v.y, h0, l0);
    split2(v.z, v.w, h1, l1);
    ((uint32_t*)hi)[2*i]   = h0;
    ((uint32_t*)hi)[2*i+1] = h1;
    ((uint32_t*)lo)[2*i]   = l0;
    ((uint32_t*)lo)[2*i+1] = l1;
}

__global__ __launch_bounds__(256)
void convert_w(const float* __restrict__ w0, const float* __restrict__ w1,
               const float* __restrict__ w2, const float* __restrict__ w3, int n4)
{
    int i = blockIdx.x * blockDim.x + threadIdx.x;
    if (i >= n4) return;
    int t = blockIdx.y;
    const float* x = (t == 0) ? w0 : (t == 1) ? w1 : (t == 2) ? w2 : w3;
    __half* hi = g_W[t];
    float4 v = ((const float4*)x)[i];
    ((uint32_t*)hi)[2*i]   = pack_hi(v.x, v.y);
    ((uint32_t*)hi)[2*i+1] = pack_hi(v.z, v.w);
}

// ---------------------------------------------------------------------------
// HMMA GEMM body. SPLITA=true : out = (Ah+Al) @ Wh  (2-pass)
//                 SPLITA=false: out =  Ah      @ Wh  (1-pass)
// CTA 128x128, 8 warps (4M x 2N), KC=32, 3-stage cp.async pipeline.
// ---------------------------------------------------------------------------
#define KC 32
#define PA_B 80
#define PB_B 272
#define A_BYTES (128 * PA_B)    // 10240
#define B_BYTES (KC * PB_B)     // 8704
#define OFF_AH 0
#define OFF_AL A_BYTES
#define OFF_BH (2 * A_BYTES)
#define STAGE (2 * A_BYTES + B_BYTES)   // 29184
#define NSTAGES 3
#define SMEM_SZ (NSTAGES * STAGE)       // 87552

template<bool SPLITA>
__device__ __forceinline__
void gemm_body(const __half* __restrict__ Ah,
               const __half* __restrict__ Al,
               const __half* __restrict__ Wh,
               const float* __restrict__ bias,
               float* __restrict__ outF,
               __half* __restrict__ outH,
               __half* __restrict__ outL,
               float scale, char* smem)
{
    const uint32_t sb = smem_u32(smem);
    const int tid = threadIdx.x;
    const int lane = tid & 31;
    const int warp = tid >> 5;
    const int warpM = warp >> 1;
    const int warpN = warp & 1;
    const int rowBase = blockIdx.y * 128;
    const int colBase = blockIdx.x * 128;

    float acc[2][8][4];
#pragma unroll
    for (int mi = 0; mi < 2; mi++)
#pragma unroll
        for (int ni = 0; ni < 8; ni++)
#pragma unroll
            for (int r = 0; r < 4; r++) acc[mi][ni][r] = 0.f;

    auto load_stage = [&](int ch, int s) {
        const int k0 = ch * KC;
        const uint32_t sbase = sb + s * STAGE;
        if (SPLITA) {
#pragma unroll
            for (int i = 0; i < 6; i++) {
                int idx = tid + i * 256;       // 0..1535
                int t = idx >> 9;              // 0:Ah 1:Al 2:Wh
                int w = idx & 511;
                if (t < 2) {
                    int r = w >> 2, c = w & 3;
                    const __half* src = (t == 0 ? Ah : Al) + (size_t)(rowBase + r) * DD + k0 + c * 8;
                    cp16(sbase + (t == 0 ? OFF_AH : OFF_AL) + r * PA_B + c * 16, src);
                } else {
                    int r = w >> 4, c = w & 15;
                    cp16(sbase + OFF_BH + r * PB_B + c * 16,
                         Wh + (size_t)(k0 + r) * DD + colBase + c * 8);
                }
            }
        } else {
#pragma unroll
            for (int i = 0; i < 4; i++) {
                int idx = tid + i * 256;       // 0..1023
                int t = idx >> 9;              // 0:Ah 1:Wh
                int w = idx & 511;
                if (t == 0) {
                    int r = w >> 2, c = w & 3;
                    cp16(sbase + OFF_AH + r * PA_B + c * 16,
                         Ah + (size_t)(rowBase + r) * DD + k0 + c * 8);
                } else {
                    int r = w >> 4, c = w & 15;
                    cp16(sbase + OFF_BH + r * PB_B + c * 16,
                         Wh + (size_t)(k0 + r) * DD + colBase + c * 8);
                }
            }
        }
        CP_COMMIT();
    };

    const int NCH = DD / KC;   // 32
    load_stage(0, 0);
    load_stage(1, 1);

    for (int ch = 0; ch < NCH; ch++) {
        CP_WAIT(1);                        // stage ch complete
        __syncthreads();                   // all warps done reading slot (ch+2)%3
        if (ch + 2 < NCH) load_stage(ch + 2, (ch + 2) % NSTAGES);

        const uint32_t stb = sb + (ch % NSTAGES) * STAGE;
#pragma unroll
        for (int kstep = 0; kstep < 2; kstep++) {
            uint32_t ah[2][4], al[2][4];
#pragma unroll
            for (int mi = 0; mi < 2; mi++) {
                uint32_t row = warpM * 32 + mi * 16 + (lane & 15);
                uint32_t ad = stb + OFF_AH + row * PA_B + kstep * 32 + (lane >> 4) * 16;
                LDSM4(ah[mi], ad);
                if (SPLITA) LDSM4(al[mi], ad + (OFF_AL - OFF_AH));
            }
            uint32_t bh[4][4];
#pragma unroll
            for (int ng = 0; ng < 4; ng++) {
                uint32_t krow = kstep * 16 + (lane & 15);
                uint32_t coln = warpN * 64 + ng * 16 + (lane >> 4) * 8;
                LDSM4T(bh[ng], stb + OFF_BH + krow * PB_B + coln * 2);
            }
#pragma unroll
            for (int mi = 0; mi < 2; mi++)
#pragma unroll
                for (int ni = 0; ni < 8; ni++) {
                    uint32_t b0 = bh[ni >> 1][(ni & 1) * 2];
                    uint32_t b1 = bh[ni >> 1][(ni & 1) * 2 + 1];
                    MMA16816(acc[mi][ni], ah[mi], b0, b1);
                    if (SPLITA) MMA16816(acc[mi][ni], al[mi], b0, b1);
                }
        }
    }

    // ---- epilogue ----
    const int lg = lane >> 2;
    const int l4 = lane & 3;
#pragma unroll
    for (int mi = 0; mi < 2; mi++) {
#pragma unroll
        for (int ni = 0; ni < 8; ni++) {
            int r0 = rowBase + warpM * 32 + mi * 16 + lg;
            int r1 = r0 + 8;
            int col = colBase + warpN * 64 + ni * 8 + l4 * 2;
            float v00 = (acc[mi][ni][0] + bias[col]) * scale;
            float v01 = (acc[mi][ni][1] + bias[col + 1]) * scale;
            float v10 = (acc[mi][ni][2] + bias[col]) * scale;
            float v11 = (acc[mi][ni][3] + bias[col + 1]) * scale;
            if (outF) {
                *(float2*)(outF + (size_t)r0 * DD + col) = make_float2(v00, v01);
                *(float2*)(outF + (size_t)r1 * DD + col) = make_float2(v10, v11);
            } else {
                int h = col >> 6, dd = col & (DK - 1);
                int b0r = r0 >> 11, s0 = r0 & (SS - 1);
                int b1r = r1 >> 11, s1 = r1 & (SS - 1);
                size_t o0 = (((size_t)(b0r * HH + h)) * SS + s0) * DK + dd;
                size_t o1 = (((size_t)(b1r * HH + h)) * SS + s1) * DK + dd;
                if (outL) {
                    uint32_t hp, lp;
                    split2(v00, v01, hp, lp);
                    *(uint32_t*)(outH + o0) = hp;
                    *(uint32_t*)(outL + o0) = lp;
                    split2(v10, v11, hp, lp);
                    *(uint32_t*)(outH + o1) = hp;
                    *(uint32_t*)(outL + o1) = lp;
                } else {
                    *(uint32_t*)(outH + o0) = pack_hi(v00, v01);
                    *(uint32_t*)(outH + o1) = pack_hi(v10, v11);
                }
            }
        }
    }
}

// Fused QKV projections: blockIdx.z selects q/k/v.
// Q: 2-pass (consumed as hi+lo). K/V: 1-pass (stored hi-only anyway).
__global__ __launch_bounds__(256, 2)
void qkv_gemm(const float* __restrict__ bq, const float* __restrict__ bk,
              const float* __restrict__ bv)
{
    extern __shared__ char smem[];
    const int z = blockIdx.z;
    if (z == 0)
        gemm_body<true >(g_A[0][0], g_A[0][1], g_W[0], bq, nullptr, g_Qh, g_Ql, QSCALE, smem);
    else if (z == 1)
        gemm_body<false>(g_A[1][0], nullptr,   g_W[1], bk, nullptr, g_Kh, nullptr, 1.f, smem);
    else
        gemm_body<false>(g_A[2][0], nullptr,   g_W[2], bv, nullptr, g_Vh, nullptr, 1.f, smem);
}

// Output projection: ctx hi/lo @ Wo -> fp32 out (2-pass).
__global__ __launch_bounds__(256, 2)
void o_gemm(const float* __restrict__ bo, float* __restrict__ out)
{
    extern __shared__ char smem[];
    gemm_body<true>(g_Ch, g_Cl, g_W[3], bo, out, nullptr, nullptr, 1.f, smem);
}

// ---------------------------------------------------------------------------
// HMMA causal flash attention, fp16 2-pass, exp2 softmax.
// CTA: 64 q-rows of one (b,h); 4 warps x 16 rows; 64-key tiles, 3-stage ring.
// ---------------------------------------------------------------------------
#define APITCH 144
#define ASQH 0
#define ASQL 9216                        // 64 rows * 144B
#define AKV0 18432
#define AKSTAGE 18432                    // Kh(9216) Vh(9216)
#define AKV_ST 3
#define ATT_SMEM (AKV0 + AKV_ST * AKSTAGE)   // 73728

__global__ __launch_bounds__(128)
void attn_mma(const __half* __restrict__ Qh, const __half* __restrict__ Ql,
              const __half* __restrict__ Kh, const __half* __restrict__ Vh,
              __half* __restrict__ Ch, __half* __restrict__ Cl)
{
    extern __shared__ char smem[];
    const uint32_t sb = smem_u32(smem);
    const int tid = threadIdx.x;
    const int lane = tid & 31;
    const int warp = tid >> 5;          // 0..3
    const int lg = lane >> 2;
    const int l4 = lane & 3;
    const uint32_t lrow = (uint32_t)(lane & 15) * APITCH + (uint32_t)(lane >> 4) * 16;

    const int qt = 31 - blockIdx.x;     // 64-row q tile, heavy first
    const int h  = blockIdx.y;
    const int b  = blockIdx.z;
    const size_t bhoff = (size_t)(b * HH + h) * SS * DK;

    // --- stage Q (hi+lo): 2 mats x 64 rows x 8 chunks = 1024 chunks ---
#pragma unroll
    for (int i = 0; i < 8; i++) {
        int idx = tid + i * 128;
        int mat = idx >> 9;            // 0:Qh 1:Ql
        int w = idx & 511;
        int r = w >> 3, c = w & 7;
        const __half* src = (mat ? Ql : Qh) + bhoff + (size_t)(qt * 64 + r) * DK + c * 8;
        cp16(sb + mat * ASQL + r * APITCH + c * 16, src);
    }
    CP_COMMIT();

    auto kv_load = [&](int jt, int st) {
        uint32_t base = sb + AKV0 + st * AKSTAGE;
        size_t koff = bhoff + (size_t)jt * 64 * DK;
#pragma unroll
        for (int i = 0; i < 8; i++) {
            int idx = tid + i * 128;
            int mat = idx >> 9;        // 0:Kh 1:Vh
            int w = idx & 511;
            int r = w >> 3, c = w & 7;
            const __half* mp = mat ? Vh : Kh;
            cp16(base + mat * 9216 + r * APITCH + c * 16, mp + koff + (size_t)r * DK + c * 8);
        }
        CP_COMMIT();
    };

    const int ntiles = qt + 1;
    kv_load(0, 0);
    if (ntiles > 1) kv_load(1, 1);
    CP_WAIT(1);                  // Q + kv0 done (kv1 may be pending)
    __syncthreads();

    // --- Q fragments in registers ---
    uint32_t qah[4][4], qal[4][4];
#pragma unroll
    for (int kk = 0; kk < 4; kk++) {
        uint32_t ad = sb + ASQH + warp * (16 * APITCH) + lrow + kk * 32;
        LDSM4(qah[kk], ad);
        LDSM4(qal[kk], ad + ASQL);
    }

    float o[8][4];
#pragma unroll
    for (int c = 0; c < 8; c++)
#pragma unroll
        for (int r = 0; r < 4; r++) o[c][r] = 0.f;
    float m0 = -1e30f, m1 = -1e30f, l0 = 0.f, l1 = 0.f;

    const int row0 = qt * 64 + warp * 16 + lg;

    for (int jt = 0; jt < ntiles; jt++) {
        if (jt + 1 < ntiles) { CP_WAIT(1); } else { CP_WAIT(0); }
        __syncthreads();
        if (jt + 2 < ntiles) kv_load(jt + 2, (jt + 2) % AKV_ST);

        const uint32_t kvb = sb + AKV0 + (jt % AKV_ST) * AKSTAGE;
        const bool diag = (jt == qt);
        const int nglim = diag ? (warp + 1) : 4;

        // ---- scores: S = (Qh+Ql) Kh ----
        float s[8][4];
#pragma unroll
        for (int c = 0; c < 8; c++)
#pragma unroll
            for (int r = 0; r < 4; r++) s[c][r] = 0.f;

#pragma unroll
        for (int ng = 0; ng < 4; ng++) {
            if (ng < nglim) {
#pragma unroll
                for (int kk = 0; kk < 4; kk++) {
                    uint32_t kh[4];
                    LDSM4(kh, kvb + ng * (16 * APITCH) + lrow + kk * 32);
                    MMA16816(s[2 * ng],     qah[kk], kh[0], kh[2]);
                    MMA16816(s[2 * ng],     qal[kk], kh[0], kh[2]);
                    MMA16816(s[2 * ng + 1], qah[kk], kh[1], kh[3]);
                    MMA16816(s[2 * ng + 1], qal[kk], kh[1], kh[3]);
                }
            }
        }

        // ---- causal mask (diagonal tile only) ----
        if (diag) {
#pragma unroll
            for (int c = 0; c < 8; c++) {
                int col = jt * 64 + c * 8 + 2 * l4;
                if (col > row0)         s[c][0] = -1e30f;
                if (col + 1 > row0)     s[c][1] = -1e30f;
                if (col > row0 + 8)     s[c][2] = -1e30f;
                if (col + 1 > row0 + 8) s[c][3] = -1e30f;
            }
        }

        // ---- online softmax (base-2 domain) ----
        float mx0 = -1e30f, mx1 = -1e30f;
#pragma unroll
        for (int c = 0; c < 8; c++) {
            mx0 = fmaxf(mx0, fmaxf(s[c][0], s[c][1]));
            mx1 = fmaxf(mx1, fmaxf(s[c][2], s[c][3]));
        }
        mx0 = fmaxf(mx0, __shfl_xor_sync(0xFFFFFFFFu, mx0, 1));
        mx0 = fmaxf(mx0, __shfl_xor_sync(0xFFFFFFFFu, mx0, 2));
        mx1 = fmaxf(mx1, __shfl_xor_sync(0xFFFFFFFFu, mx1, 1));
        mx1 = fmaxf(mx1, __shfl_xor_sync(0xFFFFFFFFu, mx1, 2));
        float mn0 = fmaxf(m0, mx0), mn1 = fmaxf(m1, mx1);
        float sc0 = exp2f(m0 - mn0), sc1 = exp2f(m1 - mn1);
        m0 = mn0; m1 = mn1;
        l0 *= sc0; l1 *= sc1;
#pragma unroll
        for (int c = 0; c < 8; c++) {
            o[c][0] *= sc0; o[c][1] *= sc0;
            o[c][2] *= sc1; o[c][3] *= sc1;
        }
#pragma unroll
        for (int c = 0; c < 8; c++) {
            s[c][0] = exp2f(s[c][0] - mn0);
            s[c][1] = exp2f(s[c][1] - mn0);
            s[c][2] = exp2f(s[c][2] - mn1);
            s[c][3] = exp2f(s[c][3] - mn1);
            l0 += s[c][0] + s[c][1];
            l1 += s[c][2] + s[c][3];
        }

        // ---- P fragments (hi/lo) ----
        uint32_t pah[4][4], pal[4][4];
#pragma unroll
        for (int kk = 0; kk < 4; kk++) {
            if (kk < nglim) {
                split2(s[2 * kk][0],     s[2 * kk][1],     pah[kk][0], pal[kk][0]);
                split2(s[2 * kk][2],     s[2 * kk][3],     pah[kk][1], pal[kk][1]);
                split2(s[2 * kk + 1][0], s[2 * kk + 1][1], pah[kk][2], pal[kk][2]);
                split2(s[2 * kk + 1][2], s[2 * kk + 1][3], pah[kk][3], pal[kk][3]);
            }
        }

        // ---- O += (Ph+Pl) Vh ----
#pragma unroll
        for (int dg = 0; dg < 4; dg++) {
#pragma unroll
            for (int kk = 0; kk < 4; kk++) {
                if (kk < nglim) {
                    uint32_t vh[4];
                    LDSM4T(vh, kvb + 9216 + kk * (16 * APITCH) + lrow + dg * 32);
                    MMA16816(o[2 * dg],     pah[kk], vh[0], vh[1]);
                    MMA16816(o[2 * dg],     pal[kk], vh[0], vh[1]);
                    MMA16816(o[2 * dg + 1], pah[kk], vh[2], vh[3]);
                    MMA16816(o[2 * dg + 1], pal[kk], vh[2], vh[3]);
                }
            }
        }
    }

    // ---- finalize: normalize and write ctx hi/lo in [B,S,D] ----
    l0 += __shfl_xor_sync(0xFFFFFFFFu, l0, 1);
    l0 += __shfl_xor_sync(0xFFFFFFFFu, l0, 2);
    l1 += __shfl_xor_sync(0xFFFFFFFFu, l1, 1);
    l1 += __shfl_xor_sync(0xFFFFFFFFu, l1, 2);
    const float inv0 = 1.f / l0, inv1 = 1.f / l1;

    const size_t r0 = (size_t)b * SS + row0;
    const size_t r1 = r0 + 8;
#pragma unroll
    for (int c = 0; c < 8; c++) {
        int col = h * DK + c * 8 + 2 * l4;
        uint32_t hp, lp;
        split2(o[c][0] * inv0, o[c][1] * inv0, hp, lp);
        *(uint32_t*)(Ch + r0 * DD + col) = hp;
        *(uint32_t*)(Cl + r0 * DD + col) = lp;
        split2(o[c][2] * inv1, o[c][3] * inv1, hp, lp);
        *(uint32_t*)(Ch + r1 * DD + col) = hp;
        *(uint32_t*)(Cl + r1 * DD + col) = lp;
    }
}

// ---------------------------------------------------------------------------
// Launch
// ---------------------------------------------------------------------------
extern "C" void kernel_launch(void* const* d_in, const int* in_sizes, int n_in,
                              void* d_out, int out_size)
{
    const float* q  = (const float*)d_in[0];
    const float* k  = (const float*)d_in[1];
    const float* v  = (const float*)d_in[2];
    const float* Wq = (const float*)d_in[4];
    const float* bq = (const float*)d_in[5];
    const float* Wk = (const float*)d_in[6];
    const float* bk = (const float*)d_in[7];
    const float* Wv = (const float*)d_in[8];
    const float* bv = (const float*)d_in[9];
    const float* Wo = (const float*)d_in[10];
    const float* bo = (const float*)d_in[11];

    __half *gQh, *gQl, *gKh, *gVh, *gCh, *gCl;
    cudaGetSymbolAddress((void**)&gQh, g_Qh);
    cudaGetSymbolAddress((void**)&gQl, g_Ql);
    cudaGetSymbolAddress((void**)&gKh, g_Kh);
    cudaGetSymbolAddress((void**)&gVh, g_Vh);
    cudaGetSymbolAddress((void**)&gCh, g_Ch);
    cudaGetSymbolAddress((void**)&gCl, g_Cl);

    cudaFuncSetAttribute(qkv_gemm, cudaFuncAttributeMaxDynamicSharedMemorySize, SMEM_SZ);
    cudaFuncSetAttribute(o_gemm,   cudaFuncAttributeMaxDynamicSharedMemorySize, SMEM_SZ);
    cudaFuncSetAttribute(attn_mma, cudaFuncAttributeMaxDynamicSharedMemorySize, ATT_SMEM);

    const int n4a = MM * DD / 4;
    const int n4w = DD * DD / 4;

    // 1) batched conversions
    convert_act<<<dim3((n4a + 255) / 256, 3), 256>>>(q, k, v, n4a);
    convert_w<<<dim3((n4w + 255) / 256, 4), 256>>>(Wq, Wk, Wv, Wo, n4w);

    // 2) fused Q/K/V projections (Q 2-pass + pre-scale; K/V 1-pass)
    qkv_gemm<<<dim3(DD / 128, MM / 128, 3), 256, SMEM_SZ>>>(bq, bk, bv);

    // 3) attention -> ctx hi/lo
    attn_mma<<<dim3(32, HH, BB), 128, ATT_SMEM>>>(gQh, gQl, gKh, gVh, gCh, gCl);

    // 4) output projection (fp32 out)
    o_gemm<<<dim3(DD / 128, MM / 128), 256, SMEM_SZ>>>(bo, (float*)d_out);
}

// round 12
// speedup vs baseline: 12.0390x; 1.1739x over previous
#include <cuda_runtime.h>
#include <cuda_fp16.h>
#include <cstdint>
#include <math.h>

// ---------------------------------------------------------------------------
// Problem constants: B=4, S=2048, D=1024, H=16, dk=64
// ---------------------------------------------------------------------------
#define BB 4
#define SS 2048
#define DD 1024
#define HH 16
#define DK 64
#define MM (BB * SS)          // 8192

// Q pre-scale: (1/sqrt(dk)) * log2(e)  -> lets softmax use exp2f
#define QSCALE 0.1803368801111204f

// ---------------------------------------------------------------------------
// Scratch (__device__ globals; no cudaMalloc allowed)
// ---------------------------------------------------------------------------
__device__ __half g_A[3][2][(size_t)MM * DD];   // [q/k/v][hi/lo] activations
__device__ __half g_W[4][(size_t)DD * DD];      // [q/k/v/o] weight hi
__device__ __half g_Qh[(size_t)BB * HH * SS * DK];
__device__ __half g_Ql[(size_t)BB * HH * SS * DK];
__device__ __half g_Kh[(size_t)BB * HH * SS * DK];
__device__ __half g_Vh[(size_t)BB * HH * SS * DK];
__device__ __half g_Ch[(size_t)MM * DD];        // ctx hi (O-proj activation)

// ---------------------------------------------------------------------------
// PTX helpers (arch-portable: ldmatrix / mma.sync / cp.async only)
// ---------------------------------------------------------------------------
__device__ __forceinline__ uint32_t smem_u32(const void* p) {
    uint32_t a;
    asm("{ .reg .u64 t; cvta.to.shared.u64 t, %1; cvt.u32.u64 %0, t; }" : "=r"(a) : "l"(p));
    return a;
}
__device__ __forceinline__ void cp16(uint32_t saddr, const void* g) {
    asm volatile("cp.async.cg.shared.global [%0], [%1], 16;" :: "r"(saddr), "l"(g) : "memory");
}
#define CP_COMMIT() asm volatile("cp.async.commit_group;" ::: "memory")
#define CP_WAIT(n)  asm volatile("cp.async.wait_group %0;" :: "n"(n) : "memory")

#define LDSM4(r, addr) asm volatile( \
    "ldmatrix.sync.aligned.m8n8.x4.shared.b16 {%0,%1,%2,%3}, [%4];" \
    : "=r"((r)[0]), "=r"((r)[1]), "=r"((r)[2]), "=r"((r)[3]) : "r"(addr))
#define LDSM4T(r, addr) asm volatile( \
    "ldmatrix.sync.aligned.m8n8.x4.trans.shared.b16 {%0,%1,%2,%3}, [%4];" \
    : "=r"((r)[0]), "=r"((r)[1]), "=r"((r)[2]), "=r"((r)[3]) : "r"(addr))

#define MMA16816(d, a, b0, b1) asm volatile( \
    "mma.sync.aligned.m16n8k16.row.col.f32.f16.f16.f32 " \
    "{%0,%1,%2,%3}, {%4,%5,%6,%7}, {%8,%9}, {%0,%1,%2,%3};" \
    : "+f"((d)[0]), "+f"((d)[1]), "+f"((d)[2]), "+f"((d)[3]) \
    : "r"((a)[0]), "r"((a)[1]), "r"((a)[2]), "r"((a)[3]), "r"(b0), "r"(b1))

// split two fp32 into packed fp16x2 (hi) and fp16x2 (lo residual)
__device__ __forceinline__ void split2(float x, float y, uint32_t& hp, uint32_t& lp) {
    __half hx = __float2half_rn(x), hy = __float2half_rn(y);
    __half2 hh = __halves2half2(hx, hy);
    __half2 ll = __halves2half2(__float2half_rn(x - __half2float(hx)),
                                __float2half_rn(y - __half2float(hy)));
    hp = *reinterpret_cast<uint32_t*>(&hh);
    lp = *reinterpret_cast<uint32_t*>(&ll);
}
__device__ __forceinline__ uint32_t pack_hi(float x, float y) {
    __half2 hh = __halves2half2(__float2half_rn(x), __float2half_rn(y));
    return *reinterpret_cast<uint32_t*>(&hh);
}

// ---------------------------------------------------------------------------
// Batched conversions
// ---------------------------------------------------------------------------
__global__ __launch_bounds__(256)
void convert_act(const float* __restrict__ x0, const float* __restrict__ x1,
                 const float* __restrict__ x2, int n4)
{
    int i = blockIdx.x * blockDim.x + threadIdx.x;
    if (i >= n4) return;
    int t = blockIdx.y;
    const float* x = (t == 0) ? x0 : (t == 1) ? x1 : x2;
    __half* hi = g_A[t][0];
    __half* lo = g_A[t][1];
    float4 v = ((const float4*)x)[i];
    uint32_t h0, l0, h1, l1;
    split2(v.x, v.y, h0, l0);
    split2(v.z, v.w, h1, l1);
    ((uint32_t*)hi)[2*i]   = h0;
    ((uint32_t*)hi)[2*i+1] = h1;
    ((uint32_t*)lo)[2*i]   = l0;
    ((uint32_t*)lo)[2*i+1] = l1;
}

__global__ __launch_bounds__(256)
void convert_w(const float* __restrict__ w0, const float* __restrict__ w1,
               const float* __restrict__ w2, const float* __restrict__ w3, int n4)
{
    int i = blockIdx.x * blockDim.x + threadIdx.x;
    if (i >= n4) return;
    int t = blockIdx.y;
    const float* x = (t == 0) ? w0 : (t == 1) ? w1 : (t == 2) ? w2 : w3;
    __half* hi = g_W[t];
    float4 v = ((const float4*)x)[i];
    ((uint32_t*)hi)[2*i]   = pack_hi(v.x, v.y);
    ((uint32_t*)hi)[2*i+1] = pack_hi(v.z, v.w);
}

// ---------------------------------------------------------------------------
// HMMA GEMM body. SPLITA=true : out = (Ah+Al) @ Wh  (2-pass)
//                 SPLITA=false: out =  Ah      @ Wh  (1-pass)
// CTA 128x128, 8 warps (4M x 2N), KC=32, 3-stage cp.async pipeline.
// ---------------------------------------------------------------------------
#define KC 32
#define PA_B 80
#define PB_B 272
#define A_BYTES (128 * PA_B)    // 10240
#define B_BYTES (KC * PB_B)     // 8704
#define OFF_AH 0
#define OFF_AL A_BYTES
#define OFF_BH (2 * A_BYTES)
#define STAGE (2 * A_BYTES + B_BYTES)   // 29184
#define NSTAGES 3
#define SMEM_SZ (NSTAGES * STAGE)       // 87552

template<bool SPLITA>
__device__ __forceinline__
void gemm_body(const __half* __restrict__ Ah,
               const __half* __restrict__ Al,
               const __half* __restrict__ Wh,
               const float* __restrict__ bias,
               float* __restrict__ outF,
               __half* __restrict__ outH,
               __half* __restrict__ outL,
               float scale, char* smem)
{
    const uint32_t sb = smem_u32(smem);
    const int tid = threadIdx.x;
    const int lane = tid & 31;
    const int warp = tid >> 5;
    const int warpM = warp >> 1;
    const int warpN = warp & 1;
    const int rowBase = blockIdx.y * 128;
    const int colBase = blockIdx.x * 128;

    float acc[2][8][4];
#pragma unroll
    for (int mi = 0; mi < 2; mi++)
#pragma unroll
        for (int ni = 0; ni < 8; ni++)
#pragma unroll
            for (int r = 0; r < 4; r++) acc[mi][ni][r] = 0.f;

    auto load_stage = [&](int ch, int s) {
        const int k0 = ch * KC;
        const uint32_t sbase = sb + s * STAGE;
        if (SPLITA) {
#pragma unroll
            for (int i = 0; i < 6; i++) {
                int idx = tid + i * 256;       // 0..1535
                int t = idx >> 9;              // 0:Ah 1:Al 2:Wh
                int w = idx & 511;
                if (t < 2) {
                    int r = w >> 2, c = w & 3;
                    const __half* src = (t == 0 ? Ah : Al) + (size_t)(rowBase + r) * DD + k0 + c * 8;
                    cp16(sbase + (t == 0 ? OFF_AH : OFF_AL) + r * PA_B + c * 16, src);
                } else {
                    int r = w >> 4, c = w & 15;
                    cp16(sbase + OFF_BH + r * PB_B + c * 16,
                         Wh + (size_t)(k0 + r) * DD + colBase + c * 8);
                }
            }
        } else {
#pragma unroll
            for (int i = 0; i < 4; i++) {
                int idx = tid + i * 256;       // 0..1023
                int t = idx >> 9;              // 0:Ah 1:Wh
                int w = idx & 511;
                if (t == 0) {
                    int r = w >> 2, c = w & 3;
                    cp16(sbase + OFF_AH + r * PA_B + c * 16,
                         Ah + (size_t)(rowBase + r) * DD + k0 + c * 8);
                } else {
                    int r = w >> 4, c = w & 15;
                    cp16(sbase + OFF_BH + r * PB_B + c * 16,
                         Wh + (size_t)(k0 + r) * DD + colBase + c * 8);
                }
            }
        }
        CP_COMMIT();
    };

    const int NCH = DD / KC;   // 32
    load_stage(0, 0);
    load_stage(1, 1);

    for (int ch = 0; ch < NCH; ch++) {
        CP_WAIT(1);                        // stage ch complete
        __syncthreads();                   // all warps done reading slot (ch+2)%3
        if (ch + 2 < NCH) load_stage(ch + 2, (ch + 2) % NSTAGES);

        const uint32_t stb = sb + (ch % NSTAGES) * STAGE;
#pragma unroll
        for (int kstep = 0; kstep < 2; kstep++) {
            uint32_t ah[2][4], al[2][4];
#pragma unroll
            for (int mi = 0; mi < 2; mi++) {
                uint32_t row = warpM * 32 + mi * 16 + (lane & 15);
                uint32_t ad = stb + OFF_AH + row * PA_B + kstep * 32 + (lane >> 4) * 16;
                LDSM4(ah[mi], ad);
                if (SPLITA) LDSM4(al[mi], ad + (OFF_AL - OFF_AH));
            }
            uint32_t bh[4][4];
#pragma unroll
            for (int ng = 0; ng < 4; ng++) {
                uint32_t krow = kstep * 16 + (lane & 15);
                uint32_t coln = warpN * 64 + ng * 16 + (lane >> 4) * 8;
                LDSM4T(bh[ng], stb + OFF_BH + krow * PB_B + coln * 2);
            }
#pragma unroll
            for (int mi = 0; mi < 2; mi++)
#pragma unroll
                for (int ni = 0; ni < 8; ni++) {
                    uint32_t b0 = bh[ni >> 1][(ni & 1) * 2];
                    uint32_t b1 = bh[ni >> 1][(ni & 1) * 2 + 1];
                    MMA16816(acc[mi][ni], ah[mi], b0, b1);
                    if (SPLITA) MMA16816(acc[mi][ni], al[mi], b0, b1);
                }
        }
    }

    // ---- epilogue ----
    const int lg = lane >> 2;
    const int l4 = lane & 3;
#pragma unroll
    for (int mi = 0; mi < 2; mi++) {
#pragma unroll
        for (int ni = 0; ni < 8; ni++) {
            int r0 = rowBase + warpM * 32 + mi * 16 + lg;
            int r1 = r0 + 8;
            int col = colBase + warpN * 64 + ni * 8 + l4 * 2;
            float v00 = (acc[mi][ni][0] + bias[col]) * scale;
            float v01 = (acc[mi][ni][1] + bias[col + 1]) * scale;
            float v10 = (acc[mi][ni][2] + bias[col]) * scale;
            float v11 = (acc[mi][ni][3] + bias[col + 1]) * scale;
            if (outF) {
                *(float2*)(outF + (size_t)r0 * DD + col) = make_float2(v00, v01);
                *(float2*)(outF + (size_t)r1 * DD + col) = make_float2(v10, v11);
            } else {
                int h = col >> 6, dd = col & (DK - 1);
                int b0r = r0 >> 11, s0 = r0 & (SS - 1);
                int b1r = r1 >> 11, s1 = r1 & (SS - 1);
                size_t o0 = (((size_t)(b0r * HH + h)) * SS + s0) * DK + dd;
                size_t o1 = (((size_t)(b1r * HH + h)) * SS + s1) * DK + dd;
                if (outL) {
                    uint32_t hp, lp;
                    split2(v00, v01, hp, lp);
                    *(uint32_t*)(outH + o0) = hp;
                    *(uint32_t*)(outL + o0) = lp;
                    split2(v10, v11, hp, lp);
                    *(uint32_t*)(outH + o1) = hp;
                    *(uint32_t*)(outL + o1) = lp;
                } else {
                    *(uint32_t*)(outH + o0) = pack_hi(v00, v01);
                    *(uint32_t*)(outH + o1) = pack_hi(v10, v11);
                }
            }
        }
    }
}

// Fused QKV projections: blockIdx.z selects q/k/v.
// Q: 2-pass (consumed as hi+lo). K/V: 1-pass (stored hi-only anyway).
__global__ __launch_bounds__(256, 2)
void qkv_gemm(const float* __restrict__ bq, const float* __restrict__ bk,
              const float* __restrict__ bv)
{
    extern __shared__ char smem[];
    const int z = blockIdx.z;
    if (z == 0)
        gemm_body<true >(g_A[0][0], g_A[0][1], g_W[0], bq, nullptr, g_Qh, g_Ql, QSCALE, smem);
    else if (z == 1)
        gemm_body<false>(g_A[1][0], nullptr,   g_W[1], bk, nullptr, g_Kh, nullptr, 1.f, smem);
    else
        gemm_body<false>(g_A[2][0], nullptr,   g_W[2], bv, nullptr, g_Vh, nullptr, 1.f, smem);
}

// Output projection: ctx hi @ Wo -> fp32 out (1-pass).
__global__ __launch_bounds__(256, 2)
void o_gemm(const float* __restrict__ bo, float* __restrict__ out)
{
    extern __shared__ char smem[];
    gemm_body<false>(g_Ch, nullptr, g_W[3], bo, out, nullptr, nullptr, 1.f, smem);
}

// ---------------------------------------------------------------------------
// HMMA causal flash attention. QK: 2-pass (Qh+Ql)Kh. PV: 1-pass Ph Vh.
// exp2 softmax; ctx written hi-only. 64-row q tiles, 3-stage KV ring.
// ---------------------------------------------------------------------------
#define APITCH 144
#define ASQH 0
#define ASQL 9216                        // 64 rows * 144B
#define AKV0 18432
#define AKSTAGE 18432                    // Kh(9216) Vh(9216)
#define AKV_ST 3
#define ATT_SMEM (AKV0 + AKV_ST * AKSTAGE)   // 73728

__global__ __launch_bounds__(128)
void attn_mma(const __half* __restrict__ Qh, const __half* __restrict__ Ql,
              const __half* __restrict__ Kh, const __half* __restrict__ Vh,
              __half* __restrict__ Ch)
{
    extern __shared__ char smem[];
    const uint32_t sb = smem_u32(smem);
    const int tid = threadIdx.x;
    const int lane = tid & 31;
    const int warp = tid >> 5;          // 0..3
    const int lg = lane >> 2;
    const int l4 = lane & 3;
    const uint32_t lrow = (uint32_t)(lane & 15) * APITCH + (uint32_t)(lane >> 4) * 16;

    const int qt = 31 - blockIdx.x;     // 64-row q tile, heavy first
    const int h  = blockIdx.y;
    const int b  = blockIdx.z;
    const size_t bhoff = (size_t)(b * HH + h) * SS * DK;

    // --- stage Q (hi+lo): 2 mats x 64 rows x 8 chunks = 1024 chunks ---
#pragma unroll
    for (int i = 0; i < 8; i++) {
        int idx = tid + i * 128;
        int mat = idx >> 9;            // 0:Qh 1:Ql
        int w = idx & 511;
        int r = w >> 3, c = w & 7;
        const __half* src = (mat ? Ql : Qh) + bhoff + (size_t)(qt * 64 + r) * DK + c * 8;
        cp16(sb + mat * ASQL + r * APITCH + c * 16, src);
    }
    CP_COMMIT();

    auto kv_load = [&](int jt, int st) {
        uint32_t base = sb + AKV0 + st * AKSTAGE;
        size_t koff = bhoff + (size_t)jt * 64 * DK;
#pragma unroll
        for (int i = 0; i < 8; i++) {
            int idx = tid + i * 128;
            int mat = idx >> 9;        // 0:Kh 1:Vh
            int w = idx & 511;
            int r = w >> 3, c = w & 7;
            const __half* mp = mat ? Vh : Kh;
            cp16(base + mat * 9216 + r * APITCH + c * 16, mp + koff + (size_t)r * DK + c * 8);
        }
        CP_COMMIT();
    };

    const int ntiles = qt + 1;
    kv_load(0, 0);
    if (ntiles > 1) kv_load(1, 1);
    CP_WAIT(1);                  // Q + kv0 done (kv1 may be pending)
    __syncthreads();

    // --- Q fragments in registers ---
    uint32_t qah[4][4], qal[4][4];
#pragma unroll
    for (int kk = 0; kk < 4; kk++) {
        uint32_t ad = sb + ASQH + warp * (16 * APITCH) + lrow + kk * 32;
        LDSM4(qah[kk], ad);
        LDSM4(qal[kk], ad + ASQL);
    }

    float o[8][4];
#pragma unroll
    for (int c = 0; c < 8; c++)
#pragma unroll
        for (int r = 0; r < 4; r++) o[c][r] = 0.f;
    float m0 = -1e30f, m1 = -1e30f, l0 = 0.f, l1 = 0.f;

    const int row0 = qt * 64 + warp * 16 + lg;

    for (int jt = 0; jt < ntiles; jt++) {
        if (jt + 1 < ntiles) { CP_WAIT(1); } else { CP_WAIT(0); }
        __syncthreads();
        if (jt + 2 < ntiles) kv_load(jt + 2, (jt + 2) % AKV_ST);

        const uint32_t kvb = sb + AKV0 + (jt % AKV_ST) * AKSTAGE;
        const bool diag = (jt == qt);
        const int nglim = diag ? (warp + 1) : 4;

        // ---- scores: S = (Qh+Ql) Kh ----
        float s[8][4];
#pragma unroll
        for (int c = 0; c < 8; c++)
#pragma unroll
            for (int r = 0; r < 4; r++) s[c][r] = 0.f;

#pragma unroll
        for (int ng = 0; ng < 4; ng++) {
            if (ng < nglim) {
#pragma unroll
                for (int kk = 0; kk < 4; kk++) {
                    uint32_t kh[4];
                    LDSM4(kh, kvb + ng * (16 * APITCH) + lrow + kk * 32);
                    MMA16816(s[2 * ng],     qah[kk], kh[0], kh[2]);
                    MMA16816(s[2 * ng],     qal[kk], kh[0], kh[2]);
                    MMA16816(s[2 * ng + 1], qah[kk], kh[1], kh[3]);
                    MMA16816(s[2 * ng + 1], qal[kk], kh[1], kh[3]);
                }
            }
        }

        // ---- causal mask (diagonal tile only) ----
        if (diag) {
#pragma unroll
            for (int c = 0; c < 8; c++) {
                int col = jt * 64 + c * 8 + 2 * l4;
                if (col > row0)         s[c][0] = -1e30f;
                if (col + 1 > row0)     s[c][1] = -1e30f;
                if (col > row0 + 8)     s[c][2] = -1e30f;
                if (col + 1 > row0 + 8) s[c][3] = -1e30f;
            }
        }

        // ---- online softmax (base-2 domain) ----
        float mx0 = -1e30f, mx1 = -1e30f;
#pragma unroll
        for (int c = 0; c < 8; c++) {
            mx0 = fmaxf(mx0, fmaxf(s[c][0], s[c][1]));
            mx1 = fmaxf(mx1, fmaxf(s[c][2], s[c][3]));
        }
        mx0 = fmaxf(mx0, __shfl_xor_sync(0xFFFFFFFFu, mx0, 1));
        mx0 = fmaxf(mx0, __shfl_xor_sync(0xFFFFFFFFu, mx0, 2));
        mx1 = fmaxf(mx1, __shfl_xor_sync(0xFFFFFFFFu, mx1, 1));
        mx1 = fmaxf(mx1, __shfl_xor_sync(0xFFFFFFFFu, mx1, 2));
        float mn0 = fmaxf(m0, mx0), mn1 = fmaxf(m1, mx1);
        float sc0 = exp2f(m0 - mn0), sc1 = exp2f(m1 - mn1);
        m0 = mn0; m1 = mn1;
        l0 *= sc0; l1 *= sc1;
#pragma unroll
        for (int c = 0; c < 8; c++) {
            o[c][0] *= sc0; o[c][1] *= sc0;
            o[c][2] *= sc1; o[c][3] *= sc1;
        }
#pragma unroll
        for (int c = 0; c < 8; c++) {
            s[c][0] = exp2f(s[c][0] - mn0);
            s[c][1] = exp2f(s[c][1] - mn0);
            s[c][2] = exp2f(s[c][2] - mn1);
            s[c][3] = exp2f(s[c][3] - mn1);
            l0 += s[c][0] + s[c][1];
            l1 += s[c][2] + s[c][3];
        }

        // ---- P fragments (hi only) ----
        uint32_t pah[4][4];
#pragma unroll
        for (int kk = 0; kk < 4; kk++) {
            if (kk < nglim) {
                pah[kk][0] = pack_hi(s[2 * kk][0],     s[2 * kk][1]);
                pah[kk][1] = pack_hi(s[2 * kk][2],     s[2 * kk][3]);
                pah[kk][2] = pack_hi(s[2 * kk + 1][0], s[2 * kk + 1][1]);
                pah[kk][3] = pack_hi(s[2 * kk + 1][2], s[2 * kk + 1][3]);
            }
        }

        // ---- O += Ph Vh ----
#pragma unroll
        for (int dg = 0; dg < 4; dg++) {
#pragma unroll
            for (int kk = 0; kk < 4; kk++) {
                if (kk < nglim) {
                    uint32_t vh[4];
                    LDSM4T(vh, kvb + 9216 + kk * (16 * APITCH) + lrow + dg * 32);
                    MMA16816(o[2 * dg],     pah[kk], vh[0], vh[1]);
                    MMA16816(o[2 * dg + 1], pah[kk], vh[2], vh[3]);
                }
            }
        }
    }

    // ---- finalize: normalize and write ctx hi in [B,S,D] ----
    l0 += __shfl_xor_sync(0xFFFFFFFFu, l0, 1);
    l0 += __shfl_xor_sync(0xFFFFFFFFu, l0, 2);
    l1 += __shfl_xor_sync(0xFFFFFFFFu, l1, 1);
    l1 += __shfl_xor_sync(0xFFFFFFFFu, l1, 2);
    const float inv0 = 1.f / l0, inv1 = 1.f / l1;

    const size_t r0 = (size_t)b * SS + row0;
    const size_t r1 = r0 + 8;
#pragma unroll
    for (int c = 0; c < 8; c++) {
        int col = h * DK + c * 8 + 2 * l4;
        *(uint32_t*)(Ch + r0 * DD + col) = pack_hi(o[c][0] * inv0, o[c][1] * inv0);
        *(uint32_t*)(Ch + r1 * DD + col) = pack_hi(o[c][2] * inv1, o[c][3] * inv1);
    }
}

// ---------------------------------------------------------------------------
// Launch
// ---------------------------------------------------------------------------
extern "C" void kernel_launch(void* const* d_in, const int* in_sizes, int n_in,
                              void* d_out, int out_size)
{
    const float* q  = (const float*)d_in[0];
    const float* k  = (const float*)d_in[1];
    const float* v  = (const float*)d_in[2];
    const float* Wq = (const float*)d_in[4];
    const float* bq = (const float*)d_in[5];
    const float* Wk = (const float*)d_in[6];
    const float* bk = (const float*)d_in[7];
    const float* Wv = (const float*)d_in[8];
    const float* bv = (const float*)d_in[9];
    const float* Wo = (const float*)d_in[10];
    const float* bo = (const float*)d_in[11];

    __half *gQh, *gQl, *gKh, *gVh, *gCh;
    cudaGetSymbolAddress((void**)&gQh, g_Qh);
    cudaGetSymbolAddress((void**)&gQl, g_Ql);
    cudaGetSymbolAddress((void**)&gKh, g_Kh);
    cudaGetSymbolAddress((void**)&gVh, g_Vh);
    cudaGetSymbolAddress((void**)&gCh, g_Ch);

    cudaFuncSetAttribute(qkv_gemm, cudaFuncAttributeMaxDynamicSharedMemorySize, SMEM_SZ);
    cudaFuncSetAttribute(o_gemm,   cudaFuncAttributeMaxDynamicSharedMemorySize, SMEM_SZ);
    cudaFuncSetAttribute(attn_mma, cudaFuncAttributeMaxDynamicSharedMemorySize, ATT_SMEM);

    const int n4a = MM * DD / 4;
    const int n4w = DD * DD / 4;

    // 1) batched conversions
    convert_act<<<dim3((n4a + 255) / 256, 3), 256>>>(q, k, v, n4a);
    convert_w<<<dim3((n4w + 255) / 256, 4), 256>>>(Wq, Wk, Wv, Wo, n4w);

    // 2) fused Q/K/V projections (Q 2-pass + pre-scale; K/V 1-pass)
    qkv_gemm<<<dim3(DD / 128, MM / 128, 3), 256, SMEM_SZ>>>(bq, bk, bv);

    // 3) attention -> ctx hi
    attn_mma<<<dim3(32, HH, BB), 128, ATT_SMEM>>>(gQh, gQl, gKh, gVh, gCh);

    // 4) output projection (1-pass, fp32 out)
    o_gemm<<<dim3(DD / 128, MM / 128), 256, SMEM_SZ>>>(bo, (float*)d_out);
}

// round 13
// speedup vs baseline: 12.1552x; 1.0097x over previous
#include <cuda_runtime.h>
#include <cuda_fp16.h>
#include <cstdint>
#include <math.h>

// ---------------------------------------------------------------------------
// Problem constants: B=4, S=2048, D=1024, H=16, dk=64
// ---------------------------------------------------------------------------
#define BB 4
#define SS 2048
#define DD 1024
#define HH 16
#define DK 64
#define MM (BB * SS)          // 8192

// Q pre-scale: (1/sqrt(dk)) * log2(e)  -> lets softmax use exp2f
#define QSCALE 0.1803368801111204f

// ---------------------------------------------------------------------------
// Scratch (__device__ globals; no cudaMalloc allowed)
// ---------------------------------------------------------------------------
__device__ __half g_A[3][2][(size_t)MM * DD];   // [q/k/v][hi/lo] activations
__device__ __half g_W[4][(size_t)DD * DD];      // [q/k/v/o] weight hi
__device__ __half g_Qh[(size_t)BB * HH * SS * DK];
__device__ __half g_Ql[(size_t)BB * HH * SS * DK];
__device__ __half g_Kh[(size_t)BB * HH * SS * DK];
__device__ __half g_Vh[(size_t)BB * HH * SS * DK];
__device__ __half g_Ch[(size_t)MM * DD];        // ctx hi (O-proj activation)

// ---------------------------------------------------------------------------
// PTX helpers (arch-portable: ldmatrix / mma.sync / cp.async only)
// ---------------------------------------------------------------------------
__device__ __forceinline__ uint32_t smem_u32(const void* p) {
    uint32_t a;
    asm("{ .reg .u64 t; cvta.to.shared.u64 t, %1; cvt.u32.u64 %0, t; }" : "=r"(a) : "l"(p));
    return a;
}
__device__ __forceinline__ void cp16(uint32_t saddr, const void* g) {
    asm volatile("cp.async.cg.shared.global [%0], [%1], 16;" :: "r"(saddr), "l"(g) : "memory");
}
#define CP_COMMIT() asm volatile("cp.async.commit_group;" ::: "memory")
#define CP_WAIT(n)  asm volatile("cp.async.wait_group %0;" :: "n"(n) : "memory")

#define LDSM4(r, addr) asm volatile( \
    "ldmatrix.sync.aligned.m8n8.x4.shared.b16 {%0,%1,%2,%3}, [%4];" \
    : "=r"((r)[0]), "=r"((r)[1]), "=r"((r)[2]), "=r"((r)[3]) : "r"(addr))
#define LDSM4T(r, addr) asm volatile( \
    "ldmatrix.sync.aligned.m8n8.x4.trans.shared.b16 {%0,%1,%2,%3}, [%4];" \
    : "=r"((r)[0]), "=r"((r)[1]), "=r"((r)[2]), "=r"((r)[3]) : "r"(addr))

#define MMA16816(d, a, b0, b1) asm volatile( \
    "mma.sync.aligned.m16n8k16.row.col.f32.f16.f16.f32 " \
    "{%0,%1,%2,%3}, {%4,%5,%6,%7}, {%8,%9}, {%0,%1,%2,%3};" \
    : "+f"((d)[0]), "+f"((d)[1]), "+f"((d)[2]), "+f"((d)[3]) \
    : "r"((a)[0]), "r"((a)[1]), "r"((a)[2]), "r"((a)[3]), "r"(b0), "r"(b1))

// split two fp32 into packed fp16x2 (hi) and fp16x2 (lo residual)
__device__ __forceinline__ void split2(float x, float y, uint32_t& hp, uint32_t& lp) {
    __half hx = __float2half_rn(x), hy = __float2half_rn(y);
    __half2 hh = __halves2half2(hx, hy);
    __half2 ll = __halves2half2(__float2half_rn(x - __half2float(hx)),
                                __float2half_rn(y - __half2float(hy)));
    hp = *reinterpret_cast<uint32_t*>(&hh);
    lp = *reinterpret_cast<uint32_t*>(&ll);
}
__device__ __forceinline__ uint32_t pack_hi(float x, float y) {
    __half2 hh = __halves2half2(__float2half_rn(x), __float2half_rn(y));
    return *reinterpret_cast<uint32_t*>(&hh);
}

// ---------------------------------------------------------------------------
// Batched conversions. lo is only consumed for the Q activation (t==0).
// ---------------------------------------------------------------------------
__global__ __launch_bounds__(256)
void convert_act(const float* __restrict__ x0, const float* __restrict__ x1,
                 const float* __restrict__ x2, int n4)
{
    int i = blockIdx.x * blockDim.x + threadIdx.x;
    if (i >= n4) return;
    int t = blockIdx.y;
    const float* x = (t == 0) ? x0 : (t == 1) ? x1 : x2;
    __half* hi = g_A[t][0];
    float4 v = ((const float4*)x)[i];
    if (t == 0) {
        __half* lo = g_A[0][1];
        uint32_t h0, l0, h1, l1;
        split2(v.x, v.y, h0, l0);
        split2(v.z, v.w, h1, l1);
        ((uint32_t*)hi)[2*i]   = h0;
        ((uint32_t*)hi)[2*i+1] = h1;
        ((uint32_t*)lo)[2*i]   = l0;
        ((uint32_t*)lo)[2*i+1] = l1;
    } else {
        ((uint32_t*)hi)[2*i]   = pack_hi(v.x, v.y);
        ((uint32_t*)hi)[2*i+1] = pack_hi(v.z, v.w);
    }
}

__global__ __launch_bounds__(256)
void convert_w(const float* __restrict__ w0, const float* __restrict__ w1,
               const float* __restrict__ w2, const float* __restrict__ w3, int n4)
{
    int i = blockIdx.x * blockDim.x + threadIdx.x;
    if (i >= n4) return;
    int t = blockIdx.y;
    const float* x = (t == 0) ? w0 : (t == 1) ? w1 : (t == 2) ? w2 : w3;
    __half* hi = g_W[t];
    float4 v = ((const float4*)x)[i];
    ((uint32_t*)hi)[2*i]   = pack_hi(v.x, v.y);
    ((uint32_t*)hi)[2*i+1] = pack_hi(v.z, v.w);
}

// ---------------------------------------------------------------------------
// HMMA GEMM body. SPLITA=true : out = (Ah+Al) @ Wh  (2-pass)
//                 SPLITA=false: out =  Ah      @ Wh  (1-pass)
// CTA 128x128, 8 warps (4M x 2N), KC=32, 3-stage cp.async pipeline.
// ---------------------------------------------------------------------------
#define KC 32
#define PA_B 80
#define PB_B 272
#define A_BYTES (128 * PA_B)    // 10240
#define B_BYTES (KC * PB_B)     // 8704
#define OFF_AH 0
#define OFF_AL A_BYTES
#define OFF_BH (2 * A_BYTES)
#define STAGE (2 * A_BYTES + B_BYTES)   // 29184
#define NSTAGES 3
#define SMEM_SZ (NSTAGES * STAGE)       // 87552

template<bool SPLITA>
__device__ __forceinline__
void gemm_body(const __half* __restrict__ Ah,
               const __half* __restrict__ Al,
               const __half* __restrict__ Wh,
               const float* __restrict__ bias,
               float* __restrict__ outF,
               __half* __restrict__ outH,
               __half* __restrict__ outL,
               float scale, char* smem)
{
    const uint32_t sb = smem_u32(smem);
    const int tid = threadIdx.x;
    const int lane = tid & 31;
    const int warp = tid >> 5;
    const int warpM = warp >> 1;
    const int warpN = warp & 1;
    const int rowBase = blockIdx.y * 128;
    const int colBase = blockIdx.x * 128;

    float acc[2][8][4];
#pragma unroll
    for (int mi = 0; mi < 2; mi++)
#pragma unroll
        for (int ni = 0; ni < 8; ni++)
#pragma unroll
            for (int r = 0; r < 4; r++) acc[mi][ni][r] = 0.f;

    auto load_stage = [&](int ch, int s) {
        const int k0 = ch * KC;
        const uint32_t sbase = sb + s * STAGE;
        if (SPLITA) {
#pragma unroll
            for (int i = 0; i < 6; i++) {
                int idx = tid + i * 256;       // 0..1535
                int t = idx >> 9;              // 0:Ah 1:Al 2:Wh
                int w = idx & 511;
                if (t < 2) {
                    int r = w >> 2, c = w & 3;
                    const __half* src = (t == 0 ? Ah : Al) + (size_t)(rowBase + r) * DD + k0 + c * 8;
                    cp16(sbase + (t == 0 ? OFF_AH : OFF_AL) + r * PA_B + c * 16, src);
                } else {
                    int r = w >> 4, c = w & 15;
                    cp16(sbase + OFF_BH + r * PB_B + c * 16,
                         Wh + (size_t)(k0 + r) * DD + colBase + c * 8);
                }
            }
        } else {
#pragma unroll
            for (int i = 0; i < 4; i++) {
                int idx = tid + i * 256;       // 0..1023
                int t = idx >> 9;              // 0:Ah 1:Wh
                int w = idx & 511;
                if (t == 0) {
                    int r = w >> 2, c = w & 3;
                    cp16(sbase + OFF_AH + r * PA_B + c * 16,
                         Ah + (size_t)(rowBase + r) * DD + k0 + c * 8);
                } else {
                    int r = w >> 4, c = w & 15;
                    cp16(sbase + OFF_BH + r * PB_B + c * 16,
                         Wh + (size_t)(k0 + r) * DD + colBase + c * 8);
                }
            }
        }
        CP_COMMIT();
    };

    const int NCH = DD / KC;   // 32
    load_stage(0, 0);
    load_stage(1, 1);

    for (int ch = 0; ch < NCH; ch++) {
        CP_WAIT(1);                        // stage ch complete
        __syncthreads();                   // all warps done reading slot (ch+2)%3
        if (ch + 2 < NCH) load_stage(ch + 2, (ch + 2) % NSTAGES);

        const uint32_t stb = sb + (ch % NSTAGES) * STAGE;
#pragma unroll
        for (int kstep = 0; kstep < 2; kstep++) {
            uint32_t ah[2][4], al[2][4];
#pragma unroll
            for (int mi = 0; mi < 2; mi++) {
                uint32_t row = warpM * 32 + mi * 16 + (lane & 15);
                uint32_t ad = stb + OFF_AH + row * PA_B + kstep * 32 + (lane >> 4) * 16;
                LDSM4(ah[mi], ad);
                if (SPLITA) LDSM4(al[mi], ad + (OFF_AL - OFF_AH));
            }
            uint32_t bh[4][4];
#pragma unroll
            for (int ng = 0; ng < 4; ng++) {
                uint32_t krow = kstep * 16 + (lane & 15);
                uint32_t coln = warpN * 64 + ng * 16 + (lane >> 4) * 8;
                LDSM4T(bh[ng], stb + OFF_BH + krow * PB_B + coln * 2);
            }
#pragma unroll
            for (int mi = 0; mi < 2; mi++)
#pragma unroll
                for (int ni = 0; ni < 8; ni++) {
                    uint32_t b0 = bh[ni >> 1][(ni & 1) * 2];
                    uint32_t b1 = bh[ni >> 1][(ni & 1) * 2 + 1];
                    MMA16816(acc[mi][ni], ah[mi], b0, b1);
                    if (SPLITA) MMA16816(acc[mi][ni], al[mi], b0, b1);
                }
        }
    }

    // ---- epilogue ----
    const int lg = lane >> 2;
    const int l4 = lane & 3;
#pragma unroll
    for (int mi = 0; mi < 2; mi++) {
#pragma unroll
        for (int ni = 0; ni < 8; ni++) {
            int r0 = rowBase + warpM * 32 + mi * 16 + lg;
            int r1 = r0 + 8;
            int col = colBase + warpN * 64 + ni * 8 + l4 * 2;
            float v00 = (acc[mi][ni][0] + bias[col]) * scale;
            float v01 = (acc[mi][ni][1] + bias[col + 1]) * scale;
            float v10 = (acc[mi][ni][2] + bias[col]) * scale;
            float v11 = (acc[mi][ni][3] + bias[col + 1]) * scale;
            if (outF) {
                *(float2*)(outF + (size_t)r0 * DD + col) = make_float2(v00, v01);
                *(float2*)(outF + (size_t)r1 * DD + col) = make_float2(v10, v11);
            } else {
                int h = col >> 6, dd = col & (DK - 1);
                int b0r = r0 >> 11, s0 = r0 & (SS - 1);
                int b1r = r1 >> 11, s1 = r1 & (SS - 1);
                size_t o0 = (((size_t)(b0r * HH + h)) * SS + s0) * DK + dd;
                size_t o1 = (((size_t)(b1r * HH + h)) * SS + s1) * DK + dd;
                if (outL) {
                    uint32_t hp, lp;
                    split2(v00, v01, hp, lp);
                    *(uint32_t*)(outH + o0) = hp;
                    *(uint32_t*)(outL + o0) = lp;
                    split2(v10, v11, hp, lp);
                    *(uint32_t*)(outH + o1) = hp;
                    *(uint32_t*)(outL + o1) = lp;
                } else {
                    *(uint32_t*)(outH + o0) = pack_hi(v00, v01);
                    *(uint32_t*)(outH + o1) = pack_hi(v10, v11);
                }
            }
        }
    }
}

// Fused QKV projections: blockIdx.z selects q/k/v.
__global__ __launch_bounds__(256, 2)
void qkv_gemm(const float* __restrict__ bq, const float* __restrict__ bk,
              const float* __restrict__ bv)
{
    extern __shared__ char smem[];
    const int z = blockIdx.z;
    if (z == 0)
        gemm_body<true >(g_A[0][0], g_A[0][1], g_W[0], bq, nullptr, g_Qh, g_Ql, QSCALE, smem);
    else if (z == 1)
        gemm_body<false>(g_A[1][0], nullptr,   g_W[1], bk, nullptr, g_Kh, nullptr, 1.f, smem);
    else
        gemm_body<false>(g_A[2][0], nullptr,   g_W[2], bv, nullptr, g_Vh, nullptr, 1.f, smem);
}

// Output projection: ctx hi @ Wo -> fp32 out (1-pass).
__global__ __launch_bounds__(256, 2)
void o_gemm(const float* __restrict__ bo, float* __restrict__ out)
{
    extern __shared__ char smem[];
    gemm_body<false>(g_Ch, nullptr, g_W[3], bo, out, nullptr, nullptr, 1.f, smem);
}

// ---------------------------------------------------------------------------
// HMMA causal flash attention. QK: 2-pass (Qh+Ql)Kh. PV: 1-pass Ph Vh.
// exp2 softmax; ctx hi-only. 64-row q tiles, 2-stage KV ring, 4 CTAs/SM.
// ---------------------------------------------------------------------------
#define APITCH 144
#define ASQH 0
#define ASQL 9216                        // 64 rows * 144B
#define AKV0 18432
#define AKSTAGE 18432                    // Kh(9216) Vh(9216)
#define ATT_SMEM (AKV0 + 2 * AKSTAGE)    // 55296 -> 4 CTAs/SM

__global__ __launch_bounds__(128, 4)
void attn_mma(const __half* __restrict__ Qh, const __half* __restrict__ Ql,
              const __half* __restrict__ Kh, const __half* __restrict__ Vh,
              __half* __restrict__ Ch)
{
    extern __shared__ char smem[];
    const uint32_t sb = smem_u32(smem);
    const int tid = threadIdx.x;
    const int lane = tid & 31;
    const int warp = tid >> 5;          // 0..3
    const int lg = lane >> 2;
    const int l4 = lane & 3;
    const uint32_t lrow = (uint32_t)(lane & 15) * APITCH + (uint32_t)(lane >> 4) * 16;

    const int qt = 31 - blockIdx.x;     // 64-row q tile, heavy first
    const int h  = blockIdx.y;
    const int b  = blockIdx.z;
    const size_t bhoff = (size_t)(b * HH + h) * SS * DK;

    // --- stage Q (hi+lo): 2 mats x 64 rows x 8 chunks = 1024 chunks ---
#pragma unroll
    for (int i = 0; i < 8; i++) {
        int idx = tid + i * 128;
        int mat = idx >> 9;            // 0:Qh 1:Ql
        int w = idx & 511;
        int r = w >> 3, c = w & 7;
        const __half* src = (mat ? Ql : Qh) + bhoff + (size_t)(qt * 64 + r) * DK + c * 8;
        cp16(sb + mat * ASQL + r * APITCH + c * 16, src);
    }
    CP_COMMIT();

    auto kv_load = [&](int jt, int st) {
        uint32_t base = sb + AKV0 + st * AKSTAGE;
        size_t koff = bhoff + (size_t)jt * 64 * DK;
#pragma unroll
        for (int i = 0; i < 8; i++) {
            int idx = tid + i * 128;
            int mat = idx >> 9;        // 0:Kh 1:Vh
            int w = idx & 511;
            int r = w >> 3, c = w & 7;
            const __half* mp = mat ? Vh : Kh;
            cp16(base + mat * 9216 + r * APITCH + c * 16, mp + koff + (size_t)r * DK + c * 8);
        }
        CP_COMMIT();
    };

    const int ntiles = qt + 1;
    kv_load(0, 0);
    CP_WAIT(1);                  // Q group done
    __syncthreads();

    // --- Q fragments in registers ---
    uint32_t qah[4][4], qal[4][4];
#pragma unroll
    for (int kk = 0; kk < 4; kk++) {
        uint32_t ad = sb + ASQH + warp * (16 * APITCH) + lrow + kk * 32;
        LDSM4(qah[kk], ad);
        LDSM4(qal[kk], ad + ASQL);
    }

    float o[8][4];
#pragma unroll
    for (int c = 0; c < 8; c++)
#pragma unroll
        for (int r = 0; r < 4; r++) o[c][r] = 0.f;
    float m0 = -1e30f, m1 = -1e30f, l0 = 0.f, l1 = 0.f;

    const int row0 = qt * 64 + warp * 16 + lg;

    for (int jt = 0; jt < ntiles; jt++) {
        if (jt + 1 < ntiles) { kv_load(jt + 1, (jt + 1) & 1); CP_WAIT(1); }
        else                 { CP_WAIT(0); }
        __syncthreads();

        const uint32_t kvb = sb + AKV0 + (jt & 1) * AKSTAGE;
        const bool diag = (jt == qt);
        const int nglim = diag ? (warp + 1) : 4;

        // ---- scores: S = (Qh+Ql) Kh ----
        float s[8][4];
#pragma unroll
        for (int c = 0; c < 8; c++)
#pragma unroll
            for (int r = 0; r < 4; r++) s[c][r] = 0.f;

#pragma unroll
        for (int ng = 0; ng < 4; ng++) {
            if (ng < nglim) {
#pragma unroll
                for (int kk = 0; kk < 4; kk++) {
                    uint32_t kh[4];
                    LDSM4(kh, kvb + ng * (16 * APITCH) + lrow + kk * 32);
                    MMA16816(s[2 * ng],     qah[kk], kh[0], kh[2]);
                    MMA16816(s[2 * ng],     qal[kk], kh[0], kh[2]);
                    MMA16816(s[2 * ng + 1], qah[kk], kh[1], kh[3]);
                    MMA16816(s[2 * ng + 1], qal[kk], kh[1], kh[3]);
                }
            }
        }

        // ---- causal mask (diagonal tile only) ----
        if (diag) {
#pragma unroll
            for (int c = 0; c < 8; c++) {
                int col = jt * 64 + c * 8 + 2 * l4;
                if (col > row0)         s[c][0] = -1e30f;
                if (col + 1 > row0)     s[c][1] = -1e30f;
                if (col > row0 + 8)     s[c][2] = -1e30f;
                if (col + 1 > row0 + 8) s[c][3] = -1e30f;
            }
        }

        // ---- online softmax (base-2 domain) ----
        float mx0 = -1e30f, mx1 = -1e30f;
#pragma unroll
        for (int c = 0; c < 8; c++) {
            mx0 = fmaxf(mx0, fmaxf(s[c][0], s[c][1]));
            mx1 = fmaxf(mx1, fmaxf(s[c][2], s[c][3]));
        }
        mx0 = fmaxf(mx0, __shfl_xor_sync(0xFFFFFFFFu, mx0, 1));
        mx0 = fmaxf(mx0, __shfl_xor_sync(0xFFFFFFFFu, mx0, 2));
        mx1 = fmaxf(mx1, __shfl_xor_sync(0xFFFFFFFFu, mx1, 1));
        mx1 = fmaxf(mx1, __shfl_xor_sync(0xFFFFFFFFu, mx1, 2));
        float mn0 = fmaxf(m0, mx0), mn1 = fmaxf(m1, mx1);
        float sc0 = exp2f(m0 - mn0), sc1 = exp2f(m1 - mn1);
        m0 = mn0; m1 = mn1;
        l0 *= sc0; l1 *= sc1;
#pragma unroll
        for (int c = 0; c < 8; c++) {
            o[c][0] *= sc0; o[c][1] *= sc0;
            o[c][2] *= sc1; o[c][3] *= sc1;
        }
#pragma unroll
        for (int c = 0; c < 8; c++) {
            s[c][0] = exp2f(s[c][0] - mn0);
            s[c][1] = exp2f(s[c][1] - mn0);
            s[c][2] = exp2f(s[c][2] - mn1);
            s[c][3] = exp2f(s[c][3] - mn1);
            l0 += s[c][0] + s[c][1];
            l1 += s[c][2] + s[c][3];
        }

        // ---- P fragments (hi only) ----
        uint32_t pah[4][4];
#pragma unroll
        for (int kk = 0; kk < 4; kk++) {
            if (kk < nglim) {
                pah[kk][0] = pack_hi(s[2 * kk][0],     s[2 * kk][1]);
                pah[kk][1] = pack_hi(s[2 * kk][2],     s[2 * kk][3]);
                pah[kk][2] = pack_hi(s[2 * kk + 1][0], s[2 * kk + 1][1]);
                pah[kk][3] = pack_hi(s[2 * kk + 1][2], s[2 * kk + 1][3]);
            }
        }

        // ---- O += Ph Vh ----
#pragma unroll
        for (int dg = 0; dg < 4; dg++) {
#pragma unroll
            for (int kk = 0; kk < 4; kk++) {
                if (kk < nglim) {
                    uint32_t vh[4];
                    LDSM4T(vh, kvb + 9216 + kk * (16 * APITCH) + lrow + dg * 32);
                    MMA16816(o[2 * dg],     pah[kk], vh[0], vh[1]);
                    MMA16816(o[2 * dg + 1], pah[kk], vh[2], vh[3]);
                }
            }
        }
        __syncthreads();
    }

    // ---- finalize: normalize and write ctx hi in [B,S,D] ----
    l0 += __shfl_xor_sync(0xFFFFFFFFu, l0, 1);
    l0 += __shfl_xor_sync(0xFFFFFFFFu, l0, 2);
    l1 += __shfl_xor_sync(0xFFFFFFFFu, l1, 1);
    l1 += __shfl_xor_sync(0xFFFFFFFFu, l1, 2);
    const float inv0 = 1.f / l0, inv1 = 1.f / l1;

    const size_t r0 = (size_t)b * SS + row0;
    const size_t r1 = r0 + 8;
#pragma unroll
    for (int c = 0; c < 8; c++) {
        int col = h * DK + c * 8 + 2 * l4;
        *(uint32_t*)(Ch + r0 * DD + col) = pack_hi(o[c][0] * inv0, o[c][1] * inv0);
        *(uint32_t*)(Ch + r1 * DD + col) = pack_hi(o[c][2] * inv1, o[c][3] * inv1);
    }
}

// ---------------------------------------------------------------------------
// Launch
// ---------------------------------------------------------------------------
extern "C" void kernel_launch(void* const* d_in, const int* in_sizes, int n_in,
                              void* d_out, int out_size)
{
    const float* q  = (const float*)d_in[0];
    const float* k  = (const float*)d_in[1];
    const float* v  = (const float*)d_in[2];
    const float* Wq = (const float*)d_in[4];
    const float* bq = (const float*)d_in[5];
    const float* Wk = (const float*)d_in[6];
    const float* bk = (const float*)d_in[7];
    const float* Wv = (const float*)d_in[8];
    const float* bv = (const float*)d_in[9];
    const float* Wo = (const float*)d_in[10];
    const float* bo = (const float*)d_in[11];

    __half *gQh, *gQl, *gKh, *gVh, *gCh;
    cudaGetSymbolAddress((void**)&gQh, g_Qh);
    cudaGetSymbolAddress((void**)&gQl, g_Ql);
    cudaGetSymbolAddress((void**)&gKh, g_Kh);
    cudaGetSymbolAddress((void**)&gVh, g_Vh);
    cudaGetSymbolAddress((void**)&gCh, g_Ch);

    cudaFuncSetAttribute(qkv_gemm, cudaFuncAttributeMaxDynamicSharedMemorySize, SMEM_SZ);
    cudaFuncSetAttribute(o_gemm,   cudaFuncAttributeMaxDynamicSharedMemorySize, SMEM_SZ);
    cudaFuncSetAttribute(attn_mma, cudaFuncAttributeMaxDynamicSharedMemorySize, ATT_SMEM);

    const int n4a = MM * DD / 4;
    const int n4w = DD * DD / 4;

    // 1) batched conversions
    convert_act<<<dim3((n4a + 255) / 256, 3), 256>>>(q, k, v, n4a);
    convert_w<<<dim3((n4w + 255) / 256, 4), 256>>>(Wq, Wk, Wv, Wo, n4w);

    // 2) fused Q/K/V projections (Q 2-pass + pre-scale; K/V 1-pass)
    qkv_gemm<<<dim3(DD / 128, MM / 128, 3), 256, SMEM_SZ>>>(bq, bk, bv);

    // 3) attention -> ctx hi (2-stage KV ring, 4 CTAs/SM)
    attn_mma<<<dim3(32, HH, BB), 128, ATT_SMEM>>>(gQh, gQl, gKh, gVh, gCh);

    // 4) output projection (1-pass, fp32 out)
    o_gemm<<<dim3(DD / 128, MM / 128), 256, SMEM_SZ>>>(bo, (float*)d_out);
}